// round 2
// baseline (speedup 1.0000x reference)
#include <cuda_runtime.h>
#include <math.h>

#define BB 8
#define NN 2048
#define CC 512
#define CIN 128
#define HH 96
#define WW 96
#define PTS (BB*NN)          // 16384
#define IMG_ELEMS (BB*HH*WW*CIN)  // 9,437,184

// Scratch (static __device__ arrays — no allocation)
__device__ float g_TI[IMG_ELEMS];   // I  transposed to [b][x][y][c]
__device__ float g_TT[IMG_ELEMS];   // IT transposed
__device__ float g_A1[IMG_ELEMS];   // IX - 0.5*I transposed
__device__ float g_A2[IMG_ELEMS];   // IY - 0.5*I transposed
__device__ float g_mask[PTS*64];    // softmax mask [pt][s*8+g]
__device__ float g_U[PTS*1024];     // U [pt][g*128+k]

// ---------------------------------------------------------------------------
// Kernel 1: transpose (B,Cin,H,W) -> (B,H,W,Cin) for I, IT; fuse A1, A2.
// ---------------------------------------------------------------------------
__global__ void k_transpose(const float* __restrict__ I, const float* __restrict__ IX,
                            const float* __restrict__ IY, const float* __restrict__ IT)
{
    __shared__ float tI[32][33], tT[32][33], t1[32][33], t2[32][33];
    int bx = blockIdx.z;
    int b = bx / HH, x = bx % HH;
    int c0 = blockIdx.y * 32, y0 = blockIdx.x * 32;
    int tx = threadIdx.x, ty = threadIdx.y;

    int c = c0 + ty, y = y0 + tx;
    size_t idx = ((size_t)b * CIN + c) * (HH * WW) + (size_t)x * WW + y;
    float vi = I[idx], vx = IX[idx], vy = IY[idx], vt = IT[idx];
    tI[ty][tx] = vi;
    tT[ty][tx] = vt;
    t1[ty][tx] = vx - 0.5f * vi;   // matches reference association (IX - 0.5*I)
    t2[ty][tx] = vy - 0.5f * vi;
    __syncthreads();

    int yo = y0 + ty, co = c0 + tx;
    size_t o = (((size_t)b * HH + x) * WW + yo) * CIN + co;
    g_TI[o] = tI[tx][ty];
    g_TT[o] = tT[tx][ty];
    g_A1[o] = t1[tx][ty];
    g_A2[o] = t2[tx][ty];
}

// ---------------------------------------------------------------------------
// Kernel 2: per-point ratios/mask GEMV (fp64 accumulation!), sigmoid,
// rect split cascade (fp32, matching reference association), softmax.
// Writes level_rects directly into d_out; mask into g_mask.
// ---------------------------------------------------------------------------
__device__ __forceinline__ float sigmoidf_(float v) { return 1.f / (1.f + expf(-v)); }

__global__ void k_point(const float* __restrict__ x, const float* __restrict__ r,
                        const float* __restrict__ Wr, const float* __restrict__ br,
                        const float* __restrict__ Wm, const float* __restrict__ bm,
                        float* __restrict__ out)
{
    __shared__ float sx[CC];
    __shared__ float slog[71];
    __shared__ float srect[56];
    int pt = blockIdx.x;
    int tid = threadIdx.x;

    const float* xp = x + (size_t)pt * CC;
    for (int i = tid; i < CC; i += 128) sx[i] = xp[i];
    __syncthreads();

    if (tid < 71) {
        // fp64 accumulation: the rect coordinates feed ceil() downstream, and a
        // 1e-5-level logit error causes discrete corner flips vs the reference.
        double acc = 0.0;
        if (tid < 7) {
            #pragma unroll 8
            for (int c = 0; c < CC; c++) acc += (double)sx[c] * (double)Wr[c * 7 + tid];
            acc += (double)br[tid];
        } else {
            int j = tid - 7;
            #pragma unroll 8
            for (int c = 0; c < CC; c++) acc += (double)sx[c] * (double)Wm[c * 64 + j];
            acc += (double)bm[j];
        }
        slog[tid] = (float)acc;
    }
    __syncthreads();

    if (tid == 0) {
        const float* rp = r + (size_t)pt * 4;
        float p0 = rp[0], p1 = rp[1], p2 = rp[2], p3 = rp[3];
        float rA[2][4], rBv[4][4], rCv[8][4];
        // level 0: dim 0 (x split)
        {
            float rat = sigmoidf_(slog[0]);
            float mid = p0 * (1.f - rat) + p2 * rat;
            rA[0][0] = p0;  rA[0][1] = p1; rA[0][2] = mid; rA[0][3] = p3;
            rA[1][0] = mid; rA[1][1] = p1; rA[1][2] = p2;  rA[1][3] = p3;
        }
        // level 1: dim 1 (y split); children order: [first-of-all, second-of-all]
        for (int j = 0; j < 2; j++) {
            float rat = sigmoidf_(slog[1 + j]);
            float mid = rA[j][1] * (1.f - rat) + rA[j][3] * rat;
            rBv[j][0] = rA[j][0]; rBv[j][1] = rA[j][1]; rBv[j][2] = rA[j][2]; rBv[j][3] = mid;
            rBv[2 + j][0] = rA[j][0]; rBv[2 + j][1] = mid; rBv[2 + j][2] = rA[j][2]; rBv[2 + j][3] = rA[j][3];
        }
        // level 2: dim 0
        for (int j = 0; j < 4; j++) {
            float rat = sigmoidf_(slog[3 + j]);
            float mid = rBv[j][0] * (1.f - rat) + rBv[j][2] * rat;
            rCv[j][0] = rBv[j][0]; rCv[j][1] = rBv[j][1]; rCv[j][2] = mid; rCv[j][3] = rBv[j][3];
            rCv[4 + j][0] = mid; rCv[4 + j][1] = rBv[j][1]; rCv[4 + j][2] = rBv[j][2]; rCv[4 + j][3] = rBv[j][3];
        }
        for (int j = 0; j < 2; j++) for (int q = 0; q < 4; q++) srect[j * 4 + q] = rA[j][q];
        for (int j = 0; j < 4; j++) for (int q = 0; q < 4; q++) srect[8 + j * 4 + q] = rBv[j][q];
        for (int j = 0; j < 8; j++) for (int q = 0; q < 4; q++) srect[24 + j * 4 + q] = rCv[j][q];
    }
    // softmax over rects (s) per group g, threads 0..7
    if (tid < 8) {
        int g = tid;
        float mx = -1e30f;
        for (int s = 0; s < 8; s++) mx = fmaxf(mx, slog[7 + s * 8 + g]);
        float e[8], sum = 0.f;
        for (int s = 0; s < 8; s++) { e[s] = expf(slog[7 + s * 8 + g] - mx); sum += e[s]; }
        float inv = 1.f / sum;
        for (int s = 0; s < 8; s++) g_mask[(size_t)pt * 64 + s * 8 + g] = e[s] * inv;
    }
    __syncthreads();

    const size_t O1 = (size_t)PTS * CC;
    const size_t O2 = O1 + (size_t)PTS * 8;
    const size_t O3 = O2 + (size_t)PTS * 16;
    if (tid < 8)  out[O1 + (size_t)pt * 8 + tid]  = srect[tid];
    if (tid < 16) out[O2 + (size_t)pt * 16 + tid] = srect[8 + tid];
    if (tid < 32) out[O3 + (size_t)pt * 32 + tid] = srect[24 + tid];
}

// ---------------------------------------------------------------------------
// Kernel 3: integral-image corner sampling + mask combine -> U.
// Block = 1 point, 128 threads (thread = channel k). Coalesced 512B gathers.
// ---------------------------------------------------------------------------
__device__ __forceinline__ float corner_eval(const float* __restrict__ TI,
                                             const float* __restrict__ TT,
                                             const float* __restrict__ A1,
                                             const float* __restrict__ A2,
                                             int k, float px, float py)
{
    float X = ceilf(px), Y = ceilf(py);
    int Xi = (int)X, Yi = (int)Y;
    int Xm = max(Xi - 1, 0), Ym = max(Yi - 1, 0);
    float dx = X - px, dy = Y - py;
    float wx1 = 0.5f * (dx * dx), wx2 = dx - wx1;   // match 0.5*dx**2 association
    float wy1 = 0.5f * (dy * dy), wy2 = dy - wy1;
#define AT(T, xi, yi) __ldg(&T[(((xi) * WW + (yi)) << 7) + k])
    float s = AT(TT, Xi, Yi);
    s -= wy1 * (AT(A1, Xi, Ym) - 0.5f * AT(TI, 0, Ym))
       + wy2 * (AT(A1, Xi, Yi) - 0.5f * AT(TI, 0, Yi));
    s -= wx1 * (AT(A2, Xm, Yi) - 0.5f * AT(TI, Xm, 0))
       + wx2 * (AT(A2, Xi, Yi) - 0.5f * AT(TI, Xi, 0));
    s += wx1 * wy1 * AT(TI, Xm, Ym) + wx2 * wy1 * AT(TI, Xi, Ym)
       + wx1 * wy2 * AT(TI, Xm, Yi) + wx2 * wy2 * AT(TI, Xi, Yi);
#undef AT
    return s;
}

__global__ void k_sample(const float* __restrict__ out)
{
    __shared__ float srect[32];
    __shared__ float smask[64];
    int pt = blockIdx.x;
    int b = pt / NN;
    int k = threadIdx.x;

    const size_t O3 = (size_t)PTS * CC + (size_t)PTS * 8 + (size_t)PTS * 16;
    if (k < 32) srect[k] = out[O3 + (size_t)pt * 32 + k] * (float)(HH - 1);
    if (k < 64) smask[k] = g_mask[(size_t)pt * 64 + k];
    __syncthreads();

    size_t ib = (size_t)b * (HH * WW * CIN);
    const float* TI = g_TI + ib;
    const float* TT = g_TT + ib;
    const float* A1 = g_A1 + ib;
    const float* A2 = g_A2 + ib;

    float U[8];
    #pragma unroll
    for (int g = 0; g < 8; g++) U[g] = 0.f;

    for (int s = 0; s < 8; s++) {
        float x1 = srect[s * 4 + 0], y1 = srect[s * 4 + 1];
        float x2 = srect[s * 4 + 2], y2 = srect[s * 4 + 3];
        float S = corner_eval(TI, TT, A1, A2, k, x2, y2)
                - corner_eval(TI, TT, A1, A2, k, x1, y2)
                - corner_eval(TI, TT, A1, A2, k, x2, y1)
                + corner_eval(TI, TT, A1, A2, k, x1, y1);
        float area = fabsf((x1 - x2) * (y1 - y2)) + 1e-9f;
        S /= area;
        #pragma unroll
        for (int g = 0; g < 8; g++) U[g] += smask[s * 8 + g] * S;
    }
    float* up = g_U + (size_t)pt * 1024;
    #pragma unroll
    for (int g = 0; g < 8; g++) up[g * 128 + k] = U[g];
}

// ---------------------------------------------------------------------------
// Kernel 4: y = U @ W_samp (group-selected) + b_samp, LayerNorm, +x residual.
// Block = 8 points, 512 threads (thread = output channel c').
// ---------------------------------------------------------------------------
__global__ void k_final(const float* __restrict__ x, const float* __restrict__ Ws,
                        const float* __restrict__ bs, const float* __restrict__ lg,
                        const float* __restrict__ lb, float* __restrict__ out)
{
    __shared__ __align__(16) float sU[8 * 1024];  // 32 KB, later reused for y
    __shared__ float smu[8], srs[8];
    int pt0 = blockIdx.x * 8;
    int tid = threadIdx.x;

    const float* up = g_U + (size_t)pt0 * 1024;
    for (int i = tid; i < 8 * 1024; i += 512) sU[i] = up[i];
    __syncthreads();

    int g = tid >> 6;
    float acc[8];
    #pragma unroll
    for (int p = 0; p < 8; p++) acc[p] = 0.f;

    const float4* sU4 = (const float4*)sU;
    for (int k4 = 0; k4 < 32; k4++) {
        float w0 = Ws[(k4 * 4 + 0) * CC + tid];
        float w1 = Ws[(k4 * 4 + 1) * CC + tid];
        float w2 = Ws[(k4 * 4 + 2) * CC + tid];
        float w3 = Ws[(k4 * 4 + 3) * CC + tid];
        #pragma unroll
        for (int p = 0; p < 8; p++) {
            float4 u = sU4[(p * 1024 + g * 128) / 4 + k4];
            acc[p] += u.x * w0 + u.y * w1 + u.z * w2 + u.w * w3;
        }
    }
    float bsv = bs[tid];
    __syncthreads();  // done reading sU
    #pragma unroll
    for (int p = 0; p < 8; p++) sU[p * 512 + tid] = acc[p] + bsv;
    __syncthreads();

    int wid = tid >> 5, lane = tid & 31;
    if (wid < 8) {
        float sum = 0.f, sq = 0.f;
        for (int i = lane; i < 512; i += 32) {
            float v = sU[wid * 512 + i];
            sum += v; sq += v * v;
        }
        #pragma unroll
        for (int o = 16; o; o >>= 1) {
            sum += __shfl_xor_sync(0xffffffffu, sum, o);
            sq  += __shfl_xor_sync(0xffffffffu, sq, o);
        }
        if (lane == 0) {
            float mu = sum * (1.f / 512.f);
            float var = sq * (1.f / 512.f) - mu * mu;
            smu[wid] = mu;
            srs[wid] = rsqrtf(var + 1e-5f);
        }
    }
    __syncthreads();

    float gg = lg[tid], bb = lb[tid];
    for (int p = 0; p < 8; p++) {
        float v = sU[p * 512 + tid];
        float o = (v - smu[p]) * srs[p] * gg + bb + x[(size_t)(pt0 + p) * CC + tid];
        out[(size_t)(pt0 + p) * CC + tid] = o;
    }
}

// ---------------------------------------------------------------------------
extern "C" void kernel_launch(void* const* d_in, const int* in_sizes, int n_in,
                              void* d_out, int out_size)
{
    const float* x  = (const float*)d_in[0];
    const float* r  = (const float*)d_in[1];
    const float* I  = (const float*)d_in[2];
    const float* IX = (const float*)d_in[3];
    const float* IY = (const float*)d_in[4];
    const float* IT = (const float*)d_in[5];
    const float* Wr = (const float*)d_in[6];
    const float* br = (const float*)d_in[7];
    const float* Wm = (const float*)d_in[8];
    const float* bm = (const float*)d_in[9];
    const float* Ws = (const float*)d_in[10];
    const float* bs = (const float*)d_in[11];
    const float* lg = (const float*)d_in[12];
    const float* lb = (const float*)d_in[13];
    float* out = (float*)d_out;
    (void)in_sizes; (void)n_in; (void)out_size;

    dim3 tb(32, 32);
    dim3 tg(WW / 32, CIN / 32, BB * HH);
    k_transpose<<<tg, tb>>>(I, IX, IY, IT);
    k_point<<<PTS, 128>>>(x, r, Wr, br, Wm, bm, out);
    k_sample<<<PTS, 128>>>(out);
    k_final<<<PTS / 8, 512>>>(x, Ws, bs, lg, lb, out);
}

// round 4
// speedup vs baseline: 8.9072x; 8.9072x over previous
#include <cuda_runtime.h>
#include <math.h>

#define BB 8
#define NN 2048
#define CC 512
#define CIN 128
#define HH 96
#define WW 96
#define PTS (BB*NN)               // 16384
#define IMG_ELEMS (BB*HH*WW*CIN)  // 9,437,184

// Scratch (static __device__ arrays — no allocation)
__device__ float g_TI[IMG_ELEMS];   // I  transposed to [b][x][y][c]
__device__ float g_TT[IMG_ELEMS];   // IT transposed
__device__ float g_A1[IMG_ELEMS];   // IX - 0.5*I transposed
__device__ float g_A2[IMG_ELEMS];   // IY - 0.5*I transposed
__device__ float g_mask[PTS*64];    // softmax mask [pt][s*8+g]
__device__ float g_U[PTS*1024];     // U [pt][g*128+k]

// ---------------------------------------------------------------------------
// float4 helpers (per-component order matches the scalar reference exprs)
// ---------------------------------------------------------------------------
__device__ __forceinline__ float4 f4add(float4 a, float4 b) {
    return make_float4(a.x + b.x, a.y + b.y, a.z + b.z, a.w + b.w);
}
__device__ __forceinline__ float4 f4sub(float4 a, float4 b) {
    return make_float4(a.x - b.x, a.y - b.y, a.z - b.z, a.w - b.w);
}
__device__ __forceinline__ float4 f4scale(float s, float4 a) {
    return make_float4(s * a.x, s * a.y, s * a.z, s * a.w);
}

// ---------------------------------------------------------------------------
// Kernel 1: transpose (B,Cin,H,W) -> (B,H,W,Cin) for I, IT; fuse A1, A2.
// ---------------------------------------------------------------------------
__global__ void k_transpose(const float* __restrict__ I, const float* __restrict__ IX,
                            const float* __restrict__ IY, const float* __restrict__ IT)
{
    __shared__ float tI[32][33], tT[32][33], t1[32][33], t2[32][33];
    int bx = blockIdx.z;
    int b = bx / HH, x = bx % HH;
    int c0 = blockIdx.y * 32, y0 = blockIdx.x * 32;
    int tx = threadIdx.x, ty = threadIdx.y;

    int c = c0 + ty, y = y0 + tx;
    size_t idx = ((size_t)b * CIN + c) * (HH * WW) + (size_t)x * WW + y;
    float vi = I[idx], vx = IX[idx], vy = IY[idx], vt = IT[idx];
    tI[ty][tx] = vi;
    tT[ty][tx] = vt;
    t1[ty][tx] = vx - 0.5f * vi;   // matches reference association (IX - 0.5*I)
    t2[ty][tx] = vy - 0.5f * vi;
    __syncthreads();

    int yo = y0 + ty, co = c0 + tx;
    size_t o = (((size_t)b * HH + x) * WW + yo) * CIN + co;
    g_TI[o] = tI[tx][ty];
    g_TT[o] = tT[tx][ty];
    g_A1[o] = t1[tx][ty];
    g_A2[o] = t2[tx][ty];
}

// ---------------------------------------------------------------------------
// Kernel 2: per-point ratios/mask GEMV (fp32 Kahan — no fp64 on B300!),
// sigmoid, rect split cascade, softmax.
// Writes level_rects directly into d_out; mask into g_mask.
// ---------------------------------------------------------------------------
__device__ __forceinline__ float sigmoidf_(float v) { return 1.f / (1.f + expf(-v)); }

__global__ void k_point(const float* __restrict__ x, const float* __restrict__ r,
                        const float* __restrict__ Wr, const float* __restrict__ br,
                        const float* __restrict__ Wm, const float* __restrict__ bm,
                        float* __restrict__ out)
{
    __shared__ float sx[CC];
    __shared__ float slog[71];
    __shared__ float srect[56];
    int pt = blockIdx.x;
    int tid = threadIdx.x;

    const float* xp = x + (size_t)pt * CC;
    for (int i = tid; i < CC; i += 128) sx[i] = xp[i];
    __syncthreads();

    if (tid < 71) {
        // Kahan compensated fp32 sum via _rn intrinsics (never reassociated).
        // Products round identically to the reference's fp32 products; the
        // summation error is ~2 ulp, matching fp64-accumulator quality.
        const float* Wcol;
        int stride, j;
        float bias;
        if (tid < 64) { j = tid;      Wcol = Wm; stride = 64; bias = bm[j]; }
        else          { j = tid - 64; Wcol = Wr; stride = 7;  bias = br[j]; }
        float s = 0.f, comp = 0.f;
        #pragma unroll 4
        for (int c = 0; c < CC; c++) {
            float t = __fmul_rn(sx[c], Wcol[c * stride + j]);
            float y = __fadd_rn(t, -comp);
            float u = __fadd_rn(s, y);
            comp = __fadd_rn(__fadd_rn(u, -s), -y);
            s = u;
        }
        s = __fadd_rn(s, bias);
        slog[tid < 64 ? 7 + tid : tid - 64] = s;
    }
    __syncthreads();

    if (tid == 0) {
        const float* rp = r + (size_t)pt * 4;
        float p0 = rp[0], p1 = rp[1], p2 = rp[2], p3 = rp[3];
        float rA[2][4], rBv[4][4], rCv[8][4];
        // level 0: dim 0 (x split)
        {
            float rat = sigmoidf_(slog[0]);
            float mid = p0 * (1.f - rat) + p2 * rat;
            rA[0][0] = p0;  rA[0][1] = p1; rA[0][2] = mid; rA[0][3] = p3;
            rA[1][0] = mid; rA[1][1] = p1; rA[1][2] = p2;  rA[1][3] = p3;
        }
        // level 1: dim 1 (y split); children order: [first-of-all, second-of-all]
        for (int j = 0; j < 2; j++) {
            float rat = sigmoidf_(slog[1 + j]);
            float mid = rA[j][1] * (1.f - rat) + rA[j][3] * rat;
            rBv[j][0] = rA[j][0]; rBv[j][1] = rA[j][1]; rBv[j][2] = rA[j][2]; rBv[j][3] = mid;
            rBv[2 + j][0] = rA[j][0]; rBv[2 + j][1] = mid; rBv[2 + j][2] = rA[j][2]; rBv[2 + j][3] = rA[j][3];
        }
        // level 2: dim 0
        for (int j = 0; j < 4; j++) {
            float rat = sigmoidf_(slog[3 + j]);
            float mid = rBv[j][0] * (1.f - rat) + rBv[j][2] * rat;
            rCv[j][0] = rBv[j][0]; rCv[j][1] = rBv[j][1]; rCv[j][2] = mid; rCv[j][3] = rBv[j][3];
            rCv[4 + j][0] = mid; rCv[4 + j][1] = rBv[j][1]; rCv[4 + j][2] = rBv[j][2]; rCv[4 + j][3] = rBv[j][3];
        }
        for (int j = 0; j < 2; j++) for (int q = 0; q < 4; q++) srect[j * 4 + q] = rA[j][q];
        for (int j = 0; j < 4; j++) for (int q = 0; q < 4; q++) srect[8 + j * 4 + q] = rBv[j][q];
        for (int j = 0; j < 8; j++) for (int q = 0; q < 4; q++) srect[24 + j * 4 + q] = rCv[j][q];
    }
    // softmax over rects (s) per group g, threads 0..7
    if (tid < 8) {
        int g = tid;
        float mx = -1e30f;
        for (int s = 0; s < 8; s++) mx = fmaxf(mx, slog[7 + s * 8 + g]);
        float e[8], sum = 0.f;
        for (int s = 0; s < 8; s++) { e[s] = expf(slog[7 + s * 8 + g] - mx); sum += e[s]; }
        float inv = 1.f / sum;
        for (int s = 0; s < 8; s++) g_mask[(size_t)pt * 64 + s * 8 + g] = e[s] * inv;
    }
    __syncthreads();

    const size_t O1 = (size_t)PTS * CC;
    const size_t O2 = O1 + (size_t)PTS * 8;
    const size_t O3 = O2 + (size_t)PTS * 16;
    if (tid < 8)  out[O1 + (size_t)pt * 8 + tid]  = srect[tid];
    if (tid < 16) out[O2 + (size_t)pt * 16 + tid] = srect[8 + tid];
    if (tid < 32) out[O3 + (size_t)pt * 32 + tid] = srect[24 + tid];
}

// ---------------------------------------------------------------------------
// Kernel 3: integral-image corner sampling + mask combine -> U.
// Warp = 1 point; lane = 4 channels (float4 → LDG.128, one warp instruction
// fetches a full 512B channel row). Block = 4 points (128 threads).
// ---------------------------------------------------------------------------
__device__ __forceinline__ float4 corner_eval4(const float4* __restrict__ TI,
                                               const float4* __restrict__ TT,
                                               const float4* __restrict__ A1,
                                               const float4* __restrict__ A2,
                                               int lane, float px, float py)
{
    float X = ceilf(px), Y = ceilf(py);
    int Xi = (int)X, Yi = (int)Y;
    int Xm = max(Xi - 1, 0), Ym = max(Yi - 1, 0);
    float dx = X - px, dy = Y - py;
    float wx1 = 0.5f * (dx * dx), wx2 = dx - wx1;   // match 0.5*dx**2 association
    float wy1 = 0.5f * (dy * dy), wy2 = dy - wy1;
#define AT4(T, xi, yi) __ldg(&T[(((xi) * WW + (yi)) << 5) + lane])
    float4 s = AT4(TT, Xi, Yi);
    s = f4sub(s, f4add(f4scale(wy1, f4sub(AT4(A1, Xi, Ym), f4scale(0.5f, AT4(TI, 0, Ym)))),
                       f4scale(wy2, f4sub(AT4(A1, Xi, Yi), f4scale(0.5f, AT4(TI, 0, Yi))))));
    s = f4sub(s, f4add(f4scale(wx1, f4sub(AT4(A2, Xm, Yi), f4scale(0.5f, AT4(TI, Xm, 0)))),
                       f4scale(wx2, f4sub(AT4(A2, Xi, Yi), f4scale(0.5f, AT4(TI, Xi, 0))))));
    s = f4add(s, f4add(f4add(f4scale(wx1 * wy1, AT4(TI, Xm, Ym)),
                             f4scale(wx2 * wy1, AT4(TI, Xi, Ym))),
                       f4add(f4scale(wx1 * wy2, AT4(TI, Xm, Yi)),
                             f4scale(wx2 * wy2, AT4(TI, Xi, Yi)))));
#undef AT4
    return s;
}

__global__ void k_sample(const float* __restrict__ out)
{
    int wid = threadIdx.x >> 5, lane = threadIdx.x & 31;
    int pt = blockIdx.x * 4 + wid;
    int b = pt / NN;

    const size_t O3 = (size_t)PTS * CC + (size_t)PTS * 8 + (size_t)PTS * 16;
    const float* rp = out + O3 + (size_t)pt * 32;
    const float* mp = g_mask + (size_t)pt * 64;

    size_t ib4 = (size_t)b * (HH * WW * CIN / 4);
    const float4* TI = (const float4*)g_TI + ib4;
    const float4* TT = (const float4*)g_TT + ib4;
    const float4* A1 = (const float4*)g_A1 + ib4;
    const float4* A2 = (const float4*)g_A2 + ib4;

    float4 U[8];
    #pragma unroll
    for (int g = 0; g < 8; g++) U[g] = make_float4(0.f, 0.f, 0.f, 0.f);

    for (int s = 0; s < 8; s++) {
        float x1 = __ldg(&rp[s * 4 + 0]) * (float)(HH - 1);
        float y1 = __ldg(&rp[s * 4 + 1]) * (float)(HH - 1);
        float x2 = __ldg(&rp[s * 4 + 2]) * (float)(HH - 1);
        float y2 = __ldg(&rp[s * 4 + 3]) * (float)(HH - 1);
        float4 S = f4add(f4sub(f4sub(corner_eval4(TI, TT, A1, A2, lane, x2, y2),
                                     corner_eval4(TI, TT, A1, A2, lane, x1, y2)),
                               corner_eval4(TI, TT, A1, A2, lane, x2, y1)),
                         corner_eval4(TI, TT, A1, A2, lane, x1, y1));
        float area = fabsf((x1 - x2) * (y1 - y2)) + 1e-9f;
        float inv = 1.f / area;
        S = make_float4(S.x * inv, S.y * inv, S.z * inv, S.w * inv);
        #pragma unroll
        for (int g = 0; g < 8; g++) {
            float m = __ldg(&mp[s * 8 + g]);
            U[g].x += m * S.x; U[g].y += m * S.y; U[g].z += m * S.z; U[g].w += m * S.w;
        }
    }
    float4* up = (float4*)(g_U + (size_t)pt * 1024);
    #pragma unroll
    for (int g = 0; g < 8; g++) up[g * 32 + lane] = U[g];
}

// ---------------------------------------------------------------------------
// Kernel 4: y = U @ W_samp (group-selected) + b_samp, LayerNorm, +x residual.
// Block = 8 points, 512 threads (thread = output channel c').
// ---------------------------------------------------------------------------
__global__ void k_final(const float* __restrict__ x, const float* __restrict__ Ws,
                        const float* __restrict__ bs, const float* __restrict__ lg,
                        const float* __restrict__ lb, float* __restrict__ out)
{
    __shared__ __align__(16) float sU[8 * 1024];  // 32 KB, later reused for y
    __shared__ float smu[8], srs[8];
    int pt0 = blockIdx.x * 8;
    int tid = threadIdx.x;

    const float* up = g_U + (size_t)pt0 * 1024;
    for (int i = tid; i < 8 * 1024; i += 512) sU[i] = up[i];
    __syncthreads();

    int g = tid >> 6;
    float acc[8];
    #pragma unroll
    for (int p = 0; p < 8; p++) acc[p] = 0.f;

    const float4* sU4 = (const float4*)sU;
    for (int k4 = 0; k4 < 32; k4++) {
        float w0 = Ws[(k4 * 4 + 0) * CC + tid];
        float w1 = Ws[(k4 * 4 + 1) * CC + tid];
        float w2 = Ws[(k4 * 4 + 2) * CC + tid];
        float w3 = Ws[(k4 * 4 + 3) * CC + tid];
        #pragma unroll
        for (int p = 0; p < 8; p++) {
            float4 u = sU4[(p * 1024 + g * 128) / 4 + k4];
            acc[p] += u.x * w0 + u.y * w1 + u.z * w2 + u.w * w3;
        }
    }
    float bsv = bs[tid];
    __syncthreads();  // done reading sU
    #pragma unroll
    for (int p = 0; p < 8; p++) sU[p * 512 + tid] = acc[p] + bsv;
    __syncthreads();

    int wid = tid >> 5, lane = tid & 31;
    if (wid < 8) {
        float sum = 0.f, sq = 0.f;
        for (int i = lane; i < 512; i += 32) {
            float v = sU[wid * 512 + i];
            sum += v; sq += v * v;
        }
        #pragma unroll
        for (int o = 16; o; o >>= 1) {
            sum += __shfl_xor_sync(0xffffffffu, sum, o);
            sq  += __shfl_xor_sync(0xffffffffu, sq, o);
        }
        if (lane == 0) {
            float mu = sum * (1.f / 512.f);
            float var = sq * (1.f / 512.f) - mu * mu;
            smu[wid] = mu;
            srs[wid] = rsqrtf(var + 1e-5f);
        }
    }
    __syncthreads();

    float gg = lg[tid], bb = lb[tid];
    for (int p = 0; p < 8; p++) {
        float v = sU[p * 512 + tid];
        float o = (v - smu[p]) * srs[p] * gg + bb + x[(size_t)(pt0 + p) * CC + tid];
        out[(size_t)(pt0 + p) * CC + tid] = o;
    }
}

// ---------------------------------------------------------------------------
extern "C" void kernel_launch(void* const* d_in, const int* in_sizes, int n_in,
                              void* d_out, int out_size)
{
    const float* x  = (const float*)d_in[0];
    const float* r  = (const float*)d_in[1];
    const float* I  = (const float*)d_in[2];
    const float* IX = (const float*)d_in[3];
    const float* IY = (const float*)d_in[4];
    const float* IT = (const float*)d_in[5];
    const float* Wr = (const float*)d_in[6];
    const float* br = (const float*)d_in[7];
    const float* Wm = (const float*)d_in[8];
    const float* bm = (const float*)d_in[9];
    const float* Ws = (const float*)d_in[10];
    const float* bs = (const float*)d_in[11];
    const float* lg = (const float*)d_in[12];
    const float* lb = (const float*)d_in[13];
    float* out = (float*)d_out;
    (void)in_sizes; (void)n_in; (void)out_size;

    dim3 tb(32, 32);
    dim3 tg(WW / 32, CIN / 32, BB * HH);
    k_transpose<<<tg, tb>>>(I, IX, IY, IT);
    k_point<<<PTS, 128>>>(x, r, Wr, br, Wm, bm, out);
    k_sample<<<PTS / 4, 128>>>(out);
    k_final<<<PTS / 8, 512>>>(x, Ws, bs, lg, lb, out);
}

// round 5
// speedup vs baseline: 11.6797x; 1.3113x over previous
#include <cuda_runtime.h>
#include <math.h>

#define BB 8
#define NN 2048
#define CC 512
#define CIN 128
#define HH 96
#define WW 96
#define PTS (BB*NN)               // 16384
#define IMG_ELEMS (BB*HH*WW*CIN)  // 9,437,184

// Scratch (static __device__ arrays — no allocation)
__device__ float g_TI[IMG_ELEMS];   // I  transposed to [b][x][y][c]
__device__ float g_TT[IMG_ELEMS];   // IT transposed
__device__ float g_A1[IMG_ELEMS];   // IX - 0.5*I transposed
__device__ float g_A2[IMG_ELEMS];   // IY - 0.5*I transposed
__device__ float g_mask[PTS*64];    // softmax mask [pt][s*8+g]
__device__ float g_U[PTS*1024];     // U [pt][g*128+k]

// ---------------------------------------------------------------------------
// float4 helpers
// ---------------------------------------------------------------------------
__device__ __forceinline__ float4 f4add(float4 a, float4 b) {
    return make_float4(a.x + b.x, a.y + b.y, a.z + b.z, a.w + b.w);
}
__device__ __forceinline__ float4 f4sub(float4 a, float4 b) {
    return make_float4(a.x - b.x, a.y - b.y, a.z - b.z, a.w - b.w);
}
__device__ __forceinline__ float4 f4scale(float s, float4 a) {
    return make_float4(s * a.x, s * a.y, s * a.z, s * a.w);
}

// ---------------------------------------------------------------------------
// Kernel 1: transpose (B,Cin,H,W) -> (B,H,W,Cin) for I, IT; fuse A1, A2.
// ---------------------------------------------------------------------------
__global__ void k_transpose(const float* __restrict__ I, const float* __restrict__ IX,
                            const float* __restrict__ IY, const float* __restrict__ IT)
{
    __shared__ float tI[32][33], tT[32][33], t1[32][33], t2[32][33];
    int bx = blockIdx.z;
    int b = bx / HH, x = bx % HH;
    int c0 = blockIdx.y * 32, y0 = blockIdx.x * 32;
    int tx = threadIdx.x, ty = threadIdx.y;

    int c = c0 + ty, y = y0 + tx;
    size_t idx = ((size_t)b * CIN + c) * (HH * WW) + (size_t)x * WW + y;
    float vi = I[idx], vx = IX[idx], vy = IY[idx], vt = IT[idx];
    tI[ty][tx] = vi;
    tT[ty][tx] = vt;
    t1[ty][tx] = vx - 0.5f * vi;   // matches reference association (IX - 0.5*I)
    t2[ty][tx] = vy - 0.5f * vi;
    __syncthreads();

    int yo = y0 + ty, co = c0 + tx;
    size_t o = (((size_t)b * HH + x) * WW + yo) * CIN + co;
    g_TI[o] = tI[tx][ty];
    g_TT[o] = tT[tx][ty];
    g_A1[o] = t1[tx][ty];
    g_A2[o] = t2[tx][ty];
}

// ---------------------------------------------------------------------------
// Kernel 2: per-point logits. Mask logits (softmax path, smooth) use plain
// FMA with a 2-way c-split across all 128 threads. Ratio logits (feed ceil()
// downstream -> discrete flips) keep Kahan compensated fp32, 2-way split.
// ---------------------------------------------------------------------------
__device__ __forceinline__ float sigmoidf_(float v) { return 1.f / (1.f + expf(-v)); }

__global__ void k_point(const float* __restrict__ x, const float* __restrict__ r,
                        const float* __restrict__ Wr, const float* __restrict__ br,
                        const float* __restrict__ Wm, const float* __restrict__ bm,
                        float* __restrict__ out)
{
    __shared__ float sx[CC];
    __shared__ float part[128];
    __shared__ float rpart[14];
    __shared__ float slog[71];   // [0..6] ratios, [7..70] mask
    __shared__ float srect[56];
    int pt = blockIdx.x;
    int tid = threadIdx.x;

    const float* xp = x + (size_t)pt * CC;
    for (int i = tid; i < CC; i += 128) sx[i] = xp[i];
    __syncthreads();

    // mask logits: j = tid&63, chunk h = tid>>6 over 256 c's, plain FMA
    {
        int j = tid & 63, h = tid >> 6;
        int c0 = h * 256;
        float acc = 0.f;
        #pragma unroll 8
        for (int c = 0; c < 256; c++)
            acc = fmaf(sx[c0 + c], Wm[(size_t)(c0 + c) * 64 + j], acc);
        part[tid] = acc;
    }
    // ratio logits: Kahan over 2 chunks of 256 (threads 0..13)
    if (tid < 14) {
        int j = (tid < 7) ? tid : tid - 7;
        int c0 = (tid < 7) ? 0 : 256;
        float s = 0.f, comp = 0.f;
        #pragma unroll 4
        for (int c = 0; c < 256; c++) {
            float t = __fmul_rn(sx[c0 + c], Wr[(size_t)(c0 + c) * 7 + j]);
            float y = __fadd_rn(t, -comp);
            float u = __fadd_rn(s, y);
            comp = __fadd_rn(__fadd_rn(u, -s), -y);
            s = u;
        }
        rpart[tid] = s;
    }
    __syncthreads();
    if (tid < 64) slog[7 + tid] = part[tid] + part[64 + tid] + bm[tid];
    if (tid < 7)  slog[tid] = __fadd_rn(__fadd_rn(rpart[tid], rpart[7 + tid]), br[tid]);
    __syncthreads();

    if (tid == 0) {
        const float* rp = r + (size_t)pt * 4;
        float p0 = rp[0], p1 = rp[1], p2 = rp[2], p3 = rp[3];
        float rA[2][4], rBv[4][4], rCv[8][4];
        // level 0: dim 0 (x split)
        {
            float rat = sigmoidf_(slog[0]);
            float mid = p0 * (1.f - rat) + p2 * rat;
            rA[0][0] = p0;  rA[0][1] = p1; rA[0][2] = mid; rA[0][3] = p3;
            rA[1][0] = mid; rA[1][1] = p1; rA[1][2] = p2;  rA[1][3] = p3;
        }
        // level 1: dim 1 (y split)
        for (int j = 0; j < 2; j++) {
            float rat = sigmoidf_(slog[1 + j]);
            float mid = rA[j][1] * (1.f - rat) + rA[j][3] * rat;
            rBv[j][0] = rA[j][0]; rBv[j][1] = rA[j][1]; rBv[j][2] = rA[j][2]; rBv[j][3] = mid;
            rBv[2 + j][0] = rA[j][0]; rBv[2 + j][1] = mid; rBv[2 + j][2] = rA[j][2]; rBv[2 + j][3] = rA[j][3];
        }
        // level 2: dim 0
        for (int j = 0; j < 4; j++) {
            float rat = sigmoidf_(slog[3 + j]);
            float mid = rBv[j][0] * (1.f - rat) + rBv[j][2] * rat;
            rCv[j][0] = rBv[j][0]; rCv[j][1] = rBv[j][1]; rCv[j][2] = mid; rCv[j][3] = rBv[j][3];
            rCv[4 + j][0] = mid; rCv[4 + j][1] = rBv[j][1]; rCv[4 + j][2] = rBv[j][2]; rCv[4 + j][3] = rBv[j][3];
        }
        for (int j = 0; j < 2; j++) for (int q = 0; q < 4; q++) srect[j * 4 + q] = rA[j][q];
        for (int j = 0; j < 4; j++) for (int q = 0; q < 4; q++) srect[8 + j * 4 + q] = rBv[j][q];
        for (int j = 0; j < 8; j++) for (int q = 0; q < 4; q++) srect[24 + j * 4 + q] = rCv[j][q];
    }
    // softmax over rects (s) per group g, threads 0..7
    if (tid < 8) {
        int g = tid;
        float mx = -1e30f;
        for (int s = 0; s < 8; s++) mx = fmaxf(mx, slog[7 + s * 8 + g]);
        float e[8], sum = 0.f;
        for (int s = 0; s < 8; s++) { e[s] = expf(slog[7 + s * 8 + g] - mx); sum += e[s]; }
        float inv = 1.f / sum;
        for (int s = 0; s < 8; s++) g_mask[(size_t)pt * 64 + s * 8 + g] = e[s] * inv;
    }
    __syncthreads();

    const size_t O1 = (size_t)PTS * CC;
    const size_t O2 = O1 + (size_t)PTS * 8;
    const size_t O3 = O2 + (size_t)PTS * 16;
    if (tid < 8)  out[O1 + (size_t)pt * 8 + tid]  = srect[tid];
    if (tid < 16) out[O2 + (size_t)pt * 16 + tid] = srect[8 + tid];
    if (tid < 32) out[O3 + (size_t)pt * 32 + tid] = srect[24 + tid];
}

// ---------------------------------------------------------------------------
// Kernel 3: integral-image sampling.
// Boundary terms (I[0,:] rows / I[:,0] cols) cancel analytically across the
// 4-corner combination -> dropped: 9 loads per corner eval instead of 13.
// Sibling rects (j, j+4) share y-interval and the x=m edge -> 6 distinct
// corner evals per pair instead of 8. 216 float4-loads/point vs 416.
// Warp = 1 point; lane = 4 channels (LDG.128).
// ---------------------------------------------------------------------------
__device__ __forceinline__ float4 corner_nb(const float4* __restrict__ TI,
                                            const float4* __restrict__ TT,
                                            const float4* __restrict__ A1,
                                            const float4* __restrict__ A2,
                                            int lane, float px, float py)
{
    float X = ceilf(px), Y = ceilf(py);
    int Xi = (int)X, Yi = (int)Y;
    int Xm = max(Xi - 1, 0), Ym = max(Yi - 1, 0);
    float dx = X - px, dy = Y - py;
    float wx1 = 0.5f * (dx * dx), wx2 = dx - wx1;
    float wy1 = 0.5f * (dy * dy), wy2 = dy - wy1;
#define AT4(T, xi, yi) __ldg(&T[(((xi) * WW + (yi)) << 5) + lane])
    float4 s = AT4(TT, Xi, Yi);
    s = f4sub(s, f4add(f4scale(wy1, AT4(A1, Xi, Ym)), f4scale(wy2, AT4(A1, Xi, Yi))));
    s = f4sub(s, f4add(f4scale(wx1, AT4(A2, Xm, Yi)), f4scale(wx2, AT4(A2, Xi, Yi))));
    s = f4add(s, f4add(f4add(f4scale(wx1 * wy1, AT4(TI, Xm, Ym)),
                             f4scale(wx2 * wy1, AT4(TI, Xi, Ym))),
                       f4add(f4scale(wx1 * wy2, AT4(TI, Xm, Yi)),
                             f4scale(wx2 * wy2, AT4(TI, Xi, Yi)))));
#undef AT4
    return s;
}

__global__ void k_sample(const float* __restrict__ out)
{
    int wid = threadIdx.x >> 5, lane = threadIdx.x & 31;
    int pt = blockIdx.x * 4 + wid;
    int b = pt / NN;

    const size_t O3 = (size_t)PTS * CC + (size_t)PTS * 8 + (size_t)PTS * 16;
    const float* rp = out + O3 + (size_t)pt * 32;
    const float* mp = g_mask + (size_t)pt * 64;

    size_t ib4 = (size_t)b * (HH * WW * CIN / 4);
    const float4* TI = (const float4*)g_TI + ib4;
    const float4* TT = (const float4*)g_TT + ib4;
    const float4* A1 = (const float4*)g_A1 + ib4;
    const float4* A2 = (const float4*)g_A2 + ib4;

    float4 U[8];
    #pragma unroll
    for (int g = 0; g < 8; g++) U[g] = make_float4(0.f, 0.f, 0.f, 0.f);

    const float F = (float)(HH - 1);
    #pragma unroll
    for (int j = 0; j < 4; j++) {
        // rect j:   (a,  yl, m,  yh);  rect j+4: (m, yl, bx, yh)
        float a  = __ldg(&rp[j * 4 + 0]) * F;
        float yl = __ldg(&rp[j * 4 + 1]) * F;
        float m  = __ldg(&rp[j * 4 + 2]) * F;
        float yh = __ldg(&rp[j * 4 + 3]) * F;
        float bx = __ldg(&rp[(4 + j) * 4 + 2]) * F;

        float4 cAl = corner_nb(TI, TT, A1, A2, lane, a,  yl);
        float4 cAh = corner_nb(TI, TT, A1, A2, lane, a,  yh);
        float4 cMl = corner_nb(TI, TT, A1, A2, lane, m,  yl);
        float4 cMh = corner_nb(TI, TT, A1, A2, lane, m,  yh);
        float4 cBl = corner_nb(TI, TT, A1, A2, lane, bx, yl);
        float4 cBh = corner_nb(TI, TT, A1, A2, lane, bx, yh);

        // S1 = tl(m,yh) - tl(a,yh) - tl(m,yl) + tl(a,yl)
        float4 S1 = f4add(f4sub(f4sub(cMh, cAh), cMl), cAl);
        // S2 = tl(bx,yh) - tl(m,yh) - tl(bx,yl) + tl(m,yl)
        float4 S2 = f4add(f4sub(f4sub(cBh, cMh), cBl), cMl);

        float inv1 = 1.f / (fabsf((a - m) * (yl - yh)) + 1e-9f);
        float inv2 = 1.f / (fabsf((m - bx) * (yl - yh)) + 1e-9f);
        S1 = f4scale(inv1, S1);
        S2 = f4scale(inv2, S2);

        #pragma unroll
        for (int g = 0; g < 8; g++) {
            float m1 = __ldg(&mp[j * 8 + g]);
            float m2 = __ldg(&mp[(4 + j) * 8 + g]);
            U[g].x += m1 * S1.x + m2 * S2.x;
            U[g].y += m1 * S1.y + m2 * S2.y;
            U[g].z += m1 * S1.z + m2 * S2.z;
            U[g].w += m1 * S1.w + m2 * S2.w;
        }
    }
    float4* up = (float4*)(g_U + (size_t)pt * 1024);
    #pragma unroll
    for (int g = 0; g < 8; g++) up[g * 32 + lane] = U[g];
}

// ---------------------------------------------------------------------------
// Kernel 4: y = U @ W_samp (group-selected) + b_samp, LayerNorm, +x residual.
// Block = 8 points, 512 threads (thread = output channel c').
// ---------------------------------------------------------------------------
__global__ void k_final(const float* __restrict__ x, const float* __restrict__ Ws,
                        const float* __restrict__ bs, const float* __restrict__ lg,
                        const float* __restrict__ lb, float* __restrict__ out)
{
    __shared__ __align__(16) float sU[8 * 1024];  // 32 KB, later reused for y
    __shared__ float smu[8], srs[8];
    int pt0 = blockIdx.x * 8;
    int tid = threadIdx.x;

    const float* up = g_U + (size_t)pt0 * 1024;
    for (int i = tid; i < 8 * 1024; i += 512) sU[i] = up[i];
    __syncthreads();

    int g = tid >> 6;
    float acc[8];
    #pragma unroll
    for (int p = 0; p < 8; p++) acc[p] = 0.f;

    const float4* sU4 = (const float4*)sU;
    for (int k4 = 0; k4 < 32; k4++) {
        float w0 = Ws[(k4 * 4 + 0) * CC + tid];
        float w1 = Ws[(k4 * 4 + 1) * CC + tid];
        float w2 = Ws[(k4 * 4 + 2) * CC + tid];
        float w3 = Ws[(k4 * 4 + 3) * CC + tid];
        #pragma unroll
        for (int p = 0; p < 8; p++) {
            float4 u = sU4[(p * 1024 + g * 128) / 4 + k4];
            acc[p] += u.x * w0 + u.y * w1 + u.z * w2 + u.w * w3;
        }
    }
    float bsv = bs[tid];
    __syncthreads();  // done reading sU
    #pragma unroll
    for (int p = 0; p < 8; p++) sU[p * 512 + tid] = acc[p] + bsv;
    __syncthreads();

    int wid = tid >> 5, lane = tid & 31;
    if (wid < 8) {
        float sum = 0.f, sq = 0.f;
        for (int i = lane; i < 512; i += 32) {
            float v = sU[wid * 512 + i];
            sum += v; sq += v * v;
        }
        #pragma unroll
        for (int o = 16; o; o >>= 1) {
            sum += __shfl_xor_sync(0xffffffffu, sum, o);
            sq  += __shfl_xor_sync(0xffffffffu, sq, o);
        }
        if (lane == 0) {
            float mu = sum * (1.f / 512.f);
            float var = sq * (1.f / 512.f) - mu * mu;
            smu[wid] = mu;
            srs[wid] = rsqrtf(var + 1e-5f);
        }
    }
    __syncthreads();

    float gg = lg[tid], bb = lb[tid];
    for (int p = 0; p < 8; p++) {
        float v = sU[p * 512 + tid];
        float o = (v - smu[p]) * srs[p] * gg + bb + x[(size_t)(pt0 + p) * CC + tid];
        out[(size_t)(pt0 + p) * CC + tid] = o;
    }
}

// ---------------------------------------------------------------------------
extern "C" void kernel_launch(void* const* d_in, const int* in_sizes, int n_in,
                              void* d_out, int out_size)
{
    const float* x  = (const float*)d_in[0];
    const float* r  = (const float*)d_in[1];
    const float* I  = (const float*)d_in[2];
    const float* IX = (const float*)d_in[3];
    const float* IY = (const float*)d_in[4];
    const float* IT = (const float*)d_in[5];
    const float* Wr = (const float*)d_in[6];
    const float* br = (const float*)d_in[7];
    const float* Wm = (const float*)d_in[8];
    const float* bm = (const float*)d_in[9];
    const float* Ws = (const float*)d_in[10];
    const float* bs = (const float*)d_in[11];
    const float* lg = (const float*)d_in[12];
    const float* lb = (const float*)d_in[13];
    float* out = (float*)d_out;
    (void)in_sizes; (void)n_in; (void)out_size;

    dim3 tb(32, 32);
    dim3 tg(WW / 32, CIN / 32, BB * HH);
    k_transpose<<<tg, tb>>>(I, IX, IY, IT);
    k_point<<<PTS, 128>>>(x, r, Wr, br, Wm, bm, out);
    k_sample<<<PTS / 4, 128>>>(out);
    k_final<<<PTS / 8, 512>>>(x, Ws, bs, lg, lb, out);
}

// round 6
// speedup vs baseline: 11.8489x; 1.0145x over previous
#include <cuda_runtime.h>
#include <math.h>

#define BB 8
#define NN 2048
#define CC 512
#define CIN 128
#define HH 96
#define WW 96
#define PTS (BB*NN)               // 16384
#define IMG_ELEMS (BB*HH*WW*CIN)  // 9,437,184

// Scratch (static __device__ arrays — no allocation)
__device__ float g_TI[IMG_ELEMS];   // I  transposed to [b][x][y][c]
__device__ float g_TT[IMG_ELEMS];   // IT transposed
__device__ float g_A1[IMG_ELEMS];   // IX - 0.5*I transposed
__device__ float g_A2[IMG_ELEMS];   // IY - 0.5*I transposed
__device__ float g_mask[PTS*64];    // softmax mask [pt][s*8+g]

// ---------------------------------------------------------------------------
// float4 helpers
// ---------------------------------------------------------------------------
__device__ __forceinline__ float4 f4add(float4 a, float4 b) {
    return make_float4(a.x + b.x, a.y + b.y, a.z + b.z, a.w + b.w);
}
__device__ __forceinline__ float4 f4sub(float4 a, float4 b) {
    return make_float4(a.x - b.x, a.y - b.y, a.z - b.z, a.w - b.w);
}
__device__ __forceinline__ float4 f4scale(float s, float4 a) {
    return make_float4(s * a.x, s * a.y, s * a.z, s * a.w);
}

// ---------------------------------------------------------------------------
// Kernel 1: transpose (B,Cin,H,W) -> (B,H,W,Cin) for I, IT; fuse A1, A2.
// ---------------------------------------------------------------------------
__global__ void k_transpose(const float* __restrict__ I, const float* __restrict__ IX,
                            const float* __restrict__ IY, const float* __restrict__ IT)
{
    __shared__ float tI[32][33], tT[32][33], t1[32][33], t2[32][33];
    int bx = blockIdx.z;
    int b = bx / HH, x = bx % HH;
    int c0 = blockIdx.y * 32, y0 = blockIdx.x * 32;
    int tx = threadIdx.x, ty = threadIdx.y;

    int c = c0 + ty, y = y0 + tx;
    size_t idx = ((size_t)b * CIN + c) * (HH * WW) + (size_t)x * WW + y;
    float vi = I[idx], vx = IX[idx], vy = IY[idx], vt = IT[idx];
    tI[ty][tx] = vi;
    tT[ty][tx] = vt;
    t1[ty][tx] = vx - 0.5f * vi;   // matches reference association (IX - 0.5*I)
    t2[ty][tx] = vy - 0.5f * vi;
    __syncthreads();

    int yo = y0 + ty, co = c0 + tx;
    size_t o = (((size_t)b * HH + x) * WW + yo) * CIN + co;
    g_TI[o] = tI[tx][ty];
    g_TT[o] = tT[tx][ty];
    g_A1[o] = t1[tx][ty];
    g_A2[o] = t2[tx][ty];
}

// ---------------------------------------------------------------------------
// Kernel 2: per-point logits. Mask logits (softmax path, smooth) use plain
// FMA with a 2-way c-split across all 128 threads. Ratio logits (feed ceil()
// downstream -> discrete flips) keep Kahan compensated fp32, 2-way split.
// ---------------------------------------------------------------------------
__device__ __forceinline__ float sigmoidf_(float v) { return 1.f / (1.f + expf(-v)); }

__global__ void k_point(const float* __restrict__ x, const float* __restrict__ r,
                        const float* __restrict__ Wr, const float* __restrict__ br,
                        const float* __restrict__ Wm, const float* __restrict__ bm,
                        float* __restrict__ out)
{
    __shared__ float sx[CC];
    __shared__ float part[128];
    __shared__ float rpart[14];
    __shared__ float slog[71];   // [0..6] ratios, [7..70] mask
    __shared__ float srect[56];
    int pt = blockIdx.x;
    int tid = threadIdx.x;

    const float* xp = x + (size_t)pt * CC;
    for (int i = tid; i < CC; i += 128) sx[i] = xp[i];
    __syncthreads();

    // mask logits: j = tid&63, chunk h = tid>>6 over 256 c's, plain FMA
    {
        int j = tid & 63, h = tid >> 6;
        int c0 = h * 256;
        float acc = 0.f;
        #pragma unroll 8
        for (int c = 0; c < 256; c++)
            acc = fmaf(sx[c0 + c], Wm[(size_t)(c0 + c) * 64 + j], acc);
        part[tid] = acc;
    }
    // ratio logits: Kahan over 2 chunks of 256 (threads 0..13)
    if (tid < 14) {
        int j = (tid < 7) ? tid : tid - 7;
        int c0 = (tid < 7) ? 0 : 256;
        float s = 0.f, comp = 0.f;
        #pragma unroll 4
        for (int c = 0; c < 256; c++) {
            float t = __fmul_rn(sx[c0 + c], Wr[(size_t)(c0 + c) * 7 + j]);
            float y = __fadd_rn(t, -comp);
            float u = __fadd_rn(s, y);
            comp = __fadd_rn(__fadd_rn(u, -s), -y);
            s = u;
        }
        rpart[tid] = s;
    }
    __syncthreads();
    if (tid < 64) slog[7 + tid] = part[tid] + part[64 + tid] + bm[tid];
    if (tid < 7)  slog[tid] = __fadd_rn(__fadd_rn(rpart[tid], rpart[7 + tid]), br[tid]);
    __syncthreads();

    if (tid == 0) {
        const float* rp = r + (size_t)pt * 4;
        float p0 = rp[0], p1 = rp[1], p2 = rp[2], p3 = rp[3];
        float rA[2][4], rBv[4][4], rCv[8][4];
        // level 0: dim 0 (x split)
        {
            float rat = sigmoidf_(slog[0]);
            float mid = p0 * (1.f - rat) + p2 * rat;
            rA[0][0] = p0;  rA[0][1] = p1; rA[0][2] = mid; rA[0][3] = p3;
            rA[1][0] = mid; rA[1][1] = p1; rA[1][2] = p2;  rA[1][3] = p3;
        }
        // level 1: dim 1 (y split)
        for (int j = 0; j < 2; j++) {
            float rat = sigmoidf_(slog[1 + j]);
            float mid = rA[j][1] * (1.f - rat) + rA[j][3] * rat;
            rBv[j][0] = rA[j][0]; rBv[j][1] = rA[j][1]; rBv[j][2] = rA[j][2]; rBv[j][3] = mid;
            rBv[2 + j][0] = rA[j][0]; rBv[2 + j][1] = mid; rBv[2 + j][2] = rA[j][2]; rBv[2 + j][3] = rA[j][3];
        }
        // level 2: dim 0
        for (int j = 0; j < 4; j++) {
            float rat = sigmoidf_(slog[3 + j]);
            float mid = rBv[j][0] * (1.f - rat) + rBv[j][2] * rat;
            rCv[j][0] = rBv[j][0]; rCv[j][1] = rBv[j][1]; rCv[j][2] = mid; rCv[j][3] = rBv[j][3];
            rCv[4 + j][0] = mid; rCv[4 + j][1] = rBv[j][1]; rCv[4 + j][2] = rBv[j][2]; rCv[4 + j][3] = rBv[j][3];
        }
        for (int j = 0; j < 2; j++) for (int q = 0; q < 4; q++) srect[j * 4 + q] = rA[j][q];
        for (int j = 0; j < 4; j++) for (int q = 0; q < 4; q++) srect[8 + j * 4 + q] = rBv[j][q];
        for (int j = 0; j < 8; j++) for (int q = 0; q < 4; q++) srect[24 + j * 4 + q] = rCv[j][q];
    }
    // softmax over rects (s) per group g, threads 0..7
    if (tid < 8) {
        int g = tid;
        float mx = -1e30f;
        for (int s = 0; s < 8; s++) mx = fmaxf(mx, slog[7 + s * 8 + g]);
        float e[8], sum = 0.f;
        for (int s = 0; s < 8; s++) { e[s] = expf(slog[7 + s * 8 + g] - mx); sum += e[s]; }
        float inv = 1.f / sum;
        for (int s = 0; s < 8; s++) g_mask[(size_t)pt * 64 + s * 8 + g] = e[s] * inv;
    }
    __syncthreads();

    const size_t O1 = (size_t)PTS * CC;
    const size_t O2 = O1 + (size_t)PTS * 8;
    const size_t O3 = O2 + (size_t)PTS * 16;
    if (tid < 8)  out[O1 + (size_t)pt * 8 + tid]  = srect[tid];
    if (tid < 16) out[O2 + (size_t)pt * 16 + tid] = srect[8 + tid];
    if (tid < 32) out[O3 + (size_t)pt * 32 + tid] = srect[24 + tid];
}

// ---------------------------------------------------------------------------
// Corner eval (boundary terms dropped — they cancel across the 4-corner
// combination): 9 float4 loads.
// ---------------------------------------------------------------------------
__device__ __forceinline__ float4 corner_nb(const float4* __restrict__ TI,
                                            const float4* __restrict__ TT,
                                            const float4* __restrict__ A1,
                                            const float4* __restrict__ A2,
                                            int lane, float px, float py)
{
    float X = ceilf(px), Y = ceilf(py);
    int Xi = (int)X, Yi = (int)Y;
    int Xm = max(Xi - 1, 0), Ym = max(Yi - 1, 0);
    float dx = X - px, dy = Y - py;
    float wx1 = 0.5f * (dx * dx), wx2 = dx - wx1;
    float wy1 = 0.5f * (dy * dy), wy2 = dy - wy1;
#define AT4(T, xi, yi) __ldg(&T[(((xi) * WW + (yi)) << 5) + lane])
    float4 s = AT4(TT, Xi, Yi);
    s = f4sub(s, f4add(f4scale(wy1, AT4(A1, Xi, Ym)), f4scale(wy2, AT4(A1, Xi, Yi))));
    s = f4sub(s, f4add(f4scale(wx1, AT4(A2, Xm, Yi)), f4scale(wx2, AT4(A2, Xi, Yi))));
    s = f4add(s, f4add(f4add(f4scale(wx1 * wy1, AT4(TI, Xm, Ym)),
                             f4scale(wx2 * wy1, AT4(TI, Xi, Ym))),
                       f4add(f4scale(wx1 * wy2, AT4(TI, Xm, Yi)),
                             f4scale(wx2 * wy2, AT4(TI, Xi, Yi)))));
#undef AT4
    return s;
}

// ---------------------------------------------------------------------------
// Kernel 3 (fused): sampling (warp = point, U -> shared) + group-GEMM +
// LayerNorm + residual. Block = 8 points, 256 threads.
// 18 distinct corner evals per point (full cross-pair dedup): columns
// x=p0 (3), x=midA (4), x=p2 (3), plus 4 split edges x=m_j (2 each).
// ---------------------------------------------------------------------------
__global__ void __launch_bounds__(256)
k_fused(const float* __restrict__ x, const float* __restrict__ Ws,
        const float* __restrict__ bs, const float* __restrict__ lg,
        const float* __restrict__ lb, float* __restrict__ out)
{
    __shared__ __align__(16) float sU[8 * 1024];  // U[p][g*128+k]; later y[p][c]
    __shared__ float smu[8], srs[8];
    int tid = threadIdx.x;
    int wid = tid >> 5, lane = tid & 31;
    int pt0 = blockIdx.x * 8;
    int pt = pt0 + wid;
    int b = pt / NN;

    // ---------------- Phase 1: sampling ----------------
    {
        const size_t O3 = (size_t)PTS * CC + (size_t)PTS * 8 + (size_t)PTS * 16;
        const float* rp = out + O3 + (size_t)pt * 32;
        const float* mp = g_mask + (size_t)pt * 64;

        size_t ib4 = (size_t)b * (HH * WW * CIN / 4);
        const float4* TI = (const float4*)g_TI + ib4;
        const float4* TT = (const float4*)g_TT + ib4;
        const float4* A1 = (const float4*)g_A1 + ib4;
        const float4* A2 = (const float4*)g_A2 + ib4;

        const float F = (float)(HH - 1);
        // shared coordinates (bit-identical across rects by construction)
        float p0x  = __ldg(&rp[0])  * F;
        float yP1  = __ldg(&rp[1])  * F;
        float yM0  = __ldg(&rp[3])  * F;
        float midA = __ldg(&rp[4])  * F;
        float yM1  = __ldg(&rp[7])  * F;
        float yP3  = __ldg(&rp[11]) * F;
        float p2x  = __ldg(&rp[22]) * F;
        float m0 = __ldg(&rp[2])  * F;
        float m1 = __ldg(&rp[6])  * F;
        float m2 = __ldg(&rp[10]) * F;
        float m3 = __ldg(&rp[14]) * F;

        // column corners (10 evals)
        float4 cP0_P1 = corner_nb(TI, TT, A1, A2, lane, p0x,  yP1);
        float4 cP0_M0 = corner_nb(TI, TT, A1, A2, lane, p0x,  yM0);
        float4 cP0_P3 = corner_nb(TI, TT, A1, A2, lane, p0x,  yP3);
        float4 cMA_P1 = corner_nb(TI, TT, A1, A2, lane, midA, yP1);
        float4 cMA_M0 = corner_nb(TI, TT, A1, A2, lane, midA, yM0);
        float4 cMA_M1 = corner_nb(TI, TT, A1, A2, lane, midA, yM1);
        float4 cMA_P3 = corner_nb(TI, TT, A1, A2, lane, midA, yP3);
        float4 cP2_P1 = corner_nb(TI, TT, A1, A2, lane, p2x,  yP1);
        float4 cP2_M1 = corner_nb(TI, TT, A1, A2, lane, p2x,  yM1);
        float4 cP2_P3 = corner_nb(TI, TT, A1, A2, lane, p2x,  yP3);

        float4 U[8];
        #pragma unroll
        for (int g = 0; g < 8; g++) U[g] = make_float4(0.f, 0.f, 0.f, 0.f);

        #pragma unroll
        for (int j = 0; j < 4; j++) {
            float mj, yl, yh;
            float4 cAl, cAh, cBl, cBh;
            if (j == 0)      { mj = m0; yl = yP1; yh = yM0; cAl = cP0_P1; cAh = cP0_M0; cBl = cMA_P1; cBh = cMA_M0; }
            else if (j == 1) { mj = m1; yl = yP1; yh = yM1; cAl = cMA_P1; cAh = cMA_M1; cBl = cP2_P1; cBh = cP2_M1; }
            else if (j == 2) { mj = m2; yl = yM0; yh = yP3; cAl = cP0_M0; cAh = cP0_P3; cBl = cMA_M0; cBh = cMA_P3; }
            else             { mj = m3; yl = yM1; yh = yP3; cAl = cMA_M1; cAh = cMA_P3; cBl = cP2_M1; cBh = cP2_P3; }
            float a = (j == 0 || j == 2) ? p0x : midA;
            float bx = (j == 0 || j == 2) ? midA : p2x;

            float4 djl = corner_nb(TI, TT, A1, A2, lane, mj, yl);
            float4 djh = corner_nb(TI, TT, A1, A2, lane, mj, yh);

            // S1 = ((tl(m,yh) - tl(a,yh)) - tl(m,yl)) + tl(a,yl)
            float4 S1 = f4add(f4sub(f4sub(djh, cAh), djl), cAl);
            // S2 = ((tl(b,yh) - tl(m,yh)) - tl(b,yl)) + tl(m,yl)
            float4 S2 = f4add(f4sub(f4sub(cBh, djh), cBl), djl);

            float inv1 = 1.f / (fabsf((a - mj) * (yl - yh)) + 1e-9f);
            float inv2 = 1.f / (fabsf((mj - bx) * (yl - yh)) + 1e-9f);
            S1 = f4scale(inv1, S1);
            S2 = f4scale(inv2, S2);

            #pragma unroll
            for (int g = 0; g < 8; g++) {
                float w1 = __ldg(&mp[j * 8 + g]);
                float w2 = __ldg(&mp[(4 + j) * 8 + g]);
                U[g].x += w1 * S1.x + w2 * S2.x;
                U[g].y += w1 * S1.y + w2 * S2.y;
                U[g].z += w1 * S1.z + w2 * S2.z;
                U[g].w += w1 * S1.w + w2 * S2.w;
            }
        }
        float4* up = (float4*)(sU + wid * 1024);
        #pragma unroll
        for (int g = 0; g < 8; g++) up[g * 32 + lane] = U[g];
    }
    __syncthreads();

    // ---------------- Phase 2: group-GEMM ----------------
    // thread t -> channels (2t, 2t+1); group g = t>>5 (warp-uniform).
    int g = tid >> 5;
    const float2* W2 = (const float2*)Ws;   // Ws row k: W2[k*256 + t]
    float2 acc[8];
    #pragma unroll
    for (int p = 0; p < 8; p++) acc[p] = make_float2(0.f, 0.f);

    const float4* sU4 = (const float4*)sU;
    for (int k4 = 0; k4 < 32; k4++) {
        int kb = k4 * 4;
        float2 w0 = __ldg(&W2[(kb + 0) * 256 + tid]);
        float2 w1 = __ldg(&W2[(kb + 1) * 256 + tid]);
        float2 w2 = __ldg(&W2[(kb + 2) * 256 + tid]);
        float2 w3 = __ldg(&W2[(kb + 3) * 256 + tid]);
        #pragma unroll
        for (int p = 0; p < 8; p++) {
            float4 u = sU4[p * 256 + g * 32 + k4];
            acc[p].x += u.x * w0.x + u.y * w1.x + u.z * w2.x + u.w * w3.x;
            acc[p].y += u.x * w0.y + u.y * w1.y + u.z * w2.y + u.w * w3.y;
        }
    }
    float2 bsv = __ldg(&((const float2*)bs)[tid]);
    __syncthreads();   // done reading sU
    #pragma unroll
    for (int p = 0; p < 8; p++) {
        sU[p * 512 + 2 * tid]     = acc[p].x + bsv.x;
        sU[p * 512 + 2 * tid + 1] = acc[p].y + bsv.y;
    }
    __syncthreads();

    // ---------------- Phase 3: LayerNorm stats (warp per point) ----------------
    {
        float sum = 0.f, sq = 0.f;
        for (int i = lane; i < 512; i += 32) {
            float v = sU[wid * 512 + i];
            sum += v; sq += v * v;
        }
        #pragma unroll
        for (int o = 16; o; o >>= 1) {
            sum += __shfl_xor_sync(0xffffffffu, sum, o);
            sq  += __shfl_xor_sync(0xffffffffu, sq, o);
        }
        if (lane == 0) {
            float mu = sum * (1.f / 512.f);
            float var = sq * (1.f / 512.f) - mu * mu;
            smu[wid] = mu;
            srs[wid] = rsqrtf(var + 1e-5f);
        }
    }
    __syncthreads();

    // ---------------- Phase 4: normalize + residual + store ----------------
    float2 gg = __ldg(&((const float2*)lg)[tid]);
    float2 bb = __ldg(&((const float2*)lb)[tid]);
    const float2* x2 = (const float2*)x;
    float2* o2 = (float2*)out;
    #pragma unroll
    for (int p = 0; p < 8; p++) {
        float mu = smu[p], rs = srs[p];
        float2 v = make_float2(sU[p * 512 + 2 * tid], sU[p * 512 + 2 * tid + 1]);
        float2 xr = __ldg(&x2[(size_t)(pt0 + p) * 256 + tid]);
        float2 o;
        o.x = (v.x - mu) * rs * gg.x + bb.x + xr.x;
        o.y = (v.y - mu) * rs * gg.y + bb.y + xr.y;
        o2[(size_t)(pt0 + p) * 256 + tid] = o;
    }
}

// ---------------------------------------------------------------------------
extern "C" void kernel_launch(void* const* d_in, const int* in_sizes, int n_in,
                              void* d_out, int out_size)
{
    const float* x  = (const float*)d_in[0];
    const float* r  = (const float*)d_in[1];
    const float* I  = (const float*)d_in[2];
    const float* IX = (const float*)d_in[3];
    const float* IY = (const float*)d_in[4];
    const float* IT = (const float*)d_in[5];
    const float* Wr = (const float*)d_in[6];
    const float* br = (const float*)d_in[7];
    const float* Wm = (const float*)d_in[8];
    const float* bm = (const float*)d_in[9];
    const float* Ws = (const float*)d_in[10];
    const float* bs = (const float*)d_in[11];
    const float* lg = (const float*)d_in[12];
    const float* lb = (const float*)d_in[13];
    float* out = (float*)d_out;
    (void)in_sizes; (void)n_in; (void)out_size;

    dim3 tb(32, 32);
    dim3 tg(WW / 32, CIN / 32, BB * HH);
    k_transpose<<<tg, tb>>>(I, IX, IY, IT);
    k_point<<<PTS, 128>>>(x, r, Wr, br, Wm, bm, out);
    k_fused<<<PTS / 8, 256>>>(x, Ws, bs, lg, lb, out);
}

// round 8
// speedup vs baseline: 16.9923x; 1.4341x over previous
#include <cuda_runtime.h>
#include <math.h>

#define BB 8
#define NN 2048
#define CC 512
#define CIN 128
#define HH 96
#define WW 96
#define PTS (BB*NN)               // 16384
#define IMG_ELEMS (BB*HH*WW*CIN)  // 9,437,184

// Scratch (static __device__ arrays — no allocation)
__device__ float g_TI[IMG_ELEMS];   // I  transposed to [b][x][y][c]
__device__ float g_TT[IMG_ELEMS];   // IT transposed
__device__ float g_A1[IMG_ELEMS];   // IX - 0.5*I transposed
__device__ float g_A2[IMG_ELEMS];   // IY - 0.5*I transposed
__device__ float g_mask[PTS*64];    // softmax mask [pt][s*8+g]

// Corner tables: 18 distinct corners; each corner belongs to <=2 rects.
// cx/cy: index into the 32-float final-rect array rp[] (bit-identical copies).
__constant__ int   c_cx[18] = {0,0,0, 4,4,4,4, 22,22,22, 2,2, 6,6, 10,10, 14,14};
__constant__ int   c_cy[18] = {1,3,11, 1,3,7,11, 1,7,11, 1,3, 1,7, 3,11, 7,11};
__constant__ int   c_r1[18] = {0,0,2, 4,4,1,6, 5,5,7, 0,0, 1,1, 2,2, 3,3};
__constant__ float c_s1[18] = {1,-1,-1, -1,1,-1,1, -1,1,1, -1,1, -1,1, -1,1, -1,1};
__constant__ int   c_r2[18] = {0,2,0, 1,6,3,3, 0,7,0, 4,4, 5,5, 6,6, 7,7};
__constant__ float c_s2[18] = {0,1,0, 1,-1,1,-1, 0,-1,0, 1,-1, 1,-1, 1,-1, 1,-1};

// ---------------------------------------------------------------------------
// float4 helpers
// ---------------------------------------------------------------------------
__device__ __forceinline__ float4 f4add(float4 a, float4 b) {
    return make_float4(a.x + b.x, a.y + b.y, a.z + b.z, a.w + b.w);
}
__device__ __forceinline__ float4 f4sub(float4 a, float4 b) {
    return make_float4(a.x - b.x, a.y - b.y, a.z - b.z, a.w - b.w);
}
__device__ __forceinline__ float4 f4scale(float s, float4 a) {
    return make_float4(s * a.x, s * a.y, s * a.z, s * a.w);
}

// ---------------------------------------------------------------------------
// Kernel 1: transpose (B,Cin,H,W) -> (B,H,W,Cin) for I, IT; fuse A1, A2.
// ---------------------------------------------------------------------------
__global__ void k_transpose(const float* __restrict__ I, const float* __restrict__ IX,
                            const float* __restrict__ IY, const float* __restrict__ IT)
{
    __shared__ float tI[32][33], tT[32][33], t1[32][33], t2[32][33];
    int bx = blockIdx.z;
    int b = bx / HH, x = bx % HH;
    int c0 = blockIdx.y * 32, y0 = blockIdx.x * 32;
    int tx = threadIdx.x, ty = threadIdx.y;

    int c = c0 + ty, y = y0 + tx;
    size_t idx = ((size_t)b * CIN + c) * (HH * WW) + (size_t)x * WW + y;
    float vi = I[idx], vx = IX[idx], vy = IY[idx], vt = IT[idx];
    tI[ty][tx] = vi;
    tT[ty][tx] = vt;
    t1[ty][tx] = vx - 0.5f * vi;
    t2[ty][tx] = vy - 0.5f * vi;
    __syncthreads();

    int yo = y0 + ty, co = c0 + tx;
    size_t o = (((size_t)b * HH + x) * WW + yo) * CIN + co;
    g_TI[o] = tI[tx][ty];
    g_TT[o] = tT[tx][ty];
    g_A1[o] = t1[tx][ty];
    g_A2[o] = t2[tx][ty];
}

// ---------------------------------------------------------------------------
// Kernel 2 v2: 8 points per block, 256 threads. Mask logits reuse each Wm
// weight across 8 points (register tiling). Ratio logits keep the exact
// Kahan recipe (bit-identical to the passing version).
// ---------------------------------------------------------------------------
__device__ __forceinline__ float sigmoidf_(float v) { return 1.f / (1.f + expf(-v)); }

__global__ void __launch_bounds__(256)
k_point(const float* __restrict__ x, const float* __restrict__ r,
        const float* __restrict__ Wr, const float* __restrict__ br,
        const float* __restrict__ Wm, const float* __restrict__ bm,
        float* __restrict__ out)
{
    __shared__ __align__(16) float sxs[8 * CC];   // 16 KB
    __shared__ float part[256 * 8];               // 8 KB  part[(q*64+j)*8+p]
    __shared__ float rpart[8 * 14];
    __shared__ float slog[8 * 71];                // per point: [0..6] ratios, [7..70] mask
    __shared__ float srect[8 * 56];
    int pt0 = blockIdx.x * 8;
    int tid = threadIdx.x;

    // load x for 8 points (contiguous 16 KB)
    {
        const float4* src = (const float4*)(x + (size_t)pt0 * CC);
        float4* dst = (float4*)sxs;
        for (int i = tid; i < 8 * CC / 4; i += 256) dst[i] = src[i];
    }
    __syncthreads();

    // ---- mask logits: j = tid&63, c-chunk q = tid>>6 (128 c each) ----
    {
        int j = tid & 63, q = tid >> 6;
        int cbase = q * 128;
        float acc[8];
        #pragma unroll
        for (int p = 0; p < 8; p++) acc[p] = 0.f;
        #pragma unroll 4
        for (int c4 = 0; c4 < 32; c4++) {
            int c = cbase + c4 * 4;
            float w0 = __ldg(&Wm[(size_t)(c + 0) * 64 + j]);
            float w1 = __ldg(&Wm[(size_t)(c + 1) * 64 + j]);
            float w2 = __ldg(&Wm[(size_t)(c + 2) * 64 + j]);
            float w3 = __ldg(&Wm[(size_t)(c + 3) * 64 + j]);
            #pragma unroll
            for (int p = 0; p < 8; p++) {
                float4 u = *(const float4*)(sxs + p * CC + c);
                acc[p] += u.x * w0 + u.y * w1 + u.z * w2 + u.w * w3;
            }
        }
        #pragma unroll
        for (int p = 0; p < 8; p++) part[tid * 8 + p] = acc[p];
    }
    // ---- ratio logits: Kahan, 8 pts x 7 logits x 2 chunks = 112 threads ----
    if (tid < 112) {
        int p = tid / 14, rem = tid % 14;
        int j = rem % 7, h = rem / 7;
        int c0 = h * 256;
        const float* sx = sxs + p * CC;
        float s = 0.f, comp = 0.f;
        #pragma unroll 4
        for (int c = 0; c < 256; c++) {
            float t = __fmul_rn(sx[c0 + c], Wr[(size_t)(c0 + c) * 7 + j]);
            float y = __fadd_rn(t, -comp);
            float u = __fadd_rn(s, y);
            comp = __fadd_rn(__fadd_rn(u, -s), -y);
            s = u;
        }
        rpart[p * 14 + h * 7 + j] = s;
    }
    __syncthreads();
    if (tid < 64) {
        int j = tid;
        float bmv = bm[j];
        #pragma unroll
        for (int p = 0; p < 8; p++) {
            float v = ((part[(0 * 64 + j) * 8 + p] + part[(1 * 64 + j) * 8 + p])
                     + (part[(2 * 64 + j) * 8 + p] + part[(3 * 64 + j) * 8 + p])) + bmv;
            slog[p * 71 + 7 + j] = v;
        }
    }
    if (tid < 56) {
        int p = tid / 7, j = tid % 7;
        slog[p * 71 + j] = __fadd_rn(__fadd_rn(rpart[p * 14 + j], rpart[p * 14 + 7 + j]), br[j]);
    }
    __syncthreads();

    // ---- rect cascade: thread p < 8 per point ----
    if (tid < 8) {
        int p = tid;
        const float* sl = slog + p * 71;
        float* sr = srect + p * 56;
        const float* rp = r + (size_t)(pt0 + p) * 4;
        float p0 = rp[0], p1 = rp[1], p2 = rp[2], p3 = rp[3];
        float rA[2][4], rBv[4][4], rCv[8][4];
        {
            float rat = sigmoidf_(sl[0]);
            float mid = p0 * (1.f - rat) + p2 * rat;
            rA[0][0] = p0;  rA[0][1] = p1; rA[0][2] = mid; rA[0][3] = p3;
            rA[1][0] = mid; rA[1][1] = p1; rA[1][2] = p2;  rA[1][3] = p3;
        }
        for (int j = 0; j < 2; j++) {
            float rat = sigmoidf_(sl[1 + j]);
            float mid = rA[j][1] * (1.f - rat) + rA[j][3] * rat;
            rBv[j][0] = rA[j][0]; rBv[j][1] = rA[j][1]; rBv[j][2] = rA[j][2]; rBv[j][3] = mid;
            rBv[2 + j][0] = rA[j][0]; rBv[2 + j][1] = mid; rBv[2 + j][2] = rA[j][2]; rBv[2 + j][3] = rA[j][3];
        }
        for (int j = 0; j < 4; j++) {
            float rat = sigmoidf_(sl[3 + j]);
            float mid = rBv[j][0] * (1.f - rat) + rBv[j][2] * rat;
            rCv[j][0] = rBv[j][0]; rCv[j][1] = rBv[j][1]; rCv[j][2] = mid; rCv[j][3] = rBv[j][3];
            rCv[4 + j][0] = mid; rCv[4 + j][1] = rBv[j][1]; rCv[4 + j][2] = rBv[j][2]; rCv[4 + j][3] = rBv[j][3];
        }
        for (int j = 0; j < 2; j++) for (int q = 0; q < 4; q++) sr[j * 4 + q] = rA[j][q];
        for (int j = 0; j < 4; j++) for (int q = 0; q < 4; q++) sr[8 + j * 4 + q] = rBv[j][q];
        for (int j = 0; j < 8; j++) for (int q = 0; q < 4; q++) sr[24 + j * 4 + q] = rCv[j][q];
    }
    // ---- softmax: 64 threads, (p, g) ----
    if (tid < 64) {
        int p = tid >> 3, g = tid & 7;
        const float* sl = slog + p * 71;
        float mx = -1e30f;
        for (int s = 0; s < 8; s++) mx = fmaxf(mx, sl[7 + s * 8 + g]);
        float e[8], sum = 0.f;
        for (int s = 0; s < 8; s++) { e[s] = expf(sl[7 + s * 8 + g] - mx); sum += e[s]; }
        float inv = 1.f / sum;
        for (int s = 0; s < 8; s++) g_mask[(size_t)(pt0 + p) * 64 + s * 8 + g] = e[s] * inv;
    }
    __syncthreads();

    const size_t O1 = (size_t)PTS * CC;
    const size_t O2 = O1 + (size_t)PTS * 8;
    const size_t O3 = O2 + (size_t)PTS * 16;
    if (tid < 64)  { int p = tid >> 3, i = tid & 7;  out[O1 + (size_t)(pt0 + p) * 8 + i]  = srect[p * 56 + i]; }
    if (tid < 128) { int p = tid >> 4, i = tid & 15; out[O2 + (size_t)(pt0 + p) * 16 + i] = srect[p * 56 + 8 + i]; }
    {              int p = tid >> 5, i = tid & 31; out[O3 + (size_t)(pt0 + p) * 32 + i] = srect[p * 56 + 24 + i]; }
}

// ---------------------------------------------------------------------------
// Corner eval (boundary terms cancel across the 4-corner combination): 9 loads.
// ---------------------------------------------------------------------------
__device__ __forceinline__ float4 corner_nb(const float4* __restrict__ TI,
                                            const float4* __restrict__ TT,
                                            const float4* __restrict__ A1,
                                            const float4* __restrict__ A2,
                                            int lane, float px, float py)
{
    float X = ceilf(px), Y = ceilf(py);
    int Xi = (int)X, Yi = (int)Y;
    int Xm = max(Xi - 1, 0), Ym = max(Yi - 1, 0);
    float dx = X - px, dy = Y - py;
    float wx1 = 0.5f * (dx * dx), wx2 = dx - wx1;
    float wy1 = 0.5f * (dy * dy), wy2 = dy - wy1;
#define AT4(T, xi, yi) __ldg(&T[(((xi) * WW + (yi)) << 5) + lane])
    float4 s = AT4(TT, Xi, Yi);
    s = f4sub(s, f4add(f4scale(wy1, AT4(A1, Xi, Ym)), f4scale(wy2, AT4(A1, Xi, Yi))));
    s = f4sub(s, f4add(f4scale(wx1, AT4(A2, Xm, Yi)), f4scale(wx2, AT4(A2, Xi, Yi))));
    s = f4add(s, f4add(f4add(f4scale(wx1 * wy1, AT4(TI, Xm, Ym)),
                             f4scale(wx2 * wy1, AT4(TI, Xi, Ym))),
                       f4add(f4scale(wx1 * wy2, AT4(TI, Xm, Yi)),
                             f4scale(wx2 * wy2, AT4(TI, Xi, Yi)))));
#undef AT4
    return s;
}

// ---------------------------------------------------------------------------
// Kernel 3 (fused): coefficient-streamed sampling + group-GEMM + LayerNorm +
// residual. Block = 8 points, 256 threads; warp = point in phase 1.
// ---------------------------------------------------------------------------
__global__ void __launch_bounds__(256)
k_fused(const float* __restrict__ x, const float* __restrict__ Ws,
        const float* __restrict__ bs, const float* __restrict__ lg,
        const float* __restrict__ lb, float* __restrict__ out)
{
    __shared__ __align__(16) float sU[8 * 1024];  // U[p][g*128+k]; later y[p][c]
    __shared__ float2 scoord[8][18];
    __shared__ __align__(16) float scoef[8][18 * 8];
    __shared__ float smu[8], srs[8];
    int tid = threadIdx.x;
    int wid = tid >> 5, lane = tid & 31;
    int pt0 = blockIdx.x * 8;
    int pt = pt0 + wid;
    int b = pt / NN;

    const size_t O3 = (size_t)PTS * CC + (size_t)PTS * 8 + (size_t)PTS * 16;
    const float* rp = out + O3 + (size_t)pt * 32;
    const float* mp = g_mask + (size_t)pt * 64;
    const float F = (float)(HH - 1);

    // ---------------- Phase 0: per-point corner coords + coefficients ----------------
    if (lane < 18) {
        float cx = __ldg(&rp[c_cx[lane]]) * F;
        float cy = __ldg(&rp[c_cy[lane]]) * F;
        scoord[wid][lane] = make_float2(cx, cy);
        int r1i = c_r1[lane], r2i = c_r2[lane];
        float x1 = __ldg(&rp[4 * r1i]) * F,  y1 = __ldg(&rp[4 * r1i + 1]) * F;
        float x2 = __ldg(&rp[4 * r1i + 2]) * F, y2 = __ldg(&rp[4 * r1i + 3]) * F;
        float w1 = c_s1[lane] / (fabsf((x1 - x2) * (y1 - y2)) + 1e-9f);
        float x1b = __ldg(&rp[4 * r2i]) * F,  y1b = __ldg(&rp[4 * r2i + 1]) * F;
        float x2b = __ldg(&rp[4 * r2i + 2]) * F, y2b = __ldg(&rp[4 * r2i + 3]) * F;
        float w2 = c_s2[lane] / (fabsf((x1b - x2b) * (y1b - y2b)) + 1e-9f);
        #pragma unroll
        for (int g = 0; g < 8; g++)
            scoef[wid][lane * 8 + g] = w1 * __ldg(&mp[r1i * 8 + g]) + w2 * __ldg(&mp[r2i * 8 + g]);
    }
    __syncwarp();

    // ---------------- Phase 1: stream 18 corners into U ----------------
    {
        size_t ib4 = (size_t)b * (HH * WW * CIN / 4);
        const float4* TI = (const float4*)g_TI + ib4;
        const float4* TT = (const float4*)g_TT + ib4;
        const float4* A1 = (const float4*)g_A1 + ib4;
        const float4* A2 = (const float4*)g_A2 + ib4;

        float4 U[8];
        #pragma unroll
        for (int g = 0; g < 8; g++) U[g] = make_float4(0.f, 0.f, 0.f, 0.f);

        const float4* cf4 = (const float4*)scoef[wid];
        #pragma unroll 6
        for (int e = 0; e < 18; e++) {
            float2 cc = scoord[wid][e];
            float4 v = corner_nb(TI, TT, A1, A2, lane, cc.x, cc.y);
            float4 ca = cf4[e * 2], cb = cf4[e * 2 + 1];
            U[0].x += ca.x * v.x; U[0].y += ca.x * v.y; U[0].z += ca.x * v.z; U[0].w += ca.x * v.w;
            U[1].x += ca.y * v.x; U[1].y += ca.y * v.y; U[1].z += ca.y * v.z; U[1].w += ca.y * v.w;
            U[2].x += ca.z * v.x; U[2].y += ca.z * v.y; U[2].z += ca.z * v.z; U[2].w += ca.z * v.w;
            U[3].x += ca.w * v.x; U[3].y += ca.w * v.y; U[3].z += ca.w * v.z; U[3].w += ca.w * v.w;
            U[4].x += cb.x * v.x; U[4].y += cb.x * v.y; U[4].z += cb.x * v.z; U[4].w += cb.x * v.w;
            U[5].x += cb.y * v.x; U[5].y += cb.y * v.y; U[5].z += cb.y * v.z; U[5].w += cb.y * v.w;
            U[6].x += cb.z * v.x; U[6].y += cb.z * v.y; U[6].z += cb.z * v.z; U[6].w += cb.z * v.w;
            U[7].x += cb.w * v.x; U[7].y += cb.w * v.y; U[7].z += cb.w * v.z; U[7].w += cb.w * v.w;
        }
        float4* up = (float4*)(sU + wid * 1024);
        #pragma unroll
        for (int g = 0; g < 8; g++) up[g * 32 + lane] = U[g];
    }
    __syncthreads();

    // ---------------- Phase 2: group-GEMM ----------------
    int g = tid >> 5;
    const float2* W2 = (const float2*)Ws;
    float2 acc[8];
    #pragma unroll
    for (int p = 0; p < 8; p++) acc[p] = make_float2(0.f, 0.f);

    const float4* sU4 = (const float4*)sU;
    for (int k4 = 0; k4 < 32; k4++) {
        int kb = k4 * 4;
        float2 w0 = __ldg(&W2[(kb + 0) * 256 + tid]);
        float2 w1 = __ldg(&W2[(kb + 1) * 256 + tid]);
        float2 w2 = __ldg(&W2[(kb + 2) * 256 + tid]);
        float2 w3 = __ldg(&W2[(kb + 3) * 256 + tid]);
        #pragma unroll
        for (int p = 0; p < 8; p++) {
            float4 u = sU4[p * 256 + g * 32 + k4];
            acc[p].x += u.x * w0.x + u.y * w1.x + u.z * w2.x + u.w * w3.x;
            acc[p].y += u.x * w0.y + u.y * w1.y + u.z * w2.y + u.w * w3.y;
        }
    }
    float2 bsv = __ldg(&((const float2*)bs)[tid]);
    __syncthreads();
    #pragma unroll
    for (int p = 0; p < 8; p++) {
        sU[p * 512 + 2 * tid]     = acc[p].x + bsv.x;
        sU[p * 512 + 2 * tid + 1] = acc[p].y + bsv.y;
    }
    __syncthreads();

    // ---------------- Phase 3: LayerNorm stats (warp per point) ----------------
    {
        float sum = 0.f, sq = 0.f;
        for (int i = lane; i < 512; i += 32) {
            float v = sU[wid * 512 + i];
            sum += v; sq += v * v;
        }
        #pragma unroll
        for (int o = 16; o; o >>= 1) {
            sum += __shfl_xor_sync(0xffffffffu, sum, o);
            sq  += __shfl_xor_sync(0xffffffffu, sq, o);
        }
        if (lane == 0) {
            float mu = sum * (1.f / 512.f);
            float var = sq * (1.f / 512.f) - mu * mu;
            smu[wid] = mu;
            srs[wid] = rsqrtf(var + 1e-5f);
        }
    }
    __syncthreads();

    // ---------------- Phase 4: normalize + residual + store ----------------
    float2 gg = __ldg(&((const float2*)lg)[tid]);
    float2 bb = __ldg(&((const float2*)lb)[tid]);
    const float2* x2 = (const float2*)x;
    float2* o2 = (float2*)out;
    #pragma unroll
    for (int p = 0; p < 8; p++) {
        float mu = smu[p], rs = srs[p];
        float2 v = make_float2(sU[p * 512 + 2 * tid], sU[p * 512 + 2 * tid + 1]);
        float2 xr = __ldg(&x2[(size_t)(pt0 + p) * 256 + tid]);
        float2 o;
        o.x = (v.x - mu) * rs * gg.x + bb.x + xr.x;
        o.y = (v.y - mu) * rs * gg.y + bb.y + xr.y;
        o2[(size_t)(pt0 + p) * 256 + tid] = o;
    }
}

// ---------------------------------------------------------------------------
extern "C" void kernel_launch(void* const* d_in, const int* in_sizes, int n_in,
                              void* d_out, int out_size)
{
    const float* x  = (const float*)d_in[0];
    const float* r  = (const float*)d_in[1];
    const float* I  = (const float*)d_in[2];
    const float* IX = (const float*)d_in[3];
    const float* IY = (const float*)d_in[4];
    const float* IT = (const float*)d_in[5];
    const float* Wr = (const float*)d_in[6];
    const float* br = (const float*)d_in[7];
    const float* Wm = (const float*)d_in[8];
    const float* bm = (const float*)d_in[9];
    const float* Ws = (const float*)d_in[10];
    const float* bs = (const float*)d_in[11];
    const float* lg = (const float*)d_in[12];
    const float* lb = (const float*)d_in[13];
    float* out = (float*)d_out;
    (void)in_sizes; (void)n_in; (void)out_size;

    dim3 tb(32, 32);
    dim3 tg(WW / 32, CIN / 32, BB * HH);
    k_transpose<<<tg, tb>>>(I, IX, IY, IT);
    k_point<<<PTS / 8, 256>>>(x, r, Wr, br, Wm, bm, out);
    k_fused<<<PTS / 8, 256>>>(x, Ws, bs, lg, lb, out);
}

// round 9
// speedup vs baseline: 18.0795x; 1.0640x over previous
#include <cuda_runtime.h>
#include <math.h>

#define BB 8
#define NN 2048
#define CC 512
#define CIN 128
#define HH 96
#define WW 96
#define PTS (BB*NN)               // 16384
#define IMG_ELEMS (BB*HH*WW*CIN)  // 9,437,184

// transpose blocks: BB*HH*(CIN/32)*(WW/32) = 8*96*4*3
#define NT_BLOCKS 9216
#define NP_BLOCKS (PTS/8)         // 2048

// Scratch (static __device__ arrays — no allocation)
__device__ float g_TI[IMG_ELEMS];   // I  transposed to [b][x][y][c]
__device__ float g_TT[IMG_ELEMS];   // IT transposed
__device__ float g_A1[IMG_ELEMS];   // IX - 0.5*I transposed
__device__ float g_A2[IMG_ELEMS];   // IY - 0.5*I transposed
__device__ float g_mask[PTS*64];    // softmax mask [pt][s*8+g]

// Corner tables: 18 distinct corners; each corner belongs to <=2 rects.
__constant__ int   c_cx[18] = {0,0,0, 4,4,4,4, 22,22,22, 2,2, 6,6, 10,10, 14,14};
__constant__ int   c_cy[18] = {1,3,11, 1,3,7,11, 1,7,11, 1,3, 1,7, 3,11, 7,11};
__constant__ int   c_r1[18] = {0,0,2, 4,4,1,6, 5,5,7, 0,0, 1,1, 2,2, 3,3};
__constant__ float c_s1[18] = {1,-1,-1, -1,1,-1,1, -1,1,1, -1,1, -1,1, -1,1, -1,1};
__constant__ int   c_r2[18] = {0,2,0, 1,6,3,3, 0,7,0, 4,4, 5,5, 6,6, 7,7};
__constant__ float c_s2[18] = {0,1,0, 1,-1,1,-1, 0,-1,0, 1,-1, 1,-1, 1,-1, 1,-1};

// ---------------------------------------------------------------------------
__device__ __forceinline__ float4 f4add(float4 a, float4 b) {
    return make_float4(a.x + b.x, a.y + b.y, a.z + b.z, a.w + b.w);
}
__device__ __forceinline__ float4 f4sub(float4 a, float4 b) {
    return make_float4(a.x - b.x, a.y - b.y, a.z - b.z, a.w - b.w);
}
__device__ __forceinline__ float4 f4scale(float s, float4 a) {
    return make_float4(s * a.x, s * a.y, s * a.z, s * a.w);
}
__device__ __forceinline__ float sigmoidf_(float v) { return 1.f / (1.f + expf(-v)); }

// ---------------------------------------------------------------------------
// Kernel 1 (merged): blocks [0, NT_BLOCKS) do the vectorized transpose;
// blocks [NT_BLOCKS, NT_BLOCKS+NP_BLOCKS) do the per-point logits/rects.
// Independent workloads co-scheduled in one launch (graph-safe overlap).
// ---------------------------------------------------------------------------
__global__ void __launch_bounds__(256)
k_pre(const float* __restrict__ I, const float* __restrict__ IX,
      const float* __restrict__ IY, const float* __restrict__ IT,
      const float* __restrict__ x, const float* __restrict__ r,
      const float* __restrict__ Wr, const float* __restrict__ br,
      const float* __restrict__ Wm, const float* __restrict__ bm,
      float* __restrict__ out)
{
    __shared__ __align__(16) char smem_raw[29120];
    int tid = threadIdx.x;

    if (blockIdx.x < NT_BLOCKS) {
        // ================= transpose branch (vectorized) =================
        float* tI = (float*)smem_raw;            // [32][33]
        float* tT = tI + 1056;
        float* t1 = tT + 1056;
        float* t2 = t1 + 1056;

        int t = blockIdx.x;
        int y0 = (t % 3) * 32;
        int c0 = ((t / 3) & 3) * 32;
        int xx = (t / 12) % HH;
        int b  = t / (12 * HH);

        int cl = tid >> 3;             // 0..31
        int y4 = (tid & 7) << 2;       // 0,4..28

        size_t idx = ((size_t)(b * CIN + c0 + cl) * (HH * WW) + (size_t)xx * WW + y0 + y4);
        float4 vi = *(const float4*)(I + idx);
        float4 vx = *(const float4*)(IX + idx);
        float4 vy = *(const float4*)(IY + idx);
        float4 vt = *(const float4*)(IT + idx);

        int sb = cl * 33 + y4;
        tI[sb + 0] = vi.x; tI[sb + 1] = vi.y; tI[sb + 2] = vi.z; tI[sb + 3] = vi.w;
        tT[sb + 0] = vt.x; tT[sb + 1] = vt.y; tT[sb + 2] = vt.z; tT[sb + 3] = vt.w;
        t1[sb + 0] = vx.x - 0.5f * vi.x; t1[sb + 1] = vx.y - 0.5f * vi.y;
        t1[sb + 2] = vx.z - 0.5f * vi.z; t1[sb + 3] = vx.w - 0.5f * vi.w;
        t2[sb + 0] = vy.x - 0.5f * vi.x; t2[sb + 1] = vy.y - 0.5f * vi.y;
        t2[sb + 2] = vy.z - 0.5f * vi.z; t2[sb + 3] = vy.w - 0.5f * vi.w;
        __syncthreads();

        int yl = tid >> 3;             // 0..31
        int c4 = (tid & 7) << 2;       // 0,4..28
        size_t o = (((size_t)b * HH + xx) * WW + y0 + yl) * CIN + c0 + c4;
        float4 oi, ot, o1, o2;
        oi.x = tI[(c4 + 0) * 33 + yl]; oi.y = tI[(c4 + 1) * 33 + yl];
        oi.z = tI[(c4 + 2) * 33 + yl]; oi.w = tI[(c4 + 3) * 33 + yl];
        ot.x = tT[(c4 + 0) * 33 + yl]; ot.y = tT[(c4 + 1) * 33 + yl];
        ot.z = tT[(c4 + 2) * 33 + yl]; ot.w = tT[(c4 + 3) * 33 + yl];
        o1.x = t1[(c4 + 0) * 33 + yl]; o1.y = t1[(c4 + 1) * 33 + yl];
        o1.z = t1[(c4 + 2) * 33 + yl]; o1.w = t1[(c4 + 3) * 33 + yl];
        o2.x = t2[(c4 + 0) * 33 + yl]; o2.y = t2[(c4 + 1) * 33 + yl];
        o2.z = t2[(c4 + 2) * 33 + yl]; o2.w = t2[(c4 + 3) * 33 + yl];
        *(float4*)(g_TI + o) = oi;
        *(float4*)(g_TT + o) = ot;
        *(float4*)(g_A1 + o) = o1;
        *(float4*)(g_A2 + o) = o2;
        return;
    }

    // ================= per-point branch =================
    float* sxs   = (float*)smem_raw;                 // [0, 16384)
    float* part  = (float*)(smem_raw + 16384);       // [16384, 24576)
    float* rpart = (float*)(smem_raw + 24576);       // 448 B
    float* slog  = (float*)(smem_raw + 25024);       // 2272 B
    float* srect = (float*)(smem_raw + 27296);       // 1792 B

    int pt0 = (blockIdx.x - NT_BLOCKS) * 8;

    {
        const float4* src = (const float4*)(x + (size_t)pt0 * CC);
        float4* dst = (float4*)sxs;
        for (int i = tid; i < 8 * CC / 4; i += 256) dst[i] = src[i];
    }
    __syncthreads();

    // ---- mask logits: j = tid&63, c-chunk q = tid>>6 (128 c each) ----
    {
        int j = tid & 63, q = tid >> 6;
        int cbase = q * 128;
        float acc[8];
        #pragma unroll
        for (int p = 0; p < 8; p++) acc[p] = 0.f;
        #pragma unroll 4
        for (int c4i = 0; c4i < 32; c4i++) {
            int c = cbase + c4i * 4;
            float w0 = __ldg(&Wm[(size_t)(c + 0) * 64 + j]);
            float w1 = __ldg(&Wm[(size_t)(c + 1) * 64 + j]);
            float w2 = __ldg(&Wm[(size_t)(c + 2) * 64 + j]);
            float w3 = __ldg(&Wm[(size_t)(c + 3) * 64 + j]);
            #pragma unroll
            for (int p = 0; p < 8; p++) {
                float4 u = *(const float4*)(sxs + p * CC + c);
                acc[p] += u.x * w0 + u.y * w1 + u.z * w2 + u.w * w3;
            }
        }
        #pragma unroll
        for (int p = 0; p < 8; p++) part[tid * 8 + p] = acc[p];
    }
    // ---- ratio logits: Kahan, 8 pts x 7 logits x 2 chunks = 112 threads ----
    if (tid < 112) {
        int p = tid / 14, rem = tid % 14;
        int j = rem % 7, h = rem / 7;
        int c0 = h * 256;
        const float* sx = sxs + p * CC;
        float s = 0.f, comp = 0.f;
        #pragma unroll 4
        for (int c = 0; c < 256; c++) {
            float t = __fmul_rn(sx[c0 + c], Wr[(size_t)(c0 + c) * 7 + j]);
            float y = __fadd_rn(t, -comp);
            float u = __fadd_rn(s, y);
            comp = __fadd_rn(__fadd_rn(u, -s), -y);
            s = u;
        }
        rpart[p * 14 + h * 7 + j] = s;
    }
    __syncthreads();
    if (tid < 64) {
        int j = tid;
        float bmv = bm[j];
        #pragma unroll
        for (int p = 0; p < 8; p++) {
            float v = ((part[(0 * 64 + j) * 8 + p] + part[(1 * 64 + j) * 8 + p])
                     + (part[(2 * 64 + j) * 8 + p] + part[(3 * 64 + j) * 8 + p])) + bmv;
            slog[p * 71 + 7 + j] = v;
        }
    }
    if (tid < 56) {
        int p = tid / 7, j = tid % 7;
        slog[p * 71 + j] = __fadd_rn(__fadd_rn(rpart[p * 14 + j], rpart[p * 14 + 7 + j]), br[j]);
    }
    __syncthreads();

    // ---- rect cascade: thread p < 8 per point ----
    if (tid < 8) {
        int p = tid;
        const float* sl = slog + p * 71;
        float* sr = srect + p * 56;
        const float* rp = r + (size_t)(pt0 + p) * 4;
        float p0 = rp[0], p1 = rp[1], p2 = rp[2], p3 = rp[3];
        float rA[2][4], rBv[4][4], rCv[8][4];
        {
            float rat = sigmoidf_(sl[0]);
            float mid = p0 * (1.f - rat) + p2 * rat;
            rA[0][0] = p0;  rA[0][1] = p1; rA[0][2] = mid; rA[0][3] = p3;
            rA[1][0] = mid; rA[1][1] = p1; rA[1][2] = p2;  rA[1][3] = p3;
        }
        for (int j = 0; j < 2; j++) {
            float rat = sigmoidf_(sl[1 + j]);
            float mid = rA[j][1] * (1.f - rat) + rA[j][3] * rat;
            rBv[j][0] = rA[j][0]; rBv[j][1] = rA[j][1]; rBv[j][2] = rA[j][2]; rBv[j][3] = mid;
            rBv[2 + j][0] = rA[j][0]; rBv[2 + j][1] = mid; rBv[2 + j][2] = rA[j][2]; rBv[2 + j][3] = rA[j][3];
        }
        for (int j = 0; j < 4; j++) {
            float rat = sigmoidf_(sl[3 + j]);
            float mid = rBv[j][0] * (1.f - rat) + rBv[j][2] * rat;
            rCv[j][0] = rBv[j][0]; rCv[j][1] = rBv[j][1]; rCv[j][2] = mid; rCv[j][3] = rBv[j][3];
            rCv[4 + j][0] = mid; rCv[4 + j][1] = rBv[j][1]; rCv[4 + j][2] = rBv[j][2]; rCv[4 + j][3] = rBv[j][3];
        }
        for (int j = 0; j < 2; j++) for (int q = 0; q < 4; q++) sr[j * 4 + q] = rA[j][q];
        for (int j = 0; j < 4; j++) for (int q = 0; q < 4; q++) sr[8 + j * 4 + q] = rBv[j][q];
        for (int j = 0; j < 8; j++) for (int q = 0; q < 4; q++) sr[24 + j * 4 + q] = rCv[j][q];
    }
    // ---- softmax: 64 threads, (p, g) ----
    if (tid < 64) {
        int p = tid >> 3, g = tid & 7;
        const float* sl = slog + p * 71;
        float mx = -1e30f;
        for (int s = 0; s < 8; s++) mx = fmaxf(mx, sl[7 + s * 8 + g]);
        float e[8], sum = 0.f;
        for (int s = 0; s < 8; s++) { e[s] = expf(sl[7 + s * 8 + g] - mx); sum += e[s]; }
        float inv = 1.f / sum;
        for (int s = 0; s < 8; s++) g_mask[(size_t)(pt0 + p) * 64 + s * 8 + g] = e[s] * inv;
    }
    __syncthreads();

    const size_t O1 = (size_t)PTS * CC;
    const size_t O2 = O1 + (size_t)PTS * 8;
    const size_t O3 = O2 + (size_t)PTS * 16;
    if (tid < 64)  { int p = tid >> 3, i = tid & 7;  out[O1 + (size_t)(pt0 + p) * 8 + i]  = srect[p * 56 + i]; }
    if (tid < 128) { int p = tid >> 4, i = tid & 15; out[O2 + (size_t)(pt0 + p) * 16 + i] = srect[p * 56 + 8 + i]; }
    {              int p = tid >> 5, i = tid & 31; out[O3 + (size_t)(pt0 + p) * 32 + i] = srect[p * 56 + 24 + i]; }
}

// ---------------------------------------------------------------------------
// Corner eval (boundary terms cancel across the 4-corner combination): 9 loads.
// ---------------------------------------------------------------------------
__device__ __forceinline__ float4 corner_nb(const float4* __restrict__ TI,
                                            const float4* __restrict__ TT,
                                            const float4* __restrict__ A1,
                                            const float4* __restrict__ A2,
                                            int lane, float px, float py)
{
    float X = ceilf(px), Y = ceilf(py);
    int Xi = (int)X, Yi = (int)Y;
    int Xm = max(Xi - 1, 0), Ym = max(Yi - 1, 0);
    float dx = X - px, dy = Y - py;
    float wx1 = 0.5f * (dx * dx), wx2 = dx - wx1;
    float wy1 = 0.5f * (dy * dy), wy2 = dy - wy1;
#define AT4(T, xi, yi) __ldg(&T[(((xi) * WW + (yi)) << 5) + lane])
    float4 s = AT4(TT, Xi, Yi);
    s = f4sub(s, f4add(f4scale(wy1, AT4(A1, Xi, Ym)), f4scale(wy2, AT4(A1, Xi, Yi))));
    s = f4sub(s, f4add(f4scale(wx1, AT4(A2, Xm, Yi)), f4scale(wx2, AT4(A2, Xi, Yi))));
    s = f4add(s, f4add(f4add(f4scale(wx1 * wy1, AT4(TI, Xm, Ym)),
                             f4scale(wx2 * wy1, AT4(TI, Xi, Ym))),
                       f4add(f4scale(wx1 * wy2, AT4(TI, Xm, Yi)),
                             f4scale(wx2 * wy2, AT4(TI, Xi, Yi)))));
#undef AT4
    return s;
}

// ---------------------------------------------------------------------------
// Kernel 2 (fused): coefficient-streamed sampling + group-GEMM + LayerNorm +
// residual. Block = 8 points, 256 threads; warp = point in phase 1.
// ---------------------------------------------------------------------------
__global__ void __launch_bounds__(256)
k_fused(const float* __restrict__ x, const float* __restrict__ Ws,
        const float* __restrict__ bs, const float* __restrict__ lg,
        const float* __restrict__ lb, float* __restrict__ out)
{
    __shared__ __align__(16) float sU[8 * 1024];  // U[p][g*128+k]; later y[p][c]
    __shared__ float2 scoord[8][18];
    __shared__ __align__(16) float scoef[8][18 * 8];
    __shared__ float smu[8], srs[8];
    int tid = threadIdx.x;
    int wid = tid >> 5, lane = tid & 31;
    int pt0 = blockIdx.x * 8;
    int pt = pt0 + wid;
    int b = pt / NN;

    const size_t O3 = (size_t)PTS * CC + (size_t)PTS * 8 + (size_t)PTS * 16;
    const float* rp = out + O3 + (size_t)pt * 32;
    const float* mp = g_mask + (size_t)pt * 64;
    const float F = (float)(HH - 1);

    // ---------------- Phase 0: per-point corner coords + coefficients ----------------
    if (lane < 18) {
        float cx = __ldg(&rp[c_cx[lane]]) * F;
        float cy = __ldg(&rp[c_cy[lane]]) * F;
        scoord[wid][lane] = make_float2(cx, cy);
        int r1i = c_r1[lane], r2i = c_r2[lane];
        float x1 = __ldg(&rp[4 * r1i]) * F,  y1 = __ldg(&rp[4 * r1i + 1]) * F;
        float x2 = __ldg(&rp[4 * r1i + 2]) * F, y2 = __ldg(&rp[4 * r1i + 3]) * F;
        float w1 = c_s1[lane] / (fabsf((x1 - x2) * (y1 - y2)) + 1e-9f);
        float x1b = __ldg(&rp[4 * r2i]) * F,  y1b = __ldg(&rp[4 * r2i + 1]) * F;
        float x2b = __ldg(&rp[4 * r2i + 2]) * F, y2b = __ldg(&rp[4 * r2i + 3]) * F;
        float w2 = c_s2[lane] / (fabsf((x1b - x2b) * (y1b - y2b)) + 1e-9f);
        #pragma unroll
        for (int g = 0; g < 8; g++)
            scoef[wid][lane * 8 + g] = w1 * __ldg(&mp[r1i * 8 + g]) + w2 * __ldg(&mp[r2i * 8 + g]);
    }
    __syncwarp();

    // ---------------- Phase 1: stream 18 corners into U ----------------
    {
        size_t ib4 = (size_t)b * (HH * WW * CIN / 4);
        const float4* TI = (const float4*)g_TI + ib4;
        const float4* TT = (const float4*)g_TT + ib4;
        const float4* A1 = (const float4*)g_A1 + ib4;
        const float4* A2 = (const float4*)g_A2 + ib4;

        float4 U[8];
        #pragma unroll
        for (int g = 0; g < 8; g++) U[g] = make_float4(0.f, 0.f, 0.f, 0.f);

        const float4* cf4 = (const float4*)scoef[wid];
        #pragma unroll 6
        for (int e = 0; e < 18; e++) {
            float2 cc = scoord[wid][e];
            float4 v = corner_nb(TI, TT, A1, A2, lane, cc.x, cc.y);
            float4 ca = cf4[e * 2], cb = cf4[e * 2 + 1];
            U[0].x += ca.x * v.x; U[0].y += ca.x * v.y; U[0].z += ca.x * v.z; U[0].w += ca.x * v.w;
            U[1].x += ca.y * v.x; U[1].y += ca.y * v.y; U[1].z += ca.y * v.z; U[1].w += ca.y * v.w;
            U[2].x += ca.z * v.x; U[2].y += ca.z * v.y; U[2].z += ca.z * v.z; U[2].w += ca.z * v.w;
            U[3].x += ca.w * v.x; U[3].y += ca.w * v.y; U[3].z += ca.w * v.z; U[3].w += ca.w * v.w;
            U[4].x += cb.x * v.x; U[4].y += cb.x * v.y; U[4].z += cb.x * v.z; U[4].w += cb.x * v.w;
            U[5].x += cb.y * v.x; U[5].y += cb.y * v.y; U[5].z += cb.y * v.z; U[5].w += cb.y * v.w;
            U[6].x += cb.z * v.x; U[6].y += cb.z * v.y; U[6].z += cb.z * v.z; U[6].w += cb.z * v.w;
            U[7].x += cb.w * v.x; U[7].y += cb.w * v.y; U[7].z += cb.w * v.z; U[7].w += cb.w * v.w;
        }
        float4* up = (float4*)(sU + wid * 1024);
        #pragma unroll
        for (int g = 0; g < 8; g++) up[g * 32 + lane] = U[g];
    }
    __syncthreads();

    // ---------------- Phase 2: group-GEMM ----------------
    int g = tid >> 5;
    const float2* W2 = (const float2*)Ws;
    float2 acc[8];
    #pragma unroll
    for (int p = 0; p < 8; p++) acc[p] = make_float2(0.f, 0.f);

    const float4* sU4 = (const float4*)sU;
    for (int k4 = 0; k4 < 32; k4++) {
        int kb = k4 * 4;
        float2 w0 = __ldg(&W2[(kb + 0) * 256 + tid]);
        float2 w1 = __ldg(&W2[(kb + 1) * 256 + tid]);
        float2 w2 = __ldg(&W2[(kb + 2) * 256 + tid]);
        float2 w3 = __ldg(&W2[(kb + 3) * 256 + tid]);
        #pragma unroll
        for (int p = 0; p < 8; p++) {
            float4 u = sU4[p * 256 + g * 32 + k4];
            acc[p].x += u.x * w0.x + u.y * w1.x + u.z * w2.x + u.w * w3.x;
            acc[p].y += u.x * w0.y + u.y * w1.y + u.z * w2.y + u.w * w3.y;
        }
    }
    float2 bsv = __ldg(&((const float2*)bs)[tid]);
    __syncthreads();
    #pragma unroll
    for (int p = 0; p < 8; p++) {
        sU[p * 512 + 2 * tid]     = acc[p].x + bsv.x;
        sU[p * 512 + 2 * tid + 1] = acc[p].y + bsv.y;
    }
    __syncthreads();

    // ---------------- Phase 3: LayerNorm stats (warp per point) ----------------
    {
        float sum = 0.f, sq = 0.f;
        for (int i = lane; i < 512; i += 32) {
            float v = sU[wid * 512 + i];
            sum += v; sq += v * v;
        }
        #pragma unroll
        for (int o = 16; o; o >>= 1) {
            sum += __shfl_xor_sync(0xffffffffu, sum, o);
            sq  += __shfl_xor_sync(0xffffffffu, sq, o);
        }
        if (lane == 0) {
            float mu = sum * (1.f / 512.f);
            float var = sq * (1.f / 512.f) - mu * mu;
            smu[wid] = mu;
            srs[wid] = rsqrtf(var + 1e-5f);
        }
    }
    __syncthreads();

    // ---------------- Phase 4: normalize + residual + store ----------------
    float2 gg = __ldg(&((const float2*)lg)[tid]);
    float2 bb = __ldg(&((const float2*)lb)[tid]);
    const float2* x2 = (const float2*)x;
    float2* o2 = (float2*)out;
    #pragma unroll
    for (int p = 0; p < 8; p++) {
        float mu = smu[p], rs = srs[p];
        float2 v = make_float2(sU[p * 512 + 2 * tid], sU[p * 512 + 2 * tid + 1]);
        float2 xr = __ldg(&x2[(size_t)(pt0 + p) * 256 + tid]);
        float2 o;
        o.x = (v.x - mu) * rs * gg.x + bb.x + xr.x;
        o.y = (v.y - mu) * rs * gg.y + bb.y + xr.y;
        o2[(size_t)(pt0 + p) * 256 + tid] = o;
    }
}

// ---------------------------------------------------------------------------
extern "C" void kernel_launch(void* const* d_in, const int* in_sizes, int n_in,
                              void* d_out, int out_size)
{
    const float* x  = (const float*)d_in[0];
    const float* r  = (const float*)d_in[1];
    const float* I  = (const float*)d_in[2];
    const float* IX = (const float*)d_in[3];
    const float* IY = (const float*)d_in[4];
    const float* IT = (const float*)d_in[5];
    const float* Wr = (const float*)d_in[6];
    const float* br = (const float*)d_in[7];
    const float* Wm = (const float*)d_in[8];
    const float* bm = (const float*)d_in[9];
    const float* Ws = (const float*)d_in[10];
    const float* bs = (const float*)d_in[11];
    const float* lg = (const float*)d_in[12];
    const float* lb = (const float*)d_in[13];
    float* out = (float*)d_out;
    (void)in_sizes; (void)n_in; (void)out_size;

    k_pre<<<NT_BLOCKS + NP_BLOCKS, 256>>>(I, IX, IY, IT, x, r, Wr, br, Wm, bm, out);
    k_fused<<<PTS / 8, 256>>>(x, Ws, bs, lg, lb, out);
}

// round 10
// speedup vs baseline: 20.5805x; 1.1383x over previous
#include <cuda_runtime.h>
#include <math.h>

#define BB 8
#define NN 2048
#define CC 512
#define CIN 128
#define HH 96
#define WW 96
#define PTS (BB*NN)               // 16384
#define IMG_ELEMS (BB*HH*WW*CIN)  // 9,437,184

// k_pre striping: 11264 blocks = 1024 groups of (9 transpose + 2 point)
#define NT_BLOCKS 9216
#define NP_BLOCKS (PTS/8)         // 2048
#define PRE_BLOCKS (NT_BLOCKS + NP_BLOCKS)

// Scratch (static __device__ arrays — no allocation)
__device__ float g_TI[IMG_ELEMS];   // I  transposed to [b][x][y][c]
__device__ float g_TT[IMG_ELEMS];   // IT transposed
__device__ float g_A1[IMG_ELEMS];   // IX - 0.5*I transposed
__device__ float g_A2[IMG_ELEMS];   // IY - 0.5*I transposed
__device__ float g_mask[PTS*64];    // softmax mask [pt][s*8+g]

// ---------------------------------------------------------------------------
__device__ __forceinline__ float4 f4add(float4 a, float4 b) {
    return make_float4(a.x + b.x, a.y + b.y, a.z + b.z, a.w + b.w);
}
__device__ __forceinline__ float4 f4sub(float4 a, float4 b) {
    return make_float4(a.x - b.x, a.y - b.y, a.z - b.z, a.w - b.w);
}
__device__ __forceinline__ float4 f4scale(float s, float4 a) {
    return make_float4(s * a.x, s * a.y, s * a.z, s * a.w);
}
__device__ __forceinline__ float sigmoidf_(float v) { return 1.f / (1.f + expf(-v)); }

// ---------------------------------------------------------------------------
// Kernel 1 (merged + striped): every group of 11 consecutive blocks carries
// 9 transpose blocks and 2 point blocks, so both independent workloads
// co-reside on the SMs from the first wave (true overlap).
// ---------------------------------------------------------------------------
__global__ void __launch_bounds__(256)
k_pre(const float* __restrict__ I, const float* __restrict__ IX,
      const float* __restrict__ IY, const float* __restrict__ IT,
      const float* __restrict__ x, const float* __restrict__ r,
      const float* __restrict__ Wr, const float* __restrict__ br,
      const float* __restrict__ Wm, const float* __restrict__ bm,
      float* __restrict__ out)
{
    __shared__ __align__(16) char smem_raw[29120];
    int tid = threadIdx.x;
    int grp = blockIdx.x / 11, loc = blockIdx.x % 11;

    if (loc < 9) {
        // ================= transpose branch (vectorized) =================
        float* tI = (float*)smem_raw;            // [32][33]
        float* tT = tI + 1056;
        float* t1 = tT + 1056;
        float* t2 = t1 + 1056;

        int t = grp * 9 + loc;
        int y0 = (t % 3) * 32;
        int c0 = ((t / 3) & 3) * 32;
        int xx = (t / 12) % HH;
        int b  = t / (12 * HH);

        int cl = tid >> 3;             // 0..31
        int y4 = (tid & 7) << 2;       // 0,4..28

        size_t idx = ((size_t)(b * CIN + c0 + cl) * (HH * WW) + (size_t)xx * WW + y0 + y4);
        float4 vi = *(const float4*)(I + idx);
        float4 vx = *(const float4*)(IX + idx);
        float4 vy = *(const float4*)(IY + idx);
        float4 vt = *(const float4*)(IT + idx);

        int sb = cl * 33 + y4;
        tI[sb + 0] = vi.x; tI[sb + 1] = vi.y; tI[sb + 2] = vi.z; tI[sb + 3] = vi.w;
        tT[sb + 0] = vt.x; tT[sb + 1] = vt.y; tT[sb + 2] = vt.z; tT[sb + 3] = vt.w;
        t1[sb + 0] = vx.x - 0.5f * vi.x; t1[sb + 1] = vx.y - 0.5f * vi.y;
        t1[sb + 2] = vx.z - 0.5f * vi.z; t1[sb + 3] = vx.w - 0.5f * vi.w;
        t2[sb + 0] = vy.x - 0.5f * vi.x; t2[sb + 1] = vy.y - 0.5f * vi.y;
        t2[sb + 2] = vy.z - 0.5f * vi.z; t2[sb + 3] = vy.w - 0.5f * vi.w;
        __syncthreads();

        int yl = tid >> 3;             // 0..31
        int c4 = (tid & 7) << 2;       // 0,4..28
        size_t o = (((size_t)b * HH + xx) * WW + y0 + yl) * CIN + c0 + c4;
        float4 oi, ot, o1, o2;
        oi.x = tI[(c4 + 0) * 33 + yl]; oi.y = tI[(c4 + 1) * 33 + yl];
        oi.z = tI[(c4 + 2) * 33 + yl]; oi.w = tI[(c4 + 3) * 33 + yl];
        ot.x = tT[(c4 + 0) * 33 + yl]; ot.y = tT[(c4 + 1) * 33 + yl];
        ot.z = tT[(c4 + 2) * 33 + yl]; ot.w = tT[(c4 + 3) * 33 + yl];
        o1.x = t1[(c4 + 0) * 33 + yl]; o1.y = t1[(c4 + 1) * 33 + yl];
        o1.z = t1[(c4 + 2) * 33 + yl]; o1.w = t1[(c4 + 3) * 33 + yl];
        o2.x = t2[(c4 + 0) * 33 + yl]; o2.y = t2[(c4 + 1) * 33 + yl];
        o2.z = t2[(c4 + 2) * 33 + yl]; o2.w = t2[(c4 + 3) * 33 + yl];
        *(float4*)(g_TI + o) = oi;
        *(float4*)(g_TT + o) = ot;
        *(float4*)(g_A1 + o) = o1;
        *(float4*)(g_A2 + o) = o2;
        return;
    }

    // ================= per-point branch =================
    float* sxs   = (float*)smem_raw;                 // [0, 16384)
    float* part  = (float*)(smem_raw + 16384);       // [16384, 24576)
    float* rpart = (float*)(smem_raw + 24576);       // 448 B
    float* slog  = (float*)(smem_raw + 25024);       // 2272 B
    float* srect = (float*)(smem_raw + 27296);       // 1792 B

    int pt0 = (grp * 2 + (loc - 9)) * 8;

    {
        const float4* src = (const float4*)(x + (size_t)pt0 * CC);
        float4* dst = (float4*)sxs;
        for (int i = tid; i < 8 * CC / 4; i += 256) dst[i] = src[i];
    }
    __syncthreads();

    // ---- mask logits: j = tid&63, c-chunk q = tid>>6 (128 c each) ----
    {
        int j = tid & 63, q = tid >> 6;
        int cbase = q * 128;
        float acc[8];
        #pragma unroll
        for (int p = 0; p < 8; p++) acc[p] = 0.f;
        #pragma unroll 4
        for (int c4i = 0; c4i < 32; c4i++) {
            int c = cbase + c4i * 4;
            float w0 = __ldg(&Wm[(size_t)(c + 0) * 64 + j]);
            float w1 = __ldg(&Wm[(size_t)(c + 1) * 64 + j]);
            float w2 = __ldg(&Wm[(size_t)(c + 2) * 64 + j]);
            float w3 = __ldg(&Wm[(size_t)(c + 3) * 64 + j]);
            #pragma unroll
            for (int p = 0; p < 8; p++) {
                float4 u = *(const float4*)(sxs + p * CC + c);
                acc[p] += u.x * w0 + u.y * w1 + u.z * w2 + u.w * w3;
            }
        }
        #pragma unroll
        for (int p = 0; p < 8; p++) part[tid * 8 + p] = acc[p];
    }
    // ---- ratio logits: Kahan, 8 pts x 7 logits x 2 chunks = 112 threads ----
    if (tid < 112) {
        int p = tid / 14, rem = tid % 14;
        int j = rem % 7, h = rem / 7;
        int c0 = h * 256;
        const float* sx = sxs + p * CC;
        float s = 0.f, comp = 0.f;
        #pragma unroll 4
        for (int c = 0; c < 256; c++) {
            float t = __fmul_rn(sx[c0 + c], Wr[(size_t)(c0 + c) * 7 + j]);
            float y = __fadd_rn(t, -comp);
            float u = __fadd_rn(s, y);
            comp = __fadd_rn(__fadd_rn(u, -s), -y);
            s = u;
        }
        rpart[p * 14 + h * 7 + j] = s;
    }
    __syncthreads();
    if (tid < 64) {
        int j = tid;
        float bmv = bm[j];
        #pragma unroll
        for (int p = 0; p < 8; p++) {
            float v = ((part[(0 * 64 + j) * 8 + p] + part[(1 * 64 + j) * 8 + p])
                     + (part[(2 * 64 + j) * 8 + p] + part[(3 * 64 + j) * 8 + p])) + bmv;
            slog[p * 71 + 7 + j] = v;
        }
    }
    if (tid < 56) {
        int p = tid / 7, j = tid % 7;
        slog[p * 71 + j] = __fadd_rn(__fadd_rn(rpart[p * 14 + j], rpart[p * 14 + 7 + j]), br[j]);
    }
    __syncthreads();

    // ---- rect cascade: thread p < 8 per point ----
    if (tid < 8) {
        int p = tid;
        const float* sl = slog + p * 71;
        float* sr = srect + p * 56;
        const float* rp = r + (size_t)(pt0 + p) * 4;
        float p0 = rp[0], p1 = rp[1], p2 = rp[2], p3 = rp[3];
        float rA[2][4], rBv[4][4], rCv[8][4];
        {
            float rat = sigmoidf_(sl[0]);
            float mid = p0 * (1.f - rat) + p2 * rat;
            rA[0][0] = p0;  rA[0][1] = p1; rA[0][2] = mid; rA[0][3] = p3;
            rA[1][0] = mid; rA[1][1] = p1; rA[1][2] = p2;  rA[1][3] = p3;
        }
        for (int j = 0; j < 2; j++) {
            float rat = sigmoidf_(sl[1 + j]);
            float mid = rA[j][1] * (1.f - rat) + rA[j][3] * rat;
            rBv[j][0] = rA[j][0]; rBv[j][1] = rA[j][1]; rBv[j][2] = rA[j][2]; rBv[j][3] = mid;
            rBv[2 + j][0] = rA[j][0]; rBv[2 + j][1] = mid; rBv[2 + j][2] = rA[j][2]; rBv[2 + j][3] = rA[j][3];
        }
        for (int j = 0; j < 4; j++) {
            float rat = sigmoidf_(sl[3 + j]);
            float mid = rBv[j][0] * (1.f - rat) + rBv[j][2] * rat;
            rCv[j][0] = rBv[j][0]; rCv[j][1] = rBv[j][1]; rCv[j][2] = mid; rCv[j][3] = rBv[j][3];
            rCv[4 + j][0] = mid; rCv[4 + j][1] = rBv[j][1]; rCv[4 + j][2] = rBv[j][2]; rCv[4 + j][3] = rBv[j][3];
        }
        for (int j = 0; j < 2; j++) for (int q = 0; q < 4; q++) sr[j * 4 + q] = rA[j][q];
        for (int j = 0; j < 4; j++) for (int q = 0; q < 4; q++) sr[8 + j * 4 + q] = rBv[j][q];
        for (int j = 0; j < 8; j++) for (int q = 0; q < 4; q++) sr[24 + j * 4 + q] = rCv[j][q];
    }
    // ---- softmax: 64 threads, (p, g) ----
    if (tid < 64) {
        int p = tid >> 3, g = tid & 7;
        const float* sl = slog + p * 71;
        float mx = -1e30f;
        for (int s = 0; s < 8; s++) mx = fmaxf(mx, sl[7 + s * 8 + g]);
        float e[8], sum = 0.f;
        for (int s = 0; s < 8; s++) { e[s] = expf(sl[7 + s * 8 + g] - mx); sum += e[s]; }
        float inv = 1.f / sum;
        for (int s = 0; s < 8; s++) g_mask[(size_t)(pt0 + p) * 64 + s * 8 + g] = e[s] * inv;
    }
    __syncthreads();

    const size_t O1 = (size_t)PTS * CC;
    const size_t O2 = O1 + (size_t)PTS * 8;
    const size_t O3 = O2 + (size_t)PTS * 16;
    if (tid < 64)  { int p = tid >> 3, i = tid & 7;  out[O1 + (size_t)(pt0 + p) * 8 + i]  = srect[p * 56 + i]; }
    if (tid < 128) { int p = tid >> 4, i = tid & 15; out[O2 + (size_t)(pt0 + p) * 16 + i] = srect[p * 56 + 8 + i]; }
    {              int p = tid >> 5, i = tid & 31; out[O3 + (size_t)(pt0 + p) * 32 + i] = srect[p * 56 + 24 + i]; }
}

// ---------------------------------------------------------------------------
// Corner eval (boundary terms cancel across the 4-corner combination): 9 loads.
// ---------------------------------------------------------------------------
__device__ __forceinline__ float4 corner_nb(const float4* __restrict__ TI,
                                            const float4* __restrict__ TT,
                                            const float4* __restrict__ A1,
                                            const float4* __restrict__ A2,
                                            int lane, float px, float py)
{
    float X = ceilf(px), Y = ceilf(py);
    int Xi = (int)X, Yi = (int)Y;
    int Xm = max(Xi - 1, 0), Ym = max(Yi - 1, 0);
    float dx = X - px, dy = Y - py;
    float wx1 = 0.5f * (dx * dx), wx2 = dx - wx1;
    float wy1 = 0.5f * (dy * dy), wy2 = dy - wy1;
#define AT4(T, xi, yi) __ldg(&T[(((xi) * WW + (yi)) << 5) + lane])
    float4 s = AT4(TT, Xi, Yi);
    s = f4sub(s, f4add(f4scale(wy1, AT4(A1, Xi, Ym)), f4scale(wy2, AT4(A1, Xi, Yi))));
    s = f4sub(s, f4add(f4scale(wx1, AT4(A2, Xm, Yi)), f4scale(wx2, AT4(A2, Xi, Yi))));
    s = f4add(s, f4add(f4add(f4scale(wx1 * wy1, AT4(TI, Xm, Ym)),
                             f4scale(wx2 * wy1, AT4(TI, Xi, Ym))),
                       f4add(f4scale(wx1 * wy2, AT4(TI, Xm, Yi)),
                             f4scale(wx2 * wy2, AT4(TI, Xi, Yi)))));
#undef AT4
    return s;
}

// ---------------------------------------------------------------------------
// Kernel 2 (fused): corner-streamed sampling into per-RECT sums S[8]
// (signed adds, compile-time tables), then mask*inv combine -> U in smem,
// then group-GEMM + LayerNorm + residual. Block = 8 points, 256 threads.
// ---------------------------------------------------------------------------
__global__ void __launch_bounds__(256)
k_fused(const float* __restrict__ x, const float* __restrict__ Ws,
        const float* __restrict__ bs, const float* __restrict__ lg,
        const float* __restrict__ lb, float* __restrict__ out)
{
    __shared__ __align__(16) float sU[8 * 1024];     // U[p][g*128+k]; later y[p][c]
    __shared__ float2 scoord[8][18];
    __shared__ float scoefR[8][64];                  // mask[r][g]*inv_r
    __shared__ float sinv[8][8];
    __shared__ float smu[8], srs[8];
    int tid = threadIdx.x;
    int wid = tid >> 5, lane = tid & 31;
    int pt0 = blockIdx.x * 8;
    int pt = pt0 + wid;
    int b = pt / NN;

    const size_t O3 = (size_t)PTS * CC + (size_t)PTS * 8 + (size_t)PTS * 16;
    const float* rp = out + O3 + (size_t)pt * 32;
    const float* mp = g_mask + (size_t)pt * 64;
    const float F = (float)(HH - 1);

    // Compile-time corner tables (local const arrays fold under full unroll)
    const int   T_CX[18] = {0,0,0, 4,4,4,4, 22,22,22, 2,2, 6,6, 10,10, 14,14};
    const int   T_CY[18] = {1,3,11, 1,3,7,11, 1,7,11, 1,3, 1,7, 3,11, 7,11};
    const int   T_R1[18] = {0,0,2, 4,4,1,6, 5,5,7, 0,0, 1,1, 2,2, 3,3};
    const int   T_S1[18] = {1,-1,-1, -1,1,-1,1, -1,1,1, -1,1, -1,1, -1,1, -1,1};
    const int   T_R2[18] = {0,2,0, 1,6,3,3, 0,7,0, 4,4, 5,5, 6,6, 7,7};
    const int   T_S2[18] = {0,1,0, 1,-1,1,-1, 0,-1,0, 1,-1, 1,-1, 1,-1, 1,-1};

    // ---------------- Phase 0: coords + per-rect coefficients ----------------
    if (lane < 18) {
        scoord[wid][lane] = make_float2(__ldg(&rp[T_CX[lane]]) * F,
                                        __ldg(&rp[T_CY[lane]]) * F);
    }
    if (lane < 8) {
        float x1 = __ldg(&rp[4 * lane]) * F,     y1 = __ldg(&rp[4 * lane + 1]) * F;
        float x2 = __ldg(&rp[4 * lane + 2]) * F, y2 = __ldg(&rp[4 * lane + 3]) * F;
        sinv[wid][lane] = 1.f / (fabsf((x1 - x2) * (y1 - y2)) + 1e-9f);
    }
    __syncwarp();
    #pragma unroll
    for (int t = lane; t < 64; t += 32)
        scoefR[wid][t] = __ldg(&mp[t]) * sinv[wid][t >> 3];
    __syncwarp();

    // ---------------- Phase 1: stream 18 corners into rect sums S ----------------
    {
        size_t ib4 = (size_t)b * (HH * WW * CIN / 4);
        const float4* TI = (const float4*)g_TI + ib4;
        const float4* TT = (const float4*)g_TT + ib4;
        const float4* A1 = (const float4*)g_A1 + ib4;
        const float4* A2 = (const float4*)g_A2 + ib4;

        float4 S[8];
        #pragma unroll
        for (int rr = 0; rr < 8; rr++) S[rr] = make_float4(0.f, 0.f, 0.f, 0.f);

        #pragma unroll
        for (int e = 0; e < 18; e++) {
            float2 cc = scoord[wid][e];
            float4 v = corner_nb(TI, TT, A1, A2, lane, cc.x, cc.y);
            if (T_S1[e] > 0) S[T_R1[e]] = f4add(S[T_R1[e]], v);
            else             S[T_R1[e]] = f4sub(S[T_R1[e]], v);
            if (T_S2[e] > 0)      S[T_R2[e]] = f4add(S[T_R2[e]], v);
            else if (T_S2[e] < 0) S[T_R2[e]] = f4sub(S[T_R2[e]], v);
        }

        // combine: U[g] = sum_r coefR[r*8+g] * S[r]
        const float* cr = scoefR[wid];
        float4* up = (float4*)(sU + wid * 1024);
        #pragma unroll
        for (int g = 0; g < 8; g++) {
            float4 u = make_float4(0.f, 0.f, 0.f, 0.f);
            #pragma unroll
            for (int rr = 0; rr < 8; rr++) {
                float c = cr[rr * 8 + g];
                u.x += c * S[rr].x; u.y += c * S[rr].y;
                u.z += c * S[rr].z; u.w += c * S[rr].w;
            }
            up[g * 32 + lane] = u;
        }
    }
    __syncthreads();

    // ---------------- Phase 2: group-GEMM ----------------
    int g = tid >> 5;
    const float2* W2 = (const float2*)Ws;
    float2 acc[8];
    #pragma unroll
    for (int p = 0; p < 8; p++) acc[p] = make_float2(0.f, 0.f);

    const float4* sU4 = (const float4*)sU;
    for (int k4 = 0; k4 < 32; k4++) {
        int kb = k4 * 4;
        float2 w0 = __ldg(&W2[(kb + 0) * 256 + tid]);
        float2 w1 = __ldg(&W2[(kb + 1) * 256 + tid]);
        float2 w2 = __ldg(&W2[(kb + 2) * 256 + tid]);
        float2 w3 = __ldg(&W2[(kb + 3) * 256 + tid]);
        #pragma unroll
        for (int p = 0; p < 8; p++) {
            float4 u = sU4[p * 256 + g * 32 + k4];
            acc[p].x += u.x * w0.x + u.y * w1.x + u.z * w2.x + u.w * w3.x;
            acc[p].y += u.x * w0.y + u.y * w1.y + u.z * w2.y + u.w * w3.y;
        }
    }
    float2 bsv = __ldg(&((const float2*)bs)[tid]);
    __syncthreads();
    #pragma unroll
    for (int p = 0; p < 8; p++) {
        sU[p * 512 + 2 * tid]     = acc[p].x + bsv.x;
        sU[p * 512 + 2 * tid + 1] = acc[p].y + bsv.y;
    }
    __syncthreads();

    // ---------------- Phase 3: LayerNorm stats (warp per point) ----------------
    {
        float sum = 0.f, sq = 0.f;
        for (int i = lane; i < 512; i += 32) {
            float v = sU[wid * 512 + i];
            sum += v; sq += v * v;
        }
        #pragma unroll
        for (int o = 16; o; o >>= 1) {
            sum += __shfl_xor_sync(0xffffffffu, sum, o);
            sq  += __shfl_xor_sync(0xffffffffu, sq, o);
        }
        if (lane == 0) {
            float mu = sum * (1.f / 512.f);
            float var = sq * (1.f / 512.f) - mu * mu;
            smu[wid] = mu;
            srs[wid] = rsqrtf(var + 1e-5f);
        }
    }
    __syncthreads();

    // ---------------- Phase 4: normalize + residual + store ----------------
    float2 gg = __ldg(&((const float2*)lg)[tid]);
    float2 bb = __ldg(&((const float2*)lb)[tid]);
    const float2* x2 = (const float2*)x;
    float2* o2 = (float2*)out;
    #pragma unroll
    for (int p = 0; p < 8; p++) {
        float mu = smu[p], rs = srs[p];
        float2 v = make_float2(sU[p * 512 + 2 * tid], sU[p * 512 + 2 * tid + 1]);
        float2 xr = __ldg(&x2[(size_t)(pt0 + p) * 256 + tid]);
        float2 o;
        o.x = (v.x - mu) * rs * gg.x + bb.x + xr.x;
        o.y = (v.y - mu) * rs * gg.y + bb.y + xr.y;
        o2[(size_t)(pt0 + p) * 256 + tid] = o;
    }
}

// ---------------------------------------------------------------------------
extern "C" void kernel_launch(void* const* d_in, const int* in_sizes, int n_in,
                              void* d_out, int out_size)
{
    const float* x  = (const float*)d_in[0];
    const float* r  = (const float*)d_in[1];
    const float* I  = (const float*)d_in[2];
    const float* IX = (const float*)d_in[3];
    const float* IY = (const float*)d_in[4];
    const float* IT = (const float*)d_in[5];
    const float* Wr = (const float*)d_in[6];
    const float* br = (const float*)d_in[7];
    const float* Wm = (const float*)d_in[8];
    const float* bm = (const float*)d_in[9];
    const float* Ws = (const float*)d_in[10];
    const float* bs = (const float*)d_in[11];
    const float* lg = (const float*)d_in[12];
    const float* lb = (const float*)d_in[13];
    float* out = (float*)d_out;
    (void)in_sizes; (void)n_in; (void)out_size;

    k_pre<<<PRE_BLOCKS, 256>>>(I, IX, IY, IT, x, r, Wr, br, Wm, bm, out);
    k_fused<<<PTS / 8, 256>>>(x, Ws, bs, lg, lb, out);
}

// round 11
// speedup vs baseline: 21.2926x; 1.0346x over previous
#include <cuda_runtime.h>
#include <math.h>

#define BB 8
#define NN 2048
#define CC 512
#define CIN 128
#define HH 96
#define WW 96
#define PTS (BB*NN)               // 16384
#define IMG_ELEMS (BB*HH*WW*CIN)  // 9,437,184

// k_pre striping: 11264 blocks = 1024 groups of (9 transpose + 2 point)
#define NT_BLOCKS 9216
#define NP_BLOCKS (PTS/8)         // 2048
#define PRE_BLOCKS (NT_BLOCKS + NP_BLOCKS)

// Scratch (static __device__ arrays — no allocation)
__device__ float g_TI[IMG_ELEMS];   // I  transposed to [b][x][y][c]
__device__ float g_TT[IMG_ELEMS];   // IT transposed
__device__ float g_A1[IMG_ELEMS];   // IX - 0.5*I transposed
__device__ float g_A2[IMG_ELEMS];   // IY - 0.5*I transposed
__device__ float g_mask[PTS*64];    // softmax mask [pt][s*8+g]

// ---------------------------------------------------------------------------
__device__ __forceinline__ float4 f4add(float4 a, float4 b) {
    return make_float4(a.x + b.x, a.y + b.y, a.z + b.z, a.w + b.w);
}
__device__ __forceinline__ float4 f4sub(float4 a, float4 b) {
    return make_float4(a.x - b.x, a.y - b.y, a.z - b.z, a.w - b.w);
}
__device__ __forceinline__ float4 f4scale(float s, float4 a) {
    return make_float4(s * a.x, s * a.y, s * a.z, s * a.w);
}
__device__ __forceinline__ float sigmoidf_(float v) { return 1.f / (1.f + expf(-v)); }

// ---------------------------------------------------------------------------
// Kernel 1 (merged + striped): every group of 11 consecutive blocks carries
// 9 transpose blocks and 2 point blocks (true overlap from wave 1).
// ---------------------------------------------------------------------------
__global__ void __launch_bounds__(256)
k_pre(const float* __restrict__ I, const float* __restrict__ IX,
      const float* __restrict__ IY, const float* __restrict__ IT,
      const float* __restrict__ x, const float* __restrict__ r,
      const float* __restrict__ Wr, const float* __restrict__ br,
      const float* __restrict__ Wm, const float* __restrict__ bm,
      float* __restrict__ out)
{
    __shared__ __align__(16) char smem_raw[29536];
    int tid = threadIdx.x;
    int grp = blockIdx.x / 11, loc = blockIdx.x % 11;

    if (loc < 9) {
        // ================= transpose branch (vectorized) =================
        float* tI = (float*)smem_raw;            // [32][33]
        float* tT = tI + 1056;
        float* t1 = tT + 1056;
        float* t2 = t1 + 1056;

        int t = grp * 9 + loc;
        int y0 = (t % 3) * 32;
        int c0 = ((t / 3) & 3) * 32;
        int xx = (t / 12) % HH;
        int b  = t / (12 * HH);

        int cl = tid >> 3;             // 0..31
        int y4 = (tid & 7) << 2;       // 0,4..28

        size_t idx = ((size_t)(b * CIN + c0 + cl) * (HH * WW) + (size_t)xx * WW + y0 + y4);
        float4 vi = *(const float4*)(I + idx);
        float4 vx = *(const float4*)(IX + idx);
        float4 vy = *(const float4*)(IY + idx);
        float4 vt = *(const float4*)(IT + idx);

        int sb = cl * 33 + y4;
        tI[sb + 0] = vi.x; tI[sb + 1] = vi.y; tI[sb + 2] = vi.z; tI[sb + 3] = vi.w;
        tT[sb + 0] = vt.x; tT[sb + 1] = vt.y; tT[sb + 2] = vt.z; tT[sb + 3] = vt.w;
        t1[sb + 0] = vx.x - 0.5f * vi.x; t1[sb + 1] = vx.y - 0.5f * vi.y;
        t1[sb + 2] = vx.z - 0.5f * vi.z; t1[sb + 3] = vx.w - 0.5f * vi.w;
        t2[sb + 0] = vy.x - 0.5f * vi.x; t2[sb + 1] = vy.y - 0.5f * vi.y;
        t2[sb + 2] = vy.z - 0.5f * vi.z; t2[sb + 3] = vy.w - 0.5f * vi.w;
        __syncthreads();

        int yl = tid >> 3;             // 0..31
        int c4 = (tid & 7) << 2;       // 0,4..28
        size_t o = (((size_t)b * HH + xx) * WW + y0 + yl) * CIN + c0 + c4;
        float4 oi, ot, o1, o2;
        oi.x = tI[(c4 + 0) * 33 + yl]; oi.y = tI[(c4 + 1) * 33 + yl];
        oi.z = tI[(c4 + 2) * 33 + yl]; oi.w = tI[(c4 + 3) * 33 + yl];
        ot.x = tT[(c4 + 0) * 33 + yl]; ot.y = tT[(c4 + 1) * 33 + yl];
        ot.z = tT[(c4 + 2) * 33 + yl]; ot.w = tT[(c4 + 3) * 33 + yl];
        o1.x = t1[(c4 + 0) * 33 + yl]; o1.y = t1[(c4 + 1) * 33 + yl];
        o1.z = t1[(c4 + 2) * 33 + yl]; o1.w = t1[(c4 + 3) * 33 + yl];
        o2.x = t2[(c4 + 0) * 33 + yl]; o2.y = t2[(c4 + 1) * 33 + yl];
        o2.z = t2[(c4 + 2) * 33 + yl]; o2.w = t2[(c4 + 3) * 33 + yl];
        *(float4*)(g_TI + o) = oi;
        *(float4*)(g_TT + o) = ot;
        *(float4*)(g_A1 + o) = o1;
        *(float4*)(g_A2 + o) = o2;
        return;
    }

    // ================= per-point branch =================
    float* sxs   = (float*)smem_raw;                 // [0, 16384)
    float* part  = (float*)(smem_raw + 16384);       // 8192 B
    float* rpart = (float*)(smem_raw + 24576);       // 896 B (8 pts x 7 x 4 chunks)
    float* slog  = (float*)(smem_raw + 25472);       // 2272 B
    float* srect = (float*)(smem_raw + 27744);       // 1792 B

    int pt0 = (grp * 2 + (loc - 9)) * 8;

    {
        const float4* src = (const float4*)(x + (size_t)pt0 * CC);
        float4* dst = (float4*)sxs;
        for (int i = tid; i < 8 * CC / 4; i += 256) dst[i] = src[i];
    }
    __syncthreads();

    // ---- mask logits: j = tid&63, c-chunk q = tid>>6 (128 c each) ----
    {
        int j = tid & 63, q = tid >> 6;
        int cbase = q * 128;
        float acc[8];
        #pragma unroll
        for (int p = 0; p < 8; p++) acc[p] = 0.f;
        #pragma unroll 4
        for (int c4i = 0; c4i < 32; c4i++) {
            int c = cbase + c4i * 4;
            float w0 = __ldg(&Wm[(size_t)(c + 0) * 64 + j]);
            float w1 = __ldg(&Wm[(size_t)(c + 1) * 64 + j]);
            float w2 = __ldg(&Wm[(size_t)(c + 2) * 64 + j]);
            float w3 = __ldg(&Wm[(size_t)(c + 3) * 64 + j]);
            #pragma unroll
            for (int p = 0; p < 8; p++) {
                float4 u = *(const float4*)(sxs + p * CC + c);
                acc[p] += u.x * w0 + u.y * w1 + u.z * w2 + u.w * w3;
            }
        }
        #pragma unroll
        for (int p = 0; p < 8; p++) part[tid * 8 + p] = acc[p];
    }
    // ---- ratio logits: Kahan, 8 pts x 7 logits x 4 chunks of 128 = 224 thr ----
    if (tid < 224) {
        int p = tid / 28, rem = tid % 28;
        int j = rem % 7, h = rem / 7;      // h in 0..3
        int c0 = h * 128;
        const float* sx = sxs + p * CC;
        float s = 0.f, comp = 0.f;
        #pragma unroll 4
        for (int c = 0; c < 128; c++) {
            float t = __fmul_rn(sx[c0 + c], Wr[(size_t)(c0 + c) * 7 + j]);
            float y = __fadd_rn(t, -comp);
            float u = __fadd_rn(s, y);
            comp = __fadd_rn(__fadd_rn(u, -s), -y);
            s = u;
        }
        rpart[(p * 7 + j) * 4 + h] = s;
    }
    __syncthreads();
    if (tid < 64) {
        int j = tid;
        float bmv = bm[j];
        #pragma unroll
        for (int p = 0; p < 8; p++) {
            float v = ((part[(0 * 64 + j) * 8 + p] + part[(1 * 64 + j) * 8 + p])
                     + (part[(2 * 64 + j) * 8 + p] + part[(3 * 64 + j) * 8 + p])) + bmv;
            slog[p * 71 + 7 + j] = v;
        }
    }
    if (tid < 56) {
        int p = tid / 7, j = tid % 7;
        const float* q = rpart + (p * 7 + j) * 4;
        slog[p * 71 + j] = __fadd_rn(__fadd_rn(__fadd_rn(q[0], q[1]),
                                               __fadd_rn(q[2], q[3])), br[j]);
    }
    __syncthreads();

    // ---- rect cascade: thread p < 8 per point ----
    if (tid < 8) {
        int p = tid;
        const float* sl = slog + p * 71;
        float* sr = srect + p * 56;
        const float* rp = r + (size_t)(pt0 + p) * 4;
        float p0 = rp[0], p1 = rp[1], p2 = rp[2], p3 = rp[3];
        float rA[2][4], rBv[4][4], rCv[8][4];
        {
            float rat = sigmoidf_(sl[0]);
            float mid = p0 * (1.f - rat) + p2 * rat;
            rA[0][0] = p0;  rA[0][1] = p1; rA[0][2] = mid; rA[0][3] = p3;
            rA[1][0] = mid; rA[1][1] = p1; rA[1][2] = p2;  rA[1][3] = p3;
        }
        for (int j = 0; j < 2; j++) {
            float rat = sigmoidf_(sl[1 + j]);
            float mid = rA[j][1] * (1.f - rat) + rA[j][3] * rat;
            rBv[j][0] = rA[j][0]; rBv[j][1] = rA[j][1]; rBv[j][2] = rA[j][2]; rBv[j][3] = mid;
            rBv[2 + j][0] = rA[j][0]; rBv[2 + j][1] = mid; rBv[2 + j][2] = rA[j][2]; rBv[2 + j][3] = rA[j][3];
        }
        for (int j = 0; j < 4; j++) {
            float rat = sigmoidf_(sl[3 + j]);
            float mid = rBv[j][0] * (1.f - rat) + rBv[j][2] * rat;
            rCv[j][0] = rBv[j][0]; rCv[j][1] = rBv[j][1]; rCv[j][2] = mid; rCv[j][3] = rBv[j][3];
            rCv[4 + j][0] = mid; rCv[4 + j][1] = rBv[j][1]; rCv[4 + j][2] = rBv[j][2]; rCv[4 + j][3] = rBv[j][3];
        }
        for (int j = 0; j < 2; j++) for (int q = 0; q < 4; q++) sr[j * 4 + q] = rA[j][q];
        for (int j = 0; j < 4; j++) for (int q = 0; q < 4; q++) sr[8 + j * 4 + q] = rBv[j][q];
        for (int j = 0; j < 8; j++) for (int q = 0; q < 4; q++) sr[24 + j * 4 + q] = rCv[j][q];
    }
    // ---- softmax: 64 threads, (p, g) ----
    if (tid < 64) {
        int p = tid >> 3, g = tid & 7;
        const float* sl = slog + p * 71;
        float mx = -1e30f;
        for (int s = 0; s < 8; s++) mx = fmaxf(mx, sl[7 + s * 8 + g]);
        float e[8], sum = 0.f;
        for (int s = 0; s < 8; s++) { e[s] = expf(sl[7 + s * 8 + g] - mx); sum += e[s]; }
        float inv = 1.f / sum;
        for (int s = 0; s < 8; s++) g_mask[(size_t)(pt0 + p) * 64 + s * 8 + g] = e[s] * inv;
    }
    __syncthreads();

    const size_t O1 = (size_t)PTS * CC;
    const size_t O2 = O1 + (size_t)PTS * 8;
    const size_t O3 = O2 + (size_t)PTS * 16;
    if (tid < 64)  { int p = tid >> 3, i = tid & 7;  out[O1 + (size_t)(pt0 + p) * 8 + i]  = srect[p * 56 + i]; }
    if (tid < 128) { int p = tid >> 4, i = tid & 15; out[O2 + (size_t)(pt0 + p) * 16 + i] = srect[p * 56 + 8 + i]; }
    {              int p = tid >> 5, i = tid & 31; out[O3 + (size_t)(pt0 + p) * 32 + i] = srect[p * 56 + 24 + i]; }
}

// ---------------------------------------------------------------------------
// Corner eval (boundary terms cancel across the 4-corner combination): 9 loads.
// ---------------------------------------------------------------------------
__device__ __forceinline__ float4 corner_nb(const float4* __restrict__ TI,
                                            const float4* __restrict__ TT,
                                            const float4* __restrict__ A1,
                                            const float4* __restrict__ A2,
                                            int lane, float px, float py)
{
    float X = ceilf(px), Y = ceilf(py);
    int Xi = (int)X, Yi = (int)Y;
    int Xm = max(Xi - 1, 0), Ym = max(Yi - 1, 0);
    float dx = X - px, dy = Y - py;
    float wx1 = 0.5f * (dx * dx), wx2 = dx - wx1;
    float wy1 = 0.5f * (dy * dy), wy2 = dy - wy1;
#define AT4(T, xi, yi) __ldg(&T[(((xi) * WW + (yi)) << 5) + lane])
    float4 s = AT4(TT, Xi, Yi);
    s = f4sub(s, f4add(f4scale(wy1, AT4(A1, Xi, Ym)), f4scale(wy2, AT4(A1, Xi, Yi))));
    s = f4sub(s, f4add(f4scale(wx1, AT4(A2, Xm, Yi)), f4scale(wx2, AT4(A2, Xi, Yi))));
    s = f4add(s, f4add(f4add(f4scale(wx1 * wy1, AT4(TI, Xm, Ym)),
                             f4scale(wx2 * wy1, AT4(TI, Xi, Ym))),
                       f4add(f4scale(wx1 * wy2, AT4(TI, Xm, Yi)),
                             f4scale(wx2 * wy2, AT4(TI, Xi, Yi)))));
#undef AT4
    return s;
}

// ---------------------------------------------------------------------------
// Kernel 2 (fused): corner-streamed sampling into per-RECT sums S[8],
// mask*inv combine -> U in smem, group-GEMM + LayerNorm + residual.
// Block = 8 points, 256 threads; min 4 blocks/SM (cap 64 regs for occupancy).
// ---------------------------------------------------------------------------
__global__ void __launch_bounds__(256, 4)
k_fused(const float* __restrict__ x, const float* __restrict__ Ws,
        const float* __restrict__ bs, const float* __restrict__ lg,
        const float* __restrict__ lb, float* __restrict__ out)
{
    __shared__ __align__(16) float sU[8 * 1024];     // U[p][g*128+k]; later y[p][c]
    __shared__ float2 scoord[8][18];
    __shared__ float scoefR[8][64];                  // mask[r][g]*inv_r
    __shared__ float sinv[8][8];
    __shared__ float smu[8], srs[8];
    int tid = threadIdx.x;
    int wid = tid >> 5, lane = tid & 31;
    int pt0 = blockIdx.x * 8;
    int pt = pt0 + wid;
    int b = pt / NN;

    const size_t O3 = (size_t)PTS * CC + (size_t)PTS * 8 + (size_t)PTS * 16;
    const float* rp = out + O3 + (size_t)pt * 32;
    const float* mp = g_mask + (size_t)pt * 64;
    const float F = (float)(HH - 1);

    // Compile-time corner tables (fold under full unroll)
    const int T_CX[18] = {0,0,0, 4,4,4,4, 22,22,22, 2,2, 6,6, 10,10, 14,14};
    const int T_CY[18] = {1,3,11, 1,3,7,11, 1,7,11, 1,3, 1,7, 3,11, 7,11};
    const int T_R1[18] = {0,0,2, 4,4,1,6, 5,5,7, 0,0, 1,1, 2,2, 3,3};
    const int T_S1[18] = {1,-1,-1, -1,1,-1,1, -1,1,1, -1,1, -1,1, -1,1, -1,1};
    const int T_R2[18] = {0,2,0, 1,6,3,3, 0,7,0, 4,4, 5,5, 6,6, 7,7};
    const int T_S2[18] = {0,1,0, 1,-1,1,-1, 0,-1,0, 1,-1, 1,-1, 1,-1, 1,-1};

    // ---------------- Phase 0: coords + per-rect coefficients ----------------
    if (lane < 18) {
        scoord[wid][lane] = make_float2(__ldg(&rp[T_CX[lane]]) * F,
                                        __ldg(&rp[T_CY[lane]]) * F);
    }
    if (lane < 8) {
        float x1 = __ldg(&rp[4 * lane]) * F,     y1 = __ldg(&rp[4 * lane + 1]) * F;
        float x2 = __ldg(&rp[4 * lane + 2]) * F, y2 = __ldg(&rp[4 * lane + 3]) * F;
        sinv[wid][lane] = 1.f / (fabsf((x1 - x2) * (y1 - y2)) + 1e-9f);
    }
    __syncwarp();
    #pragma unroll
    for (int t = lane; t < 64; t += 32)
        scoefR[wid][t] = __ldg(&mp[t]) * sinv[wid][t >> 3];
    __syncwarp();

    // ---------------- Phase 1: stream 18 corners into rect sums S ----------------
    {
        size_t ib4 = (size_t)b * (HH * WW * CIN / 4);
        const float4* TI = (const float4*)g_TI + ib4;
        const float4* TT = (const float4*)g_TT + ib4;
        const float4* A1 = (const float4*)g_A1 + ib4;
        const float4* A2 = (const float4*)g_A2 + ib4;

        float4 S[8];
        #pragma unroll
        for (int rr = 0; rr < 8; rr++) S[rr] = make_float4(0.f, 0.f, 0.f, 0.f);

        #pragma unroll
        for (int e = 0; e < 18; e++) {
            float2 cc = scoord[wid][e];
            float4 v = corner_nb(TI, TT, A1, A2, lane, cc.x, cc.y);
            if (T_S1[e] > 0) S[T_R1[e]] = f4add(S[T_R1[e]], v);
            else             S[T_R1[e]] = f4sub(S[T_R1[e]], v);
            if (T_S2[e] > 0)      S[T_R2[e]] = f4add(S[T_R2[e]], v);
            else if (T_S2[e] < 0) S[T_R2[e]] = f4sub(S[T_R2[e]], v);
        }

        // combine: U[g] = sum_r coefR[r*8+g] * S[r]
        const float* cr = scoefR[wid];
        float4* up = (float4*)(sU + wid * 1024);
        #pragma unroll
        for (int g = 0; g < 8; g++) {
            float4 u = make_float4(0.f, 0.f, 0.f, 0.f);
            #pragma unroll
            for (int rr = 0; rr < 8; rr++) {
                float c = cr[rr * 8 + g];
                u.x += c * S[rr].x; u.y += c * S[rr].y;
                u.z += c * S[rr].z; u.w += c * S[rr].w;
            }
            up[g * 32 + lane] = u;
        }
    }
    __syncthreads();

    // ---------------- Phase 2: group-GEMM ----------------
    int g = tid >> 5;
    const float2* W2 = (const float2*)Ws;
    float2 acc[8];
    #pragma unroll
    for (int p = 0; p < 8; p++) acc[p] = make_float2(0.f, 0.f);

    const float4* sU4 = (const float4*)sU;
    for (int k4 = 0; k4 < 32; k4++) {
        int kb = k4 * 4;
        float2 w0 = __ldg(&W2[(kb + 0) * 256 + tid]);
        float2 w1 = __ldg(&W2[(kb + 1) * 256 + tid]);
        float2 w2 = __ldg(&W2[(kb + 2) * 256 + tid]);
        float2 w3 = __ldg(&W2[(kb + 3) * 256 + tid]);
        #pragma unroll
        for (int p = 0; p < 8; p++) {
            float4 u = sU4[p * 256 + g * 32 + k4];
            acc[p].x += u.x * w0.x + u.y * w1.x + u.z * w2.x + u.w * w3.x;
            acc[p].y += u.x * w0.y + u.y * w1.y + u.z * w2.y + u.w * w3.y;
        }
    }
    float2 bsv = __ldg(&((const float2*)bs)[tid]);
    __syncthreads();
    #pragma unroll
    for (int p = 0; p < 8; p++) {
        sU[p * 512 + 2 * tid]     = acc[p].x + bsv.x;
        sU[p * 512 + 2 * tid + 1] = acc[p].y + bsv.y;
    }
    __syncthreads();

    // ---------------- Phase 3: LayerNorm stats (warp per point) ----------------
    {
        float sum = 0.f, sq = 0.f;
        for (int i = lane; i < 512; i += 32) {
            float v = sU[wid * 512 + i];
            sum += v; sq += v * v;
        }
        #pragma unroll
        for (int o = 16; o; o >>= 1) {
            sum += __shfl_xor_sync(0xffffffffu, sum, o);
            sq  += __shfl_xor_sync(0xffffffffu, sq, o);
        }
        if (lane == 0) {
            float mu = sum * (1.f / 512.f);
            float var = sq * (1.f / 512.f) - mu * mu;
            smu[wid] = mu;
            srs[wid] = rsqrtf(var + 1e-5f);
        }
    }
    __syncthreads();

    // ---------------- Phase 4: normalize + residual + store ----------------
    float2 gg = __ldg(&((const float2*)lg)[tid]);
    float2 bb = __ldg(&((const float2*)lb)[tid]);
    const float2* x2 = (const float2*)x;
    float2* o2 = (float2*)out;
    #pragma unroll
    for (int p = 0; p < 8; p++) {
        float mu = smu[p], rs = srs[p];
        float2 v = make_float2(sU[p * 512 + 2 * tid], sU[p * 512 + 2 * tid + 1]);
        float2 xr = __ldg(&x2[(size_t)(pt0 + p) * 256 + tid]);
        float2 o;
        o.x = (v.x - mu) * rs * gg.x + bb.x + xr.x;
        o.y = (v.y - mu) * rs * gg.y + bb.y + xr.y;
        o2[(size_t)(pt0 + p) * 256 + tid] = o;
    }
}

// ---------------------------------------------------------------------------
extern "C" void kernel_launch(void* const* d_in, const int* in_sizes, int n_in,
                              void* d_out, int out_size)
{
    const float* x  = (const float*)d_in[0];
    const float* r  = (const float*)d_in[1];
    const float* I  = (const float*)d_in[2];
    const float* IX = (const float*)d_in[3];
    const float* IY = (const float*)d_in[4];
    const float* IT = (const float*)d_in[5];
    const float* Wr = (const float*)d_in[6];
    const float* br = (const float*)d_in[7];
    const float* Wm = (const float*)d_in[8];
    const float* bm = (const float*)d_in[9];
    const float* Ws = (const float*)d_in[10];
    const float* bs = (const float*)d_in[11];
    const float* lg = (const float*)d_in[12];
    const float* lb = (const float*)d_in[13];
    float* out = (float*)d_out;
    (void)in_sizes; (void)n_in; (void)out_size;

    k_pre<<<PRE_BLOCKS, 256>>>(I, IX, IY, IT, x, r, Wr, br, Wm, bm, out);
    k_fused<<<PTS / 8, 256>>>(x, Ws, bs, lg, lb, out);
}

// round 13
// speedup vs baseline: 22.5746x; 1.0602x over previous
#include <cuda_runtime.h>
#include <math.h>

#define BB 8
#define NN 2048
#define CC 512
#define CIN 128
#define HH 96
#define WW 96
#define PTS (BB*NN)               // 16384
#define IMG_ELEMS (BB*HH*WW*CIN)  // 9,437,184

// k_pre striping: 11264 blocks = 1024 groups of (9 transpose + 2 point),
// plus 16 appended blocks that build the packed weight layout.
#define NT_BLOCKS 9216
#define NP_BLOCKS (PTS/8)         // 2048
#define PRE_BLOCKS (NT_BLOCKS + NP_BLOCKS)
#define WT_BLOCKS 16

// Scratch (static __device__ arrays — no allocation)
__device__ float g_TI[IMG_ELEMS];   // I  transposed to [b][x][y][c]
__device__ float g_TT[IMG_ELEMS];   // IT transposed
__device__ float g_A1[IMG_ELEMS];   // IX - 0.5*I transposed
__device__ float g_A2[IMG_ELEMS];   // IY - 0.5*I transposed
__device__ float g_mask[PTS*64];    // softmax mask [pt][s*8+g]
__device__ unsigned long long g_Wt8[64*512];  // Wt8[kk*512+c] = (Ws[2kk][c], Ws[2kk+1][c])

// ---------------------------------------------------------------------------
__device__ __forceinline__ float4 f4add(float4 a, float4 b) {
    return make_float4(a.x + b.x, a.y + b.y, a.z + b.z, a.w + b.w);
}
__device__ __forceinline__ float4 f4sub(float4 a, float4 b) {
    return make_float4(a.x - b.x, a.y - b.y, a.z - b.z, a.w - b.w);
}
__device__ __forceinline__ float4 f4scale(float s, float4 a) {
    return make_float4(s * a.x, s * a.y, s * a.z, s * a.w);
}
__device__ __forceinline__ float sigmoidf_(float v) { return 1.f / (1.f + expf(-v)); }

// packed f32x2 FMA: d = a*b + d (elementwise on packed pairs)
__device__ __forceinline__ void ffma2(unsigned long long& d, unsigned long long a,
                                      unsigned long long b) {
    asm("fma.rn.f32x2 %0, %1, %2, %0;" : "+l"(d) : "l"(a), "l"(b));
}
union F4U { float4 f; unsigned long long l[2]; };

// ---------------------------------------------------------------------------
// Kernel 1 (merged + striped): groups of 11 blocks = 9 transpose + 2 point;
// 16 appended blocks pack Ws into g_Wt8.
// ---------------------------------------------------------------------------
__global__ void __launch_bounds__(256)
k_pre(const float* __restrict__ I, const float* __restrict__ IX,
      const float* __restrict__ IY, const float* __restrict__ IT,
      const float* __restrict__ x, const float* __restrict__ r,
      const float* __restrict__ Wr, const float* __restrict__ br,
      const float* __restrict__ Wm, const float* __restrict__ bm,
      const float* __restrict__ Ws, float* __restrict__ out)
{
    __shared__ __align__(16) char smem_raw[29536];
    int tid = threadIdx.x;

    if (blockIdx.x >= PRE_BLOCKS) {
        // ============ weight pack branch: Wt8[kk*512+c] ============
        int base = (blockIdx.x - PRE_BLOCKS) * 2048 + tid;
        #pragma unroll
        for (int i = 0; i < 8; i++) {
            int idx = base + i * 256;
            int kk = idx >> 9, c = idx & 511;
            unsigned int lo = __float_as_uint(Ws[(2 * kk) * 512 + c]);
            unsigned int hi = __float_as_uint(Ws[(2 * kk + 1) * 512 + c]);
            g_Wt8[idx] = ((unsigned long long)hi << 32) | lo;
        }
        return;
    }

    int grp = blockIdx.x / 11, loc = blockIdx.x % 11;

    if (loc < 9) {
        // ================= transpose branch (vectorized) =================
        float* tI = (float*)smem_raw;            // [32][33]
        float* tT = tI + 1056;
        float* t1 = tT + 1056;
        float* t2 = t1 + 1056;

        int t = grp * 9 + loc;
        int y0 = (t % 3) * 32;
        int c0 = ((t / 3) & 3) * 32;
        int xx = (t / 12) % HH;
        int b  = t / (12 * HH);

        int cl = tid >> 3;             // 0..31
        int y4 = (tid & 7) << 2;       // 0,4..28

        size_t idx = ((size_t)(b * CIN + c0 + cl) * (HH * WW) + (size_t)xx * WW + y0 + y4);
        float4 vi = *(const float4*)(I + idx);
        float4 vx = *(const float4*)(IX + idx);
        float4 vy = *(const float4*)(IY + idx);
        float4 vt = *(const float4*)(IT + idx);

        int sb = cl * 33 + y4;
        tI[sb + 0] = vi.x; tI[sb + 1] = vi.y; tI[sb + 2] = vi.z; tI[sb + 3] = vi.w;
        tT[sb + 0] = vt.x; tT[sb + 1] = vt.y; tT[sb + 2] = vt.z; tT[sb + 3] = vt.w;
        t1[sb + 0] = vx.x - 0.5f * vi.x; t1[sb + 1] = vx.y - 0.5f * vi.y;
        t1[sb + 2] = vx.z - 0.5f * vi.z; t1[sb + 3] = vx.w - 0.5f * vi.w;
        t2[sb + 0] = vy.x - 0.5f * vi.x; t2[sb + 1] = vy.y - 0.5f * vi.y;
        t2[sb + 2] = vy.z - 0.5f * vi.z; t2[sb + 3] = vy.w - 0.5f * vi.w;
        __syncthreads();

        int yl = tid >> 3;             // 0..31
        int c4 = (tid & 7) << 2;       // 0,4..28
        size_t o = (((size_t)b * HH + xx) * WW + y0 + yl) * CIN + c0 + c4;
        float4 oi, ot, o1, o2;
        oi.x = tI[(c4 + 0) * 33 + yl]; oi.y = tI[(c4 + 1) * 33 + yl];
        oi.z = tI[(c4 + 2) * 33 + yl]; oi.w = tI[(c4 + 3) * 33 + yl];
        ot.x = tT[(c4 + 0) * 33 + yl]; ot.y = tT[(c4 + 1) * 33 + yl];
        ot.z = tT[(c4 + 2) * 33 + yl]; ot.w = tT[(c4 + 3) * 33 + yl];
        o1.x = t1[(c4 + 0) * 33 + yl]; o1.y = t1[(c4 + 1) * 33 + yl];
        o1.z = t1[(c4 + 2) * 33 + yl]; o1.w = t1[(c4 + 3) * 33 + yl];
        o2.x = t2[(c4 + 0) * 33 + yl]; o2.y = t2[(c4 + 1) * 33 + yl];
        o2.z = t2[(c4 + 2) * 33 + yl]; o2.w = t2[(c4 + 3) * 33 + yl];
        *(float4*)(g_TI + o) = oi;
        *(float4*)(g_TT + o) = ot;
        *(float4*)(g_A1 + o) = o1;
        *(float4*)(g_A2 + o) = o2;
        return;
    }

    // ================= per-point branch =================
    float* sxs   = (float*)smem_raw;                 // [0, 16384)
    float* part  = (float*)(smem_raw + 16384);       // 8192 B
    float* rpart = (float*)(smem_raw + 24576);       // 896 B (8 pts x 7 x 4 chunks)
    float* slog  = (float*)(smem_raw + 25472);       // 2272 B
    float* srect = (float*)(smem_raw + 27744);       // 1792 B

    int pt0 = (grp * 2 + (loc - 9)) * 8;

    {
        const float4* src = (const float4*)(x + (size_t)pt0 * CC);
        float4* dst = (float4*)sxs;
        for (int i = tid; i < 8 * CC / 4; i += 256) dst[i] = src[i];
    }
    __syncthreads();

    // ---- mask logits: j = tid&63, c-chunk q = tid>>6 (128 c each) ----
    {
        int j = tid & 63, q = tid >> 6;
        int cbase = q * 128;
        float acc[8];
        #pragma unroll
        for (int p = 0; p < 8; p++) acc[p] = 0.f;
        #pragma unroll 4
        for (int c4i = 0; c4i < 32; c4i++) {
            int c = cbase + c4i * 4;
            float w0 = __ldg(&Wm[(size_t)(c + 0) * 64 + j]);
            float w1 = __ldg(&Wm[(size_t)(c + 1) * 64 + j]);
            float w2 = __ldg(&Wm[(size_t)(c + 2) * 64 + j]);
            float w3 = __ldg(&Wm[(size_t)(c + 3) * 64 + j]);
            #pragma unroll
            for (int p = 0; p < 8; p++) {
                float4 u = *(const float4*)(sxs + p * CC + c);
                acc[p] += u.x * w0 + u.y * w1 + u.z * w2 + u.w * w3;
            }
        }
        #pragma unroll
        for (int p = 0; p < 8; p++) part[tid * 8 + p] = acc[p];
    }
    // ---- ratio logits: Kahan, 4 chunks of 128, 2 interleaved 64-chains ----
    if (tid < 224) {
        int p = tid / 28, rem = tid % 28;
        int j = rem % 7, h = rem / 7;      // h in 0..3
        int c0 = h * 128;
        const float* sx = sxs + p * CC;
        float s0 = 0.f, k0 = 0.f, s1 = 0.f, k1 = 0.f;
        #pragma unroll 4
        for (int c = 0; c < 64; c++) {
            float t = __fmul_rn(sx[c0 + c], Wr[(size_t)(c0 + c) * 7 + j]);
            float y = __fadd_rn(t, -k0);
            float u = __fadd_rn(s0, y);
            k0 = __fadd_rn(__fadd_rn(u, -s0), -y);
            s0 = u;
            float t2 = __fmul_rn(sx[c0 + 64 + c], Wr[(size_t)(c0 + 64 + c) * 7 + j]);
            float y2 = __fadd_rn(t2, -k1);
            float u2 = __fadd_rn(s1, y2);
            k1 = __fadd_rn(__fadd_rn(u2, -s1), -y2);
            s1 = u2;
        }
        rpart[(p * 7 + j) * 4 + h] = __fadd_rn(s0, s1);
    }
    __syncthreads();
    if (tid < 64) {
        int j = tid;
        float bmv = bm[j];
        #pragma unroll
        for (int p = 0; p < 8; p++) {
            float v = ((part[(0 * 64 + j) * 8 + p] + part[(1 * 64 + j) * 8 + p])
                     + (part[(2 * 64 + j) * 8 + p] + part[(3 * 64 + j) * 8 + p])) + bmv;
            slog[p * 71 + 7 + j] = v;
        }
    }
    if (tid < 56) {
        int p = tid / 7, j = tid % 7;
        const float* q = rpart + (p * 7 + j) * 4;
        slog[p * 71 + j] = __fadd_rn(__fadd_rn(__fadd_rn(q[0], q[1]),
                                               __fadd_rn(q[2], q[3])), br[j]);
    }
    __syncthreads();

    // ---- rect cascade: thread p < 8 per point ----
    if (tid < 8) {
        int p = tid;
        const float* sl = slog + p * 71;
        float* sr = srect + p * 56;
        const float* rp = r + (size_t)(pt0 + p) * 4;
        float p0 = rp[0], p1 = rp[1], p2 = rp[2], p3 = rp[3];
        float rA[2][4], rBv[4][4], rCv[8][4];
        {
            float rat = sigmoidf_(sl[0]);
            float mid = p0 * (1.f - rat) + p2 * rat;
            rA[0][0] = p0;  rA[0][1] = p1; rA[0][2] = mid; rA[0][3] = p3;
            rA[1][0] = mid; rA[1][1] = p1; rA[1][2] = p2;  rA[1][3] = p3;
        }
        for (int j = 0; j < 2; j++) {
            float rat = sigmoidf_(sl[1 + j]);
            float mid = rA[j][1] * (1.f - rat) + rA[j][3] * rat;
            rBv[j][0] = rA[j][0]; rBv[j][1] = rA[j][1]; rBv[j][2] = rA[j][2]; rBv[j][3] = mid;
            rBv[2 + j][0] = rA[j][0]; rBv[2 + j][1] = mid; rBv[2 + j][2] = rA[j][2]; rBv[2 + j][3] = rA[j][3];
        }
        for (int j = 0; j < 4; j++) {
            float rat = sigmoidf_(sl[3 + j]);
            float mid = rBv[j][0] * (1.f - rat) + rBv[j][2] * rat;
            rCv[j][0] = rBv[j][0]; rCv[j][1] = rBv[j][1]; rCv[j][2] = mid; rCv[j][3] = rBv[j][3];
            rCv[4 + j][0] = mid; rCv[4 + j][1] = rBv[j][1]; rCv[4 + j][2] = rBv[j][2]; rCv[4 + j][3] = rBv[j][3];
        }
        for (int j = 0; j < 2; j++) for (int q = 0; q < 4; q++) sr[j * 4 + q] = rA[j][q];
        for (int j = 0; j < 4; j++) for (int q = 0; q < 4; q++) sr[8 + j * 4 + q] = rBv[j][q];
        for (int j = 0; j < 8; j++) for (int q = 0; q < 4; q++) sr[24 + j * 4 + q] = rCv[j][q];
    }
    // ---- softmax: 64 threads, (p, g) ----
    if (tid < 64) {
        int p = tid >> 3, g = tid & 7;
        const float* sl = slog + p * 71;
        float mx = -1e30f;
        for (int s = 0; s < 8; s++) mx = fmaxf(mx, sl[7 + s * 8 + g]);
        float e[8], sum = 0.f;
        for (int s = 0; s < 8; s++) { e[s] = expf(sl[7 + s * 8 + g] - mx); sum += e[s]; }
        float inv = 1.f / sum;
        for (int s = 0; s < 8; s++) g_mask[(size_t)(pt0 + p) * 64 + s * 8 + g] = e[s] * inv;
    }
    __syncthreads();

    const size_t O1 = (size_t)PTS * CC;
    const size_t O2 = O1 + (size_t)PTS * 8;
    const size_t O3 = O2 + (size_t)PTS * 16;
    if (tid < 64)  { int p = tid >> 3, i = tid & 7;  out[O1 + (size_t)(pt0 + p) * 8 + i]  = srect[p * 56 + i]; }
    if (tid < 128) { int p = tid >> 4, i = tid & 15; out[O2 + (size_t)(pt0 + p) * 16 + i] = srect[p * 56 + 8 + i]; }
    {              int p = tid >> 5, i = tid & 31; out[O3 + (size_t)(pt0 + p) * 32 + i] = srect[p * 56 + 24 + i]; }
}

// ---------------------------------------------------------------------------
// Corner eval (boundary terms cancel across the 4-corner combination): 9 loads.
// ---------------------------------------------------------------------------
__device__ __forceinline__ float4 corner_nb(const float4* __restrict__ TI,
                                            const float4* __restrict__ TT,
                                            const float4* __restrict__ A1,
                                            const float4* __restrict__ A2,
                                            int lane, float px, float py)
{
    float X = ceilf(px), Y = ceilf(py);
    int Xi = (int)X, Yi = (int)Y;
    int Xm = max(Xi - 1, 0), Ym = max(Yi - 1, 0);
    float dx = X - px, dy = Y - py;
    float wx1 = 0.5f * (dx * dx), wx2 = dx - wx1;
    float wy1 = 0.5f * (dy * dy), wy2 = dy - wy1;
#define AT4(T, xi, yi) __ldg(&T[(((xi) * WW + (yi)) << 5) + lane])
    float4 s = AT4(TT, Xi, Yi);
    s = f4sub(s, f4add(f4scale(wy1, AT4(A1, Xi, Ym)), f4scale(wy2, AT4(A1, Xi, Yi))));
    s = f4sub(s, f4add(f4scale(wx1, AT4(A2, Xm, Yi)), f4scale(wx2, AT4(A2, Xi, Yi))));
    s = f4add(s, f4add(f4add(f4scale(wx1 * wy1, AT4(TI, Xm, Ym)),
                             f4scale(wx2 * wy1, AT4(TI, Xi, Ym))),
                       f4add(f4scale(wx1 * wy2, AT4(TI, Xm, Yi)),
                             f4scale(wx2 * wy2, AT4(TI, Xi, Yi)))));
#undef AT4
    return s;
}

// ---------------------------------------------------------------------------
// Kernel 2 (fused): sampling into rect sums S[8] -> U in smem, then
// packed-f32x2 group-GEMM (k-pair packing; Wt8 layout) + LayerNorm + residual.
// ---------------------------------------------------------------------------
__global__ void __launch_bounds__(256)
k_fused(const float* __restrict__ x, const float* __restrict__ bs,
        const float* __restrict__ lg, const float* __restrict__ lb,
        float* __restrict__ out)
{
    __shared__ __align__(16) float sU[8 * 1024];     // U[p][g*128+k]; later y[p][c]
    __shared__ float2 scoord[8][18];
    __shared__ float scoefR[8][64];                  // mask[r][g]*inv_r
    __shared__ float sinv[8][8];
    __shared__ float smu[8], srs[8];
    int tid = threadIdx.x;
    int wid = tid >> 5, lane = tid & 31;
    int pt0 = blockIdx.x * 8;
    int pt = pt0 + wid;
    int b = pt / NN;

    const size_t O3 = (size_t)PTS * CC + (size_t)PTS * 8 + (size_t)PTS * 16;
    const float* rp = out + O3 + (size_t)pt * 32;
    const float* mp = g_mask + (size_t)pt * 64;
    const float F = (float)(HH - 1);

    // Compile-time corner tables (fold under full unroll)
    const int T_CX[18] = {0,0,0, 4,4,4,4, 22,22,22, 2,2, 6,6, 10,10, 14,14};
    const int T_CY[18] = {1,3,11, 1,3,7,11, 1,7,11, 1,3, 1,7, 3,11, 7,11};
    const int T_R1[18] = {0,0,2, 4,4,1,6, 5,5,7, 0,0, 1,1, 2,2, 3,3};
    const int T_S1[18] = {1,-1,-1, -1,1,-1,1, -1,1,1, -1,1, -1,1, -1,1, -1,1};
    const int T_R2[18] = {0,2,0, 1,6,3,3, 0,7,0, 4,4, 5,5, 6,6, 7,7};
    const int T_S2[18] = {0,1,0, 1,-1,1,-1, 0,-1,0, 1,-1, 1,-1, 1,-1, 1,-1};

    // ---------------- Phase 0: coords + per-rect coefficients ----------------
    if (lane < 18) {
        scoord[wid][lane] = make_float2(__ldg(&rp[T_CX[lane]]) * F,
                                        __ldg(&rp[T_CY[lane]]) * F);
    }
    if (lane < 8) {
        float x1 = __ldg(&rp[4 * lane]) * F,     y1 = __ldg(&rp[4 * lane + 1]) * F;
        float x2 = __ldg(&rp[4 * lane + 2]) * F, y2 = __ldg(&rp[4 * lane + 3]) * F;
        sinv[wid][lane] = 1.f / (fabsf((x1 - x2) * (y1 - y2)) + 1e-9f);
    }
    __syncwarp();
    #pragma unroll
    for (int t = lane; t < 64; t += 32)
        scoefR[wid][t] = __ldg(&mp[t]) * sinv[wid][t >> 3];
    __syncwarp();

    // ---------------- Phase 1: stream 18 corners into rect sums S ----------------
    {
        size_t ib4 = (size_t)b * (HH * WW * CIN / 4);
        const float4* TI = (const float4*)g_TI + ib4;
        const float4* TT = (const float4*)g_TT + ib4;
        const float4* A1 = (const float4*)g_A1 + ib4;
        const float4* A2 = (const float4*)g_A2 + ib4;

        float4 S[8];
        #pragma unroll
        for (int rr = 0; rr < 8; rr++) S[rr] = make_float4(0.f, 0.f, 0.f, 0.f);

        #pragma unroll
        for (int e = 0; e < 18; e++) {
            float2 cc = scoord[wid][e];
            float4 v = corner_nb(TI, TT, A1, A2, lane, cc.x, cc.y);
            if (T_S1[e] > 0) S[T_R1[e]] = f4add(S[T_R1[e]], v);
            else             S[T_R1[e]] = f4sub(S[T_R1[e]], v);
            if (T_S2[e] > 0)      S[T_R2[e]] = f4add(S[T_R2[e]], v);
            else if (T_S2[e] < 0) S[T_R2[e]] = f4sub(S[T_R2[e]], v);
        }

        // combine: U[g] = sum_r coefR[r*8+g] * S[r]
        const float* cr = scoefR[wid];
        float4* up = (float4*)(sU + wid * 1024);
        #pragma unroll
        for (int g = 0; g < 8; g++) {
            float4 u = make_float4(0.f, 0.f, 0.f, 0.f);
            #pragma unroll
            for (int rr = 0; rr < 8; rr++) {
                float c = cr[rr * 8 + g];
                u.x += c * S[rr].x; u.y += c * S[rr].y;
                u.z += c * S[rr].z; u.w += c * S[rr].w;
            }
            up[g * 32 + lane] = u;
        }
    }
    __syncthreads();

    // ---------------- Phase 2: packed-f32x2 group-GEMM ----------------
    // thread -> channels (2t, 2t+1); group g = t>>5 (warp-uniform).
    // acc holds (even-k partial, odd-k partial) per channel, summed at end.
    int g = tid >> 5;
    unsigned long long acc0[8], acc1[8];
    #pragma unroll
    for (int p = 0; p < 8; p++) { acc0[p] = 0ull; acc1[p] = 0ull; }

    const ulonglong2* Wt16 = (const ulonglong2*)g_Wt8;  // [kk][c-pair]: 256 u64x2 per kk
    const float4* sU4 = (const float4*)sU;
    for (int k4 = 0; k4 < 32; k4++) {
        ulonglong2 wA = __ldg(&Wt16[(2 * k4) * 256 + tid]);      // k = 4k4, 4k4+1
        ulonglong2 wB = __ldg(&Wt16[(2 * k4 + 1) * 256 + tid]);  // k = 4k4+2, 4k4+3
        #pragma unroll
        for (int p = 0; p < 8; p++) {
            F4U u;
            u.f = sU4[p * 256 + g * 32 + k4];
            ffma2(acc0[p], u.l[0], wA.x);
            ffma2(acc0[p], u.l[1], wB.x);
            ffma2(acc1[p], u.l[0], wA.y);
            ffma2(acc1[p], u.l[1], wB.y);
        }
    }
    float2 bsv = __ldg(&((const float2*)bs)[tid]);
    __syncthreads();
    #pragma unroll
    for (int p = 0; p < 8; p++) {
        unsigned int e0 = (unsigned int)acc0[p], o0 = (unsigned int)(acc0[p] >> 32);
        unsigned int e1 = (unsigned int)acc1[p], o1 = (unsigned int)(acc1[p] >> 32);
        sU[p * 512 + 2 * tid]     = (__uint_as_float(e0) + __uint_as_float(o0)) + bsv.x;
        sU[p * 512 + 2 * tid + 1] = (__uint_as_float(e1) + __uint_as_float(o1)) + bsv.y;
    }
    __syncthreads();

    // ---------------- Phase 3: LayerNorm stats (warp per point) ----------------
    {
        float sum = 0.f, sq = 0.f;
        for (int i = lane; i < 512; i += 32) {
            float v = sU[wid * 512 + i];
            sum += v; sq += v * v;
        }
        #pragma unroll
        for (int o = 16; o; o >>= 1) {
            sum += __shfl_xor_sync(0xffffffffu, sum, o);
            sq  += __shfl_xor_sync(0xffffffffu, sq, o);
        }
        if (lane == 0) {
            float mu = sum * (1.f / 512.f);
            float var = sq * (1.f / 512.f) - mu * mu;
            smu[wid] = mu;
            srs[wid] = rsqrtf(var + 1e-5f);
        }
    }
    __syncthreads();

    // ---------------- Phase 4: normalize + residual + store ----------------
    float2 gg = __ldg(&((const float2*)lg)[tid]);
    float2 bb = __ldg(&((const float2*)lb)[tid]);
    const float2* x2 = (const float2*)x;
    float2* o2 = (float2*)out;
    #pragma unroll
    for (int p = 0; p < 8; p++) {
        float mu = smu[p], rs = srs[p];
        float2 v = make_float2(sU[p * 512 + 2 * tid], sU[p * 512 + 2 * tid + 1]);
        float2 xr = __ldg(&x2[(size_t)(pt0 + p) * 256 + tid]);
        float2 o;
        o.x = (v.x - mu) * rs * gg.x + bb.x + xr.x;
        o.y = (v.y - mu) * rs * gg.y + bb.y + xr.y;
        o2[(size_t)(pt0 + p) * 256 + tid] = o;
    }
}

// ---------------------------------------------------------------------------
extern "C" void kernel_launch(void* const* d_in, const int* in_sizes, int n_in,
                              void* d_out, int out_size)
{
    const float* x  = (const float*)d_in[0];
    const float* r  = (const float*)d_in[1];
    const float* I  = (const float*)d_in[2];
    const float* IX = (const float*)d_in[3];
    const float* IY = (const float*)d_in[4];
    const float* IT = (const float*)d_in[5];
    const float* Wr = (const float*)d_in[6];
    const float* br = (const float*)d_in[7];
    const float* Wm = (const float*)d_in[8];
    const float* bm = (const float*)d_in[9];
    const float* Ws = (const float*)d_in[10];
    const float* bs = (const float*)d_in[11];
    const float* lg = (const float*)d_in[12];
    const float* lb = (const float*)d_in[13];
    float* out = (float*)d_out;
    (void)in_sizes; (void)n_in; (void)out_size;

    k_pre<<<PRE_BLOCKS + WT_BLOCKS, 256>>>(I, IX, IY, IT, x, r, Wr, br, Wm, bm, Ws, out);
    k_fused<<<PTS / 8, 256>>>(x, bs, lg, lb, out);
}

// round 14
// speedup vs baseline: 22.9487x; 1.0166x over previous
#include <cuda_runtime.h>
#include <cuda_fp16.h>
#include <math.h>

#define BB 8
#define NN 2048
#define CC 512
#define CIN 128
#define HH 96
#define WW 96
#define PTS (BB*NN)               // 16384
#define IMG_ELEMS (BB*HH*WW*CIN)  // 9,437,184

// k_pre striping: 11264 blocks = 1024 groups of (9 transpose + 2 point),
// plus 16 appended blocks that build the packed weight layout.
#define NT_BLOCKS 9216
#define NP_BLOCKS (PTS/8)         // 2048
#define PRE_BLOCKS (NT_BLOCKS + NP_BLOCKS)
#define WT_BLOCKS 16

// Scratch (static __device__ arrays — no allocation)
__device__ __half2 g_TIh[IMG_ELEMS/2];  // I transposed, fp16 (gather weights <= 0.25)
__device__ float g_TT[IMG_ELEMS];   // IT transposed
__device__ float g_A1[IMG_ELEMS];   // IX - 0.5*I transposed
__device__ float g_A2[IMG_ELEMS];   // IY - 0.5*I transposed
__device__ float g_mask[PTS*64];    // softmax mask [pt][s*8+g]
__device__ unsigned long long g_Wt8[64*512];  // Wt8[kk*512+c] = (Ws[2kk][c], Ws[2kk+1][c])

// ---------------------------------------------------------------------------
__device__ __forceinline__ float4 f4add(float4 a, float4 b) {
    return make_float4(a.x + b.x, a.y + b.y, a.z + b.z, a.w + b.w);
}
__device__ __forceinline__ float4 f4sub(float4 a, float4 b) {
    return make_float4(a.x - b.x, a.y - b.y, a.z - b.z, a.w - b.w);
}
__device__ __forceinline__ float4 f4scale(float s, float4 a) {
    return make_float4(s * a.x, s * a.y, s * a.z, s * a.w);
}
__device__ __forceinline__ float sigmoidf_(float v) { return 1.f / (1.f + expf(-v)); }

// packed f32x2 FMA: d = a*b + d (elementwise on packed pairs)
__device__ __forceinline__ void ffma2(unsigned long long& d, unsigned long long a,
                                      unsigned long long b) {
    asm("fma.rn.f32x2 %0, %1, %2, %0;" : "+l"(d) : "l"(a), "l"(b));
}
union F4U { float4 f; unsigned long long l[2]; };

// fp16 gather: 4 channels (8B) -> float4
__device__ __forceinline__ float4 ldh4(const __half2* __restrict__ T, int cell, int lane) {
    uint2 v = __ldg((const uint2*)(T + cell * 64 + lane * 2));
    __half2 h0 = *reinterpret_cast<__half2*>(&v.x);
    __half2 h1 = *reinterpret_cast<__half2*>(&v.y);
    float2 f0 = __half22float2(h0), f1 = __half22float2(h1);
    return make_float4(f0.x, f0.y, f1.x, f1.y);
}

// ---------------------------------------------------------------------------
// Kernel 1 (merged + striped): groups of 11 blocks = 9 transpose + 2 point;
// 16 appended blocks pack Ws into g_Wt8.
// ---------------------------------------------------------------------------
__global__ void __launch_bounds__(256)
k_pre(const float* __restrict__ I, const float* __restrict__ IX,
      const float* __restrict__ IY, const float* __restrict__ IT,
      const float* __restrict__ x, const float* __restrict__ r,
      const float* __restrict__ Wr, const float* __restrict__ br,
      const float* __restrict__ Wm, const float* __restrict__ bm,
      const float* __restrict__ Ws, float* __restrict__ out)
{
    __shared__ __align__(16) char smem_raw[29536];
    int tid = threadIdx.x;

    if (blockIdx.x >= PRE_BLOCKS) {
        // ============ weight pack branch: Wt8[kk*512+c] ============
        int base = (blockIdx.x - PRE_BLOCKS) * 2048 + tid;
        #pragma unroll
        for (int i = 0; i < 8; i++) {
            int idx = base + i * 256;
            int kk = idx >> 9, c = idx & 511;
            unsigned int lo = __float_as_uint(Ws[(2 * kk) * 512 + c]);
            unsigned int hi = __float_as_uint(Ws[(2 * kk + 1) * 512 + c]);
            g_Wt8[idx] = ((unsigned long long)hi << 32) | lo;
        }
        return;
    }

    int grp = blockIdx.x / 11, loc = blockIdx.x % 11;

    if (loc < 9) {
        // ================= transpose branch (vectorized) =================
        float* tI = (float*)smem_raw;            // [32][33]
        float* tT = tI + 1056;
        float* t1 = tT + 1056;
        float* t2 = t1 + 1056;

        int t = grp * 9 + loc;
        int y0 = (t % 3) * 32;
        int c0 = ((t / 3) & 3) * 32;
        int xx = (t / 12) % HH;
        int b  = t / (12 * HH);

        int cl = tid >> 3;             // 0..31
        int y4 = (tid & 7) << 2;       // 0,4..28

        size_t idx = ((size_t)(b * CIN + c0 + cl) * (HH * WW) + (size_t)xx * WW + y0 + y4);
        float4 vi = *(const float4*)(I + idx);
        float4 vx = *(const float4*)(IX + idx);
        float4 vy = *(const float4*)(IY + idx);
        float4 vt = *(const float4*)(IT + idx);

        int sb = cl * 33 + y4;
        tI[sb + 0] = vi.x; tI[sb + 1] = vi.y; tI[sb + 2] = vi.z; tI[sb + 3] = vi.w;
        tT[sb + 0] = vt.x; tT[sb + 1] = vt.y; tT[sb + 2] = vt.z; tT[sb + 3] = vt.w;
        t1[sb + 0] = vx.x - 0.5f * vi.x; t1[sb + 1] = vx.y - 0.5f * vi.y;
        t1[sb + 2] = vx.z - 0.5f * vi.z; t1[sb + 3] = vx.w - 0.5f * vi.w;
        t2[sb + 0] = vy.x - 0.5f * vi.x; t2[sb + 1] = vy.y - 0.5f * vi.y;
        t2[sb + 2] = vy.z - 0.5f * vi.z; t2[sb + 3] = vy.w - 0.5f * vi.w;
        __syncthreads();

        int yl = tid >> 3;             // 0..31
        int c4 = (tid & 7) << 2;       // 0,4..28
        size_t o = (((size_t)b * HH + xx) * WW + y0 + yl) * CIN + c0 + c4;
        float4 oi, ot, o1, o2;
        oi.x = tI[(c4 + 0) * 33 + yl]; oi.y = tI[(c4 + 1) * 33 + yl];
        oi.z = tI[(c4 + 2) * 33 + yl]; oi.w = tI[(c4 + 3) * 33 + yl];
        ot.x = tT[(c4 + 0) * 33 + yl]; ot.y = tT[(c4 + 1) * 33 + yl];
        ot.z = tT[(c4 + 2) * 33 + yl]; ot.w = tT[(c4 + 3) * 33 + yl];
        o1.x = t1[(c4 + 0) * 33 + yl]; o1.y = t1[(c4 + 1) * 33 + yl];
        o1.z = t1[(c4 + 2) * 33 + yl]; o1.w = t1[(c4 + 3) * 33 + yl];
        o2.x = t2[(c4 + 0) * 33 + yl]; o2.y = t2[(c4 + 1) * 33 + yl];
        o2.z = t2[(c4 + 2) * 33 + yl]; o2.w = t2[(c4 + 3) * 33 + yl];
        // TI stored fp16 (all its gather weights are <= 0.25)
        {
            __half2 h01 = __floats2half2_rn(oi.x, oi.y);
            __half2 h23 = __floats2half2_rn(oi.z, oi.w);
            uint2 hp;
            hp.x = *reinterpret_cast<unsigned int*>(&h01);
            hp.y = *reinterpret_cast<unsigned int*>(&h23);
            *(uint2*)(g_TIh + o / 2) = hp;
        }
        *(float4*)(g_TT + o) = ot;
        *(float4*)(g_A1 + o) = o1;
        *(float4*)(g_A2 + o) = o2;
        return;
    }

    // ================= per-point branch =================
    float* sxs   = (float*)smem_raw;                 // [0, 16384)
    float* part  = (float*)(smem_raw + 16384);       // 8192 B
    float* rpart = (float*)(smem_raw + 24576);       // 896 B (8 pts x 7 x 4 chunks)
    float* slog  = (float*)(smem_raw + 25472);       // 2272 B
    float* srect = (float*)(smem_raw + 27744);       // 1792 B

    int pt0 = (grp * 2 + (loc - 9)) * 8;

    {
        const float4* src = (const float4*)(x + (size_t)pt0 * CC);
        float4* dst = (float4*)sxs;
        for (int i = tid; i < 8 * CC / 4; i += 256) dst[i] = src[i];
    }
    __syncthreads();

    // ---- mask logits: j = tid&63, c-chunk q = tid>>6 (128 c each) ----
    {
        int j = tid & 63, q = tid >> 6;
        int cbase = q * 128;
        float acc[8];
        #pragma unroll
        for (int p = 0; p < 8; p++) acc[p] = 0.f;
        #pragma unroll 4
        for (int c4i = 0; c4i < 32; c4i++) {
            int c = cbase + c4i * 4;
            float w0 = __ldg(&Wm[(size_t)(c + 0) * 64 + j]);
            float w1 = __ldg(&Wm[(size_t)(c + 1) * 64 + j]);
            float w2 = __ldg(&Wm[(size_t)(c + 2) * 64 + j]);
            float w3 = __ldg(&Wm[(size_t)(c + 3) * 64 + j]);
            #pragma unroll
            for (int p = 0; p < 8; p++) {
                float4 u = *(const float4*)(sxs + p * CC + c);
                acc[p] += u.x * w0 + u.y * w1 + u.z * w2 + u.w * w3;
            }
        }
        #pragma unroll
        for (int p = 0; p < 8; p++) part[tid * 8 + p] = acc[p];
    }
    // ---- ratio logits: Kahan, 4 chunks of 128, 2 interleaved 64-chains ----
    if (tid < 224) {
        int p = tid / 28, rem = tid % 28;
        int j = rem % 7, h = rem / 7;      // h in 0..3
        int c0 = h * 128;
        const float* sx = sxs + p * CC;
        float s0 = 0.f, k0 = 0.f, s1 = 0.f, k1 = 0.f;
        #pragma unroll 4
        for (int c = 0; c < 64; c++) {
            float t = __fmul_rn(sx[c0 + c], Wr[(size_t)(c0 + c) * 7 + j]);
            float y = __fadd_rn(t, -k0);
            float u = __fadd_rn(s0, y);
            k0 = __fadd_rn(__fadd_rn(u, -s0), -y);
            s0 = u;
            float t2 = __fmul_rn(sx[c0 + 64 + c], Wr[(size_t)(c0 + 64 + c) * 7 + j]);
            float y2 = __fadd_rn(t2, -k1);
            float u2 = __fadd_rn(s1, y2);
            k1 = __fadd_rn(__fadd_rn(u2, -s1), -y2);
            s1 = u2;
        }
        rpart[(p * 7 + j) * 4 + h] = __fadd_rn(s0, s1);
    }
    __syncthreads();
    if (tid < 64) {
        int j = tid;
        float bmv = bm[j];
        #pragma unroll
        for (int p = 0; p < 8; p++) {
            float v = ((part[(0 * 64 + j) * 8 + p] + part[(1 * 64 + j) * 8 + p])
                     + (part[(2 * 64 + j) * 8 + p] + part[(3 * 64 + j) * 8 + p])) + bmv;
            slog[p * 71 + 7 + j] = v;
        }
    }
    if (tid < 56) {
        int p = tid / 7, j = tid % 7;
        const float* q = rpart + (p * 7 + j) * 4;
        slog[p * 71 + j] = __fadd_rn(__fadd_rn(__fadd_rn(q[0], q[1]),
                                               __fadd_rn(q[2], q[3])), br[j]);
    }
    __syncthreads();

    // ---- rect cascade: thread p < 8 per point ----
    if (tid < 8) {
        int p = tid;
        const float* sl = slog + p * 71;
        float* sr = srect + p * 56;
        const float* rp = r + (size_t)(pt0 + p) * 4;
        float p0 = rp[0], p1 = rp[1], p2 = rp[2], p3 = rp[3];
        float rA[2][4], rBv[4][4], rCv[8][4];
        {
            float rat = sigmoidf_(sl[0]);
            float mid = p0 * (1.f - rat) + p2 * rat;
            rA[0][0] = p0;  rA[0][1] = p1; rA[0][2] = mid; rA[0][3] = p3;
            rA[1][0] = mid; rA[1][1] = p1; rA[1][2] = p2;  rA[1][3] = p3;
        }
        for (int j = 0; j < 2; j++) {
            float rat = sigmoidf_(sl[1 + j]);
            float mid = rA[j][1] * (1.f - rat) + rA[j][3] * rat;
            rBv[j][0] = rA[j][0]; rBv[j][1] = rA[j][1]; rBv[j][2] = rA[j][2]; rBv[j][3] = mid;
            rBv[2 + j][0] = rA[j][0]; rBv[2 + j][1] = mid; rBv[2 + j][2] = rA[j][2]; rBv[2 + j][3] = rA[j][3];
        }
        for (int j = 0; j < 4; j++) {
            float rat = sigmoidf_(sl[3 + j]);
            float mid = rBv[j][0] * (1.f - rat) + rBv[j][2] * rat;
            rCv[j][0] = rBv[j][0]; rCv[j][1] = rBv[j][1]; rCv[j][2] = mid; rCv[j][3] = rBv[j][3];
            rCv[4 + j][0] = mid; rCv[4 + j][1] = rBv[j][1]; rCv[4 + j][2] = rBv[j][2]; rCv[4 + j][3] = rBv[j][3];
        }
        for (int j = 0; j < 2; j++) for (int q = 0; q < 4; q++) sr[j * 4 + q] = rA[j][q];
        for (int j = 0; j < 4; j++) for (int q = 0; q < 4; q++) sr[8 + j * 4 + q] = rBv[j][q];
        for (int j = 0; j < 8; j++) for (int q = 0; q < 4; q++) sr[24 + j * 4 + q] = rCv[j][q];
    }
    // ---- softmax: 64 threads, (p, g) ----
    if (tid < 64) {
        int p = tid >> 3, g = tid & 7;
        const float* sl = slog + p * 71;
        float mx = -1e30f;
        for (int s = 0; s < 8; s++) mx = fmaxf(mx, sl[7 + s * 8 + g]);
        float e[8], sum = 0.f;
        for (int s = 0; s < 8; s++) { e[s] = expf(sl[7 + s * 8 + g] - mx); sum += e[s]; }
        float inv = 1.f / sum;
        for (int s = 0; s < 8; s++) g_mask[(size_t)(pt0 + p) * 64 + s * 8 + g] = e[s] * inv;
    }
    __syncthreads();

    const size_t O1 = (size_t)PTS * CC;
    const size_t O2 = O1 + (size_t)PTS * 8;
    const size_t O3 = O2 + (size_t)PTS * 16;
    if (tid < 64)  { int p = tid >> 3, i = tid & 7;  out[O1 + (size_t)(pt0 + p) * 8 + i]  = srect[p * 56 + i]; }
    if (tid < 128) { int p = tid >> 4, i = tid & 15; out[O2 + (size_t)(pt0 + p) * 16 + i] = srect[p * 56 + 8 + i]; }
    {              int p = tid >> 5, i = tid & 31; out[O3 + (size_t)(pt0 + p) * 32 + i] = srect[p * 56 + 24 + i]; }
}

// ---------------------------------------------------------------------------
// Corner eval: TT/A1/A2 fp32 (5 loads), TI fp16 (4 x 8B loads).
// ---------------------------------------------------------------------------
__device__ __forceinline__ float4 corner_nb(const __half2* __restrict__ TIh,
                                            const float4* __restrict__ TT,
                                            const float4* __restrict__ A1,
                                            const float4* __restrict__ A2,
                                            int lane, float px, float py)
{
    float X = ceilf(px), Y = ceilf(py);
    int Xi = (int)X, Yi = (int)Y;
    int Xm = max(Xi - 1, 0), Ym = max(Yi - 1, 0);
    float dx = X - px, dy = Y - py;
    float wx1 = 0.5f * (dx * dx), wx2 = dx - wx1;
    float wy1 = 0.5f * (dy * dy), wy2 = dy - wy1;
#define AT4(T, xi, yi) __ldg(&T[(((xi) * WW + (yi)) << 5) + lane])
    float4 s = AT4(TT, Xi, Yi);
    s = f4sub(s, f4add(f4scale(wy1, AT4(A1, Xi, Ym)), f4scale(wy2, AT4(A1, Xi, Yi))));
    s = f4sub(s, f4add(f4scale(wx1, AT4(A2, Xm, Yi)), f4scale(wx2, AT4(A2, Xi, Yi))));
    s = f4add(s, f4add(f4add(f4scale(wx1 * wy1, ldh4(TIh, Xm * WW + Ym, lane)),
                             f4scale(wx2 * wy1, ldh4(TIh, Xi * WW + Ym, lane))),
                       f4add(f4scale(wx1 * wy2, ldh4(TIh, Xm * WW + Yi, lane)),
                             f4scale(wx2 * wy2, ldh4(TIh, Xi * WW + Yi, lane)))));
#undef AT4
    return s;
}

// ---------------------------------------------------------------------------
// Kernel 2 (fused): sampling into rect sums S[8] -> U in smem, then
// packed-f32x2 group-GEMM (k-pair packing; Wt8 layout) + LayerNorm + residual.
// ---------------------------------------------------------------------------
__global__ void __launch_bounds__(256)
k_fused(const float* __restrict__ x, const float* __restrict__ bs,
        const float* __restrict__ lg, const float* __restrict__ lb,
        float* __restrict__ out)
{
    __shared__ __align__(16) float sU[8 * 1024];     // U[p][g*128+k]; later y[p][c]
    __shared__ float2 scoord[8][18];
    __shared__ float scoefR[8][64];                  // mask[r][g]*inv_r
    __shared__ float sinv[8][8];
    __shared__ float smu[8], srs[8];
    int tid = threadIdx.x;
    int wid = tid >> 5, lane = tid & 31;
    int pt0 = blockIdx.x * 8;
    int pt = pt0 + wid;
    int b = pt / NN;

    const size_t O3 = (size_t)PTS * CC + (size_t)PTS * 8 + (size_t)PTS * 16;
    const float* rp = out + O3 + (size_t)pt * 32;
    const float* mp = g_mask + (size_t)pt * 64;
    const float F = (float)(HH - 1);

    // Compile-time corner tables (fold under full unroll)
    const int T_CX[18] = {0,0,0, 4,4,4,4, 22,22,22, 2,2, 6,6, 10,10, 14,14};
    const int T_CY[18] = {1,3,11, 1,3,7,11, 1,7,11, 1,3, 1,7, 3,11, 7,11};
    const int T_R1[18] = {0,0,2, 4,4,1,6, 5,5,7, 0,0, 1,1, 2,2, 3,3};
    const int T_S1[18] = {1,-1,-1, -1,1,-1,1, -1,1,1, -1,1, -1,1, -1,1, -1,1};
    const int T_R2[18] = {0,2,0, 1,6,3,3, 0,7,0, 4,4, 5,5, 6,6, 7,7};
    const int T_S2[18] = {0,1,0, 1,-1,1,-1, 0,-1,0, 1,-1, 1,-1, 1,-1, 1,-1};

    // ---------------- Phase 0: coords + per-rect coefficients ----------------
    if (lane < 18) {
        scoord[wid][lane] = make_float2(__ldg(&rp[T_CX[lane]]) * F,
                                        __ldg(&rp[T_CY[lane]]) * F);
    }
    if (lane < 8) {
        float x1 = __ldg(&rp[4 * lane]) * F,     y1 = __ldg(&rp[4 * lane + 1]) * F;
        float x2 = __ldg(&rp[4 * lane + 2]) * F, y2 = __ldg(&rp[4 * lane + 3]) * F;
        sinv[wid][lane] = 1.f / (fabsf((x1 - x2) * (y1 - y2)) + 1e-9f);
    }
    __syncwarp();
    #pragma unroll
    for (int t = lane; t < 64; t += 32)
        scoefR[wid][t] = __ldg(&mp[t]) * sinv[wid][t >> 3];
    __syncwarp();

    // ---------------- Phase 1: stream 18 corners into rect sums S ----------------
    {
        size_t ibase = (size_t)b * (HH * WW);
        const __half2* TIh = g_TIh + ibase * (CIN / 2);
        const float4* TT = (const float4*)g_TT + ibase * (CIN / 4);
        const float4* A1 = (const float4*)g_A1 + ibase * (CIN / 4);
        const float4* A2 = (const float4*)g_A2 + ibase * (CIN / 4);

        float4 S[8];
        #pragma unroll
        for (int rr = 0; rr < 8; rr++) S[rr] = make_float4(0.f, 0.f, 0.f, 0.f);

        #pragma unroll
        for (int e = 0; e < 18; e++) {
            float2 cc = scoord[wid][e];
            float4 v = corner_nb(TIh, TT, A1, A2, lane, cc.x, cc.y);
            if (T_S1[e] > 0) S[T_R1[e]] = f4add(S[T_R1[e]], v);
            else             S[T_R1[e]] = f4sub(S[T_R1[e]], v);
            if (T_S2[e] > 0)      S[T_R2[e]] = f4add(S[T_R2[e]], v);
            else if (T_S2[e] < 0) S[T_R2[e]] = f4sub(S[T_R2[e]], v);
        }

        // combine: U[g] = sum_r coefR[r*8+g] * S[r]
        const float* cr = scoefR[wid];
        float4* up = (float4*)(sU + wid * 1024);
        #pragma unroll
        for (int g = 0; g < 8; g++) {
            float4 u = make_float4(0.f, 0.f, 0.f, 0.f);
            #pragma unroll
            for (int rr = 0; rr < 8; rr++) {
                float c = cr[rr * 8 + g];
                u.x += c * S[rr].x; u.y += c * S[rr].y;
                u.z += c * S[rr].z; u.w += c * S[rr].w;
            }
            up[g * 32 + lane] = u;
        }
    }
    __syncthreads();

    // ---------------- Phase 2: packed-f32x2 group-GEMM ----------------
    int g = tid >> 5;
    unsigned long long acc0[8], acc1[8];
    #pragma unroll
    for (int p = 0; p < 8; p++) { acc0[p] = 0ull; acc1[p] = 0ull; }

    const ulonglong2* Wt16 = (const ulonglong2*)g_Wt8;  // [kk][c-pair]
    const float4* sU4 = (const float4*)sU;
    for (int k4 = 0; k4 < 32; k4++) {
        ulonglong2 wA = __ldg(&Wt16[(2 * k4) * 256 + tid]);      // k = 4k4, 4k4+1
        ulonglong2 wB = __ldg(&Wt16[(2 * k4 + 1) * 256 + tid]);  // k = 4k4+2, 4k4+3
        #pragma unroll
        for (int p = 0; p < 8; p++) {
            F4U u;
            u.f = sU4[p * 256 + g * 32 + k4];
            ffma2(acc0[p], u.l[0], wA.x);
            ffma2(acc0[p], u.l[1], wB.x);
            ffma2(acc1[p], u.l[0], wA.y);
            ffma2(acc1[p], u.l[1], wB.y);
        }
    }
    float2 bsv = __ldg(&((const float2*)bs)[tid]);
    __syncthreads();
    #pragma unroll
    for (int p = 0; p < 8; p++) {
        unsigned int e0 = (unsigned int)acc0[p], o0 = (unsigned int)(acc0[p] >> 32);
        unsigned int e1 = (unsigned int)acc1[p], o1 = (unsigned int)(acc1[p] >> 32);
        sU[p * 512 + 2 * tid]     = (__uint_as_float(e0) + __uint_as_float(o0)) + bsv.x;
        sU[p * 512 + 2 * tid + 1] = (__uint_as_float(e1) + __uint_as_float(o1)) + bsv.y;
    }
    __syncthreads();

    // ---------------- Phase 3: LayerNorm stats (warp per point) ----------------
    {
        float sum = 0.f, sq = 0.f;
        for (int i = lane; i < 512; i += 32) {
            float v = sU[wid * 512 + i];
            sum += v; sq += v * v;
        }
        #pragma unroll
        for (int o = 16; o; o >>= 1) {
            sum += __shfl_xor_sync(0xffffffffu, sum, o);
            sq  += __shfl_xor_sync(0xffffffffu, sq, o);
        }
        if (lane == 0) {
            float mu = sum * (1.f / 512.f);
            float var = sq * (1.f / 512.f) - mu * mu;
            smu[wid] = mu;
            srs[wid] = rsqrtf(var + 1e-5f);
        }
    }
    __syncthreads();

    // ---------------- Phase 4: normalize + residual + store ----------------
    float2 gg = __ldg(&((const float2*)lg)[tid]);
    float2 bb = __ldg(&((const float2*)lb)[tid]);
    const float2* x2 = (const float2*)x;
    float2* o2 = (float2*)out;
    #pragma unroll
    for (int p = 0; p < 8; p++) {
        float mu = smu[p], rs = srs[p];
        float2 v = make_float2(sU[p * 512 + 2 * tid], sU[p * 512 + 2 * tid + 1]);
        float2 xr = __ldg(&x2[(size_t)(pt0 + p) * 256 + tid]);
        float2 o;
        o.x = (v.x - mu) * rs * gg.x + bb.x + xr.x;
        o.y = (v.y - mu) * rs * gg.y + bb.y + xr.y;
        o2[(size_t)(pt0 + p) * 256 + tid] = o;
    }
}

// ---------------------------------------------------------------------------
extern "C" void kernel_launch(void* const* d_in, const int* in_sizes, int n_in,
                              void* d_out, int out_size)
{
    const float* x  = (const float*)d_in[0];
    const float* r  = (const float*)d_in[1];
    const float* I  = (const float*)d_in[2];
    const float* IX = (const float*)d_in[3];
    const float* IY = (const float*)d_in[4];
    const float* IT = (const float*)d_in[5];
    const float* Wr = (const float*)d_in[6];
    const float* br = (const float*)d_in[7];
    const float* Wm = (const float*)d_in[8];
    const float* bm = (const float*)d_in[9];
    const float* Ws = (const float*)d_in[10];
    const float* bs = (const float*)d_in[11];
    const float* lg = (const float*)d_in[12];
    const float* lb = (const float*)d_in[13];
    float* out = (float*)d_out;
    (void)in_sizes; (void)n_in; (void)out_size;

    k_pre<<<PRE_BLOCKS + WT_BLOCKS, 256>>>(I, IX, IY, IT, x, r, Wr, br, Wm, bm, Ws, out);
    k_fused<<<PTS / 8, 256>>>(x, bs, lg, lb, out);
}

// round 15
// speedup vs baseline: 23.3327x; 1.0167x over previous
#include <cuda_runtime.h>
#include <cuda_fp16.h>
#include <math.h>

#define BB 8
#define NN 2048
#define CC 512
#define CIN 128
#define HH 96
#define WW 96
#define PTS (BB*NN)               // 16384
#define IMG_ELEMS (BB*HH*WW*CIN)  // 9,437,184

#define NT_BLOCKS 9216            // transpose blocks
#define WT_BLOCKS 16              // weight-pack blocks

// Scratch (static __device__ arrays — no allocation)
__device__ __half2 g_TIh[IMG_ELEMS/2];  // I transposed, fp16 (gather weights <= 0.25)
__device__ float g_TT[IMG_ELEMS];   // IT transposed
__device__ float g_A1[IMG_ELEMS];   // IX - 0.5*I transposed
__device__ float g_A2[IMG_ELEMS];   // IY - 0.5*I transposed
__device__ unsigned long long g_Wt8[64*512];  // (Ws[2kk][c], Ws[2kk+1][c])

// ---------------------------------------------------------------------------
__device__ __forceinline__ float4 f4add(float4 a, float4 b) {
    return make_float4(a.x + b.x, a.y + b.y, a.z + b.z, a.w + b.w);
}
__device__ __forceinline__ float4 f4sub(float4 a, float4 b) {
    return make_float4(a.x - b.x, a.y - b.y, a.z - b.z, a.w - b.w);
}
__device__ __forceinline__ float4 f4scale(float s, float4 a) {
    return make_float4(s * a.x, s * a.y, s * a.z, s * a.w);
}
__device__ __forceinline__ float sigmoidf_(float v) { return 1.f / (1.f + expf(-v)); }

__device__ __forceinline__ void ffma2(unsigned long long& d, unsigned long long a,
                                      unsigned long long b) {
    asm("fma.rn.f32x2 %0, %1, %2, %0;" : "+l"(d) : "l"(a), "l"(b));
}
union F4U { float4 f; unsigned long long l[2]; };

__device__ __forceinline__ float4 ldh4(const __half2* __restrict__ T, int cell, int lane) {
    uint2 v = __ldg((const uint2*)(T + cell * 64 + lane * 2));
    __half2 h0 = *reinterpret_cast<__half2*>(&v.x);
    __half2 h1 = *reinterpret_cast<__half2*>(&v.y);
    float2 f0 = __half22float2(h0), f1 = __half22float2(h1);
    return make_float4(f0.x, f0.y, f1.x, f1.y);
}

// ---------------------------------------------------------------------------
// Kernel 1: transpose (9216 blocks) + weight pack (16 blocks). Pure bandwidth.
// ---------------------------------------------------------------------------
__global__ void __launch_bounds__(256)
k_pre(const float* __restrict__ I, const float* __restrict__ IX,
      const float* __restrict__ IY, const float* __restrict__ IT,
      const float* __restrict__ Ws)
{
    __shared__ __align__(16) float sm[4 * 1056];
    int tid = threadIdx.x;

    if (blockIdx.x >= NT_BLOCKS) {
        int base = (blockIdx.x - NT_BLOCKS) * 2048 + tid;
        #pragma unroll
        for (int i = 0; i < 8; i++) {
            int idx = base + i * 256;
            int kk = idx >> 9, c = idx & 511;
            unsigned int lo = __float_as_uint(Ws[(2 * kk) * 512 + c]);
            unsigned int hi = __float_as_uint(Ws[(2 * kk + 1) * 512 + c]);
            g_Wt8[idx] = ((unsigned long long)hi << 32) | lo;
        }
        return;
    }

    float* tI = sm;
    float* tT = tI + 1056;
    float* t1 = tT + 1056;
    float* t2 = t1 + 1056;

    int t = blockIdx.x;
    int y0 = (t % 3) * 32;
    int c0 = ((t / 3) & 3) * 32;
    int xx = (t / 12) % HH;
    int b  = t / (12 * HH);

    int cl = tid >> 3;             // 0..31
    int y4 = (tid & 7) << 2;       // 0,4..28

    size_t idx = ((size_t)(b * CIN + c0 + cl) * (HH * WW) + (size_t)xx * WW + y0 + y4);
    float4 vi = *(const float4*)(I + idx);
    float4 vx = *(const float4*)(IX + idx);
    float4 vy = *(const float4*)(IY + idx);
    float4 vt = *(const float4*)(IT + idx);

    int sb = cl * 33 + y4;
    tI[sb + 0] = vi.x; tI[sb + 1] = vi.y; tI[sb + 2] = vi.z; tI[sb + 3] = vi.w;
    tT[sb + 0] = vt.x; tT[sb + 1] = vt.y; tT[sb + 2] = vt.z; tT[sb + 3] = vt.w;
    t1[sb + 0] = vx.x - 0.5f * vi.x; t1[sb + 1] = vx.y - 0.5f * vi.y;
    t1[sb + 2] = vx.z - 0.5f * vi.z; t1[sb + 3] = vx.w - 0.5f * vi.w;
    t2[sb + 0] = vy.x - 0.5f * vi.x; t2[sb + 1] = vy.y - 0.5f * vi.y;
    t2[sb + 2] = vy.z - 0.5f * vi.z; t2[sb + 3] = vy.w - 0.5f * vi.w;
    __syncthreads();

    int yl = tid >> 3;
    int c4 = (tid & 7) << 2;
    size_t o = (((size_t)b * HH + xx) * WW + y0 + yl) * CIN + c0 + c4;
    float4 oi, ot, o1, o2;
    oi.x = tI[(c4 + 0) * 33 + yl]; oi.y = tI[(c4 + 1) * 33 + yl];
    oi.z = tI[(c4 + 2) * 33 + yl]; oi.w = tI[(c4 + 3) * 33 + yl];
    ot.x = tT[(c4 + 0) * 33 + yl]; ot.y = tT[(c4 + 1) * 33 + yl];
    ot.z = tT[(c4 + 2) * 33 + yl]; ot.w = tT[(c4 + 3) * 33 + yl];
    o1.x = t1[(c4 + 0) * 33 + yl]; o1.y = t1[(c4 + 1) * 33 + yl];
    o1.z = t1[(c4 + 2) * 33 + yl]; o1.w = t1[(c4 + 3) * 33 + yl];
    o2.x = t2[(c4 + 0) * 33 + yl]; o2.y = t2[(c4 + 1) * 33 + yl];
    o2.z = t2[(c4 + 2) * 33 + yl]; o2.w = t2[(c4 + 3) * 33 + yl];
    {
        __half2 h01 = __floats2half2_rn(oi.x, oi.y);
        __half2 h23 = __floats2half2_rn(oi.z, oi.w);
        uint2 hp;
        hp.x = *reinterpret_cast<unsigned int*>(&h01);
        hp.y = *reinterpret_cast<unsigned int*>(&h23);
        *(uint2*)(g_TIh + o / 2) = hp;
    }
    *(float4*)(g_TT + o) = ot;
    *(float4*)(g_A1 + o) = o1;
    *(float4*)(g_A2 + o) = o2;
}

// ---------------------------------------------------------------------------
// Corner eval: TT/A1/A2 fp32 (5 loads), TI fp16 (4 x 8B loads).
// ---------------------------------------------------------------------------
__device__ __forceinline__ float4 corner_nb(const __half2* __restrict__ TIh,
                                            const float4* __restrict__ TT,
                                            const float4* __restrict__ A1,
                                            const float4* __restrict__ A2,
                                            int lane, float px, float py)
{
    float X = ceilf(px), Y = ceilf(py);
    int Xi = (int)X, Yi = (int)Y;
    int Xm = max(Xi - 1, 0), Ym = max(Yi - 1, 0);
    float dx = X - px, dy = Y - py;
    float wx1 = 0.5f * (dx * dx), wx2 = dx - wx1;
    float wy1 = 0.5f * (dy * dy), wy2 = dy - wy1;
#define AT4(T, xi, yi) __ldg(&T[(((xi) * WW + (yi)) << 5) + lane])
    float4 s = AT4(TT, Xi, Yi);
    s = f4sub(s, f4add(f4scale(wy1, AT4(A1, Xi, Ym)), f4scale(wy2, AT4(A1, Xi, Yi))));
    s = f4sub(s, f4add(f4scale(wx1, AT4(A2, Xm, Yi)), f4scale(wx2, AT4(A2, Xi, Yi))));
    s = f4add(s, f4add(f4add(f4scale(wx1 * wy1, ldh4(TIh, Xm * WW + Ym, lane)),
                             f4scale(wx2 * wy1, ldh4(TIh, Xi * WW + Ym, lane))),
                       f4add(f4scale(wx1 * wy2, ldh4(TIh, Xm * WW + Yi, lane)),
                             f4scale(wx2 * wy2, ldh4(TIh, Xi * WW + Yi, lane)))));
#undef AT4
    return s;
}

// ---------------------------------------------------------------------------
// Kernel 2 (mega-fused): per-point logits (issue-heavy — fills the latency
// bubbles of the gather phase) -> rect cascade -> softmax (all smem-resident),
// then corner-streamed sampling -> U -> packed-f32x2 GEMM -> LN + residual.
// Block = 8 points, 256 threads.
// ---------------------------------------------------------------------------
__global__ void __launch_bounds__(256)
k_fused(const float* __restrict__ x, const float* __restrict__ r,
        const float* __restrict__ Wr, const float* __restrict__ br,
        const float* __restrict__ Wm, const float* __restrict__ bm,
        const float* __restrict__ bs, const float* __restrict__ lg,
        const float* __restrict__ lb, float* __restrict__ out)
{
    // Aliased smem: [0,32768) = sxs(16K)+part(8K) during logits, sU after.
    __shared__ __align__(16) char sm[43296];
    float* sxs   = (float*)sm;                   // [0,16384)   (logit phase)
    float* part  = (float*)(sm + 16384);         // [16384,24576) (logit phase)
    float* sU    = (float*)sm;                   // [0,32768)   (sampling/GEMM)
    float* rpart = (float*)(sm + 32768);         // 896
    float* slog  = (float*)(sm + 33664);         // 2272
    float* srect = (float*)(sm + 35936);         // 1792
    float* smask = (float*)(sm + 37728);         // 2048
    float2* scoord = (float2*)(sm + 39776);      // 1152 (8x18 float2)
    float* scoefR = (float*)(sm + 40928);        // 2048
    float* sinv  = (float*)(sm + 42976);         // 256
    float* smu   = (float*)(sm + 43232);         // 32
    float* srs   = (float*)(sm + 43264);         // 32

    int tid = threadIdx.x;
    int wid = tid >> 5, lane = tid & 31;
    int pt0 = blockIdx.x * 8;
    int pt = pt0 + wid;
    int b = pt / NN;

    // ================= Stage A: logits =================
    {
        const float4* src = (const float4*)(x + (size_t)pt0 * CC);
        float4* dst = (float4*)sxs;
        for (int i = tid; i < 8 * CC / 4; i += 256) dst[i] = src[i];
    }
    __syncthreads();

    // mask logits: j = tid&63, c-chunk q = tid>>6 (128 c each)
    {
        int j = tid & 63, q = tid >> 6;
        int cbase = q * 128;
        float acc[8];
        #pragma unroll
        for (int p = 0; p < 8; p++) acc[p] = 0.f;
        #pragma unroll 4
        for (int c4i = 0; c4i < 32; c4i++) {
            int c = cbase + c4i * 4;
            float w0 = __ldg(&Wm[(size_t)(c + 0) * 64 + j]);
            float w1 = __ldg(&Wm[(size_t)(c + 1) * 64 + j]);
            float w2 = __ldg(&Wm[(size_t)(c + 2) * 64 + j]);
            float w3 = __ldg(&Wm[(size_t)(c + 3) * 64 + j]);
            #pragma unroll
            for (int p = 0; p < 8; p++) {
                float4 u = *(const float4*)(sxs + p * CC + c);
                acc[p] += u.x * w0 + u.y * w1 + u.z * w2 + u.w * w3;
            }
        }
        #pragma unroll
        for (int p = 0; p < 8; p++) part[tid * 8 + p] = acc[p];
    }
    // ratio logits: Kahan, 8 pts x 7 logits x 4 chunks of 128 (2 ILP chains)
    if (tid < 224) {
        int p = tid / 28, rem = tid % 28;
        int j = rem % 7, h = rem / 7;
        int c0 = h * 128;
        const float* sx = sxs + p * CC;
        float s0 = 0.f, k0 = 0.f, s1 = 0.f, k1 = 0.f;
        #pragma unroll 4
        for (int c = 0; c < 64; c++) {
            float t = __fmul_rn(sx[c0 + c], Wr[(size_t)(c0 + c) * 7 + j]);
            float y = __fadd_rn(t, -k0);
            float u = __fadd_rn(s0, y);
            k0 = __fadd_rn(__fadd_rn(u, -s0), -y);
            s0 = u;
            float t2 = __fmul_rn(sx[c0 + 64 + c], Wr[(size_t)(c0 + 64 + c) * 7 + j]);
            float y2 = __fadd_rn(t2, -k1);
            float u2 = __fadd_rn(s1, y2);
            k1 = __fadd_rn(__fadd_rn(u2, -s1), -y2);
            s1 = u2;
        }
        rpart[(p * 7 + j) * 4 + h] = __fadd_rn(s0, s1);
    }
    __syncthreads();
    if (tid < 64) {
        int j = tid;
        float bmv = bm[j];
        #pragma unroll
        for (int p = 0; p < 8; p++) {
            float v = ((part[(0 * 64 + j) * 8 + p] + part[(1 * 64 + j) * 8 + p])
                     + (part[(2 * 64 + j) * 8 + p] + part[(3 * 64 + j) * 8 + p])) + bmv;
            slog[p * 71 + 7 + j] = v;
        }
    }
    if (tid < 56) {
        int p = tid / 7, j = tid % 7;
        const float* q = rpart + (p * 7 + j) * 4;
        slog[p * 71 + j] = __fadd_rn(__fadd_rn(__fadd_rn(q[0], q[1]),
                                               __fadd_rn(q[2], q[3])), br[j]);
    }
    __syncthreads();

    // rect cascade: thread p < 8 per point
    if (tid < 8) {
        int p = tid;
        const float* sl = slog + p * 71;
        float* sr = srect + p * 56;
        const float* rp = r + (size_t)(pt0 + p) * 4;
        float p0 = rp[0], p1 = rp[1], p2 = rp[2], p3 = rp[3];
        float rA[2][4], rBv[4][4], rCv[8][4];
        {
            float rat = sigmoidf_(sl[0]);
            float mid = p0 * (1.f - rat) + p2 * rat;
            rA[0][0] = p0;  rA[0][1] = p1; rA[0][2] = mid; rA[0][3] = p3;
            rA[1][0] = mid; rA[1][1] = p1; rA[1][2] = p2;  rA[1][3] = p3;
        }
        for (int j = 0; j < 2; j++) {
            float rat = sigmoidf_(sl[1 + j]);
            float mid = rA[j][1] * (1.f - rat) + rA[j][3] * rat;
            rBv[j][0] = rA[j][0]; rBv[j][1] = rA[j][1]; rBv[j][2] = rA[j][2]; rBv[j][3] = mid;
            rBv[2 + j][0] = rA[j][0]; rBv[2 + j][1] = mid; rBv[2 + j][2] = rA[j][2]; rBv[2 + j][3] = rA[j][3];
        }
        for (int j = 0; j < 4; j++) {
            float rat = sigmoidf_(sl[3 + j]);
            float mid = rBv[j][0] * (1.f - rat) + rBv[j][2] * rat;
            rCv[j][0] = rBv[j][0]; rCv[j][1] = rBv[j][1]; rCv[j][2] = mid; rCv[j][3] = rBv[j][3];
            rCv[4 + j][0] = mid; rCv[4 + j][1] = rBv[j][1]; rCv[4 + j][2] = rBv[j][2]; rCv[4 + j][3] = rBv[j][3];
        }
        for (int j = 0; j < 2; j++) for (int q = 0; q < 4; q++) sr[j * 4 + q] = rA[j][q];
        for (int j = 0; j < 4; j++) for (int q = 0; q < 4; q++) sr[8 + j * 4 + q] = rBv[j][q];
        for (int j = 0; j < 8; j++) for (int q = 0; q < 4; q++) sr[24 + j * 4 + q] = rCv[j][q];
    }
    // softmax: 64 threads, (p, g) -> smask (smem only; no global roundtrip)
    if (tid < 64) {
        int p = tid >> 3, g = tid & 7;
        const float* sl = slog + p * 71;
        float mx = -1e30f;
        for (int s = 0; s < 8; s++) mx = fmaxf(mx, sl[7 + s * 8 + g]);
        float e[8], sum = 0.f;
        for (int s = 0; s < 8; s++) { e[s] = expf(sl[7 + s * 8 + g] - mx); sum += e[s]; }
        float inv = 1.f / sum;
        for (int s = 0; s < 8; s++) smask[p * 64 + s * 8 + g] = e[s] * inv;
    }
    __syncthreads();

    // rect outputs
    {
        const size_t O1 = (size_t)PTS * CC;
        const size_t O2 = O1 + (size_t)PTS * 8;
        const size_t O3 = O2 + (size_t)PTS * 16;
        if (tid < 64)  { int p = tid >> 3, i = tid & 7;  out[O1 + (size_t)(pt0 + p) * 8 + i]  = srect[p * 56 + i]; }
        if (tid < 128) { int p = tid >> 4, i = tid & 15; out[O2 + (size_t)(pt0 + p) * 16 + i] = srect[p * 56 + 8 + i]; }
        {              int p = tid >> 5, i = tid & 31; out[O3 + (size_t)(pt0 + p) * 32 + i] = srect[p * 56 + 24 + i]; }
    }

    // ================= Stage B: sampling =================
    const float F = (float)(HH - 1);
    const float* rp = srect + wid * 56 + 24;   // final 8 rects of this warp's point
    const float* mp = smask + wid * 64;

    const int T_CX[18] = {0,0,0, 4,4,4,4, 22,22,22, 2,2, 6,6, 10,10, 14,14};
    const int T_CY[18] = {1,3,11, 1,3,7,11, 1,7,11, 1,3, 1,7, 3,11, 7,11};
    const int T_R1[18] = {0,0,2, 4,4,1,6, 5,5,7, 0,0, 1,1, 2,2, 3,3};
    const int T_S1[18] = {1,-1,-1, -1,1,-1,1, -1,1,1, -1,1, -1,1, -1,1, -1,1};
    const int T_R2[18] = {0,2,0, 1,6,3,3, 0,7,0, 4,4, 5,5, 6,6, 7,7};
    const int T_S2[18] = {0,1,0, 1,-1,1,-1, 0,-1,0, 1,-1, 1,-1, 1,-1, 1,-1};

    if (lane < 18) {
        scoord[wid * 18 + lane] = make_float2(rp[T_CX[lane]] * F, rp[T_CY[lane]] * F);
    }
    if (lane < 8) {
        float x1 = rp[4 * lane] * F,     y1 = rp[4 * lane + 1] * F;
        float x2 = rp[4 * lane + 2] * F, y2 = rp[4 * lane + 3] * F;
        sinv[wid * 8 + lane] = 1.f / (fabsf((x1 - x2) * (y1 - y2)) + 1e-9f);
    }
    __syncwarp();
    #pragma unroll
    for (int t = lane; t < 64; t += 32)
        scoefR[wid * 64 + t] = mp[t] * sinv[wid * 8 + (t >> 3)];
    __syncthreads();   // full barrier: sxs/part region about to be overwritten by sU

    {
        size_t ibase = (size_t)b * (HH * WW);
        const __half2* TIh = g_TIh + ibase * (CIN / 2);
        const float4* TT = (const float4*)g_TT + ibase * (CIN / 4);
        const float4* A1 = (const float4*)g_A1 + ibase * (CIN / 4);
        const float4* A2 = (const float4*)g_A2 + ibase * (CIN / 4);

        float4 S[8];
        #pragma unroll
        for (int rr = 0; rr < 8; rr++) S[rr] = make_float4(0.f, 0.f, 0.f, 0.f);

        #pragma unroll
        for (int e = 0; e < 18; e++) {
            float2 cc = scoord[wid * 18 + e];
            float4 v = corner_nb(TIh, TT, A1, A2, lane, cc.x, cc.y);
            if (T_S1[e] > 0) S[T_R1[e]] = f4add(S[T_R1[e]], v);
            else             S[T_R1[e]] = f4sub(S[T_R1[e]], v);
            if (T_S2[e] > 0)      S[T_R2[e]] = f4add(S[T_R2[e]], v);
            else if (T_S2[e] < 0) S[T_R2[e]] = f4sub(S[T_R2[e]], v);
        }

        const float* cr = scoefR + wid * 64;
        float4* up = (float4*)(sU + wid * 1024);
        #pragma unroll
        for (int g = 0; g < 8; g++) {
            float4 u = make_float4(0.f, 0.f, 0.f, 0.f);
            #pragma unroll
            for (int rr = 0; rr < 8; rr++) {
                float c = cr[rr * 8 + g];
                u.x += c * S[rr].x; u.y += c * S[rr].y;
                u.z += c * S[rr].z; u.w += c * S[rr].w;
            }
            up[g * 32 + lane] = u;
        }
    }
    __syncthreads();

    // ================= Stage C: packed-f32x2 group-GEMM =================
    int g = tid >> 5;
    unsigned long long acc0[8], acc1[8];
    #pragma unroll
    for (int p = 0; p < 8; p++) { acc0[p] = 0ull; acc1[p] = 0ull; }

    const ulonglong2* Wt16 = (const ulonglong2*)g_Wt8;
    const float4* sU4 = (const float4*)sU;
    for (int k4 = 0; k4 < 32; k4++) {
        ulonglong2 wA = __ldg(&Wt16[(2 * k4) * 256 + tid]);
        ulonglong2 wB = __ldg(&Wt16[(2 * k4 + 1) * 256 + tid]);
        #pragma unroll
        for (int p = 0; p < 8; p++) {
            F4U u;
            u.f = sU4[p * 256 + g * 32 + k4];
            ffma2(acc0[p], u.l[0], wA.x);
            ffma2(acc0[p], u.l[1], wB.x);
            ffma2(acc1[p], u.l[0], wA.y);
            ffma2(acc1[p], u.l[1], wB.y);
        }
    }
    float2 bsv = __ldg(&((const float2*)bs)[tid]);
    __syncthreads();
    #pragma unroll
    for (int p = 0; p < 8; p++) {
        unsigned int e0 = (unsigned int)acc0[p], o0 = (unsigned int)(acc0[p] >> 32);
        unsigned int e1 = (unsigned int)acc1[p], o1 = (unsigned int)(acc1[p] >> 32);
        sU[p * 512 + 2 * tid]     = (__uint_as_float(e0) + __uint_as_float(o0)) + bsv.x;
        sU[p * 512 + 2 * tid + 1] = (__uint_as_float(e1) + __uint_as_float(o1)) + bsv.y;
    }
    __syncthreads();

    // ================= Stage D: LayerNorm + residual =================
    {
        float sum = 0.f, sq = 0.f;
        for (int i = lane; i < 512; i += 32) {
            float v = sU[wid * 512 + i];
            sum += v; sq += v * v;
        }
        #pragma unroll
        for (int o = 16; o; o >>= 1) {
            sum += __shfl_xor_sync(0xffffffffu, sum, o);
            sq  += __shfl_xor_sync(0xffffffffu, sq, o);
        }
        if (lane == 0) {
            float mu = sum * (1.f / 512.f);
            float var = sq * (1.f / 512.f) - mu * mu;
            smu[wid] = mu;
            srs[wid] = rsqrtf(var + 1e-5f);
        }
    }
    __syncthreads();

    float2 gg = __ldg(&((const float2*)lg)[tid]);
    float2 bb = __ldg(&((const float2*)lb)[tid]);
    const float2* x2 = (const float2*)x;
    float2* o2 = (float2*)out;
    #pragma unroll
    for (int p = 0; p < 8; p++) {
        float mu = smu[p], rs = srs[p];
        float2 v = make_float2(sU[p * 512 + 2 * tid], sU[p * 512 + 2 * tid + 1]);
        float2 xr = __ldg(&x2[(size_t)(pt0 + p) * 256 + tid]);
        float2 o;
        o.x = (v.x - mu) * rs * gg.x + bb.x + xr.x;
        o.y = (v.y - mu) * rs * gg.y + bb.y + xr.y;
        o2[(size_t)(pt0 + p) * 256 + tid] = o;
    }
}

// ---------------------------------------------------------------------------
extern "C" void kernel_launch(void* const* d_in, const int* in_sizes, int n_in,
                              void* d_out, int out_size)
{
    const float* x  = (const float*)d_in[0];
    const float* r  = (const float*)d_in[1];
    const float* I  = (const float*)d_in[2];
    const float* IX = (const float*)d_in[3];
    const float* IY = (const float*)d_in[4];
    const float* IT = (const float*)d_in[5];
    const float* Wr = (const float*)d_in[6];
    const float* br = (const float*)d_in[7];
    const float* Wm = (const float*)d_in[8];
    const float* bm = (const float*)d_in[9];
    const float* Ws = (const float*)d_in[10];
    const float* bs = (const float*)d_in[11];
    const float* lg = (const float*)d_in[12];
    const float* lb = (const float*)d_in[13];
    float* out = (float*)d_out;
    (void)in_sizes; (void)n_in; (void)out_size;

    k_pre<<<NT_BLOCKS + WT_BLOCKS, 256>>>(I, IX, IY, IT, Ws);
    k_fused<<<PTS / 8, 256>>>(x, r, Wr, br, Wm, bm, bs, lg, lb, out);
}

// round 17
// speedup vs baseline: 23.4541x; 1.0052x over previous
#include <cuda_runtime.h>
#include <cuda_fp16.h>
#include <math.h>

#define BB 8
#define NN 2048
#define CC 512
#define CIN 128
#define HH 96
#define WW 96
#define PTS (BB*NN)               // 16384
#define IMG_ELEMS (BB*HH*WW*CIN)  // 9,437,184

#define NT_BLOCKS 9216            // transpose blocks
#define WT_BLOCKS 16              // Ws pack blocks
#define WM_BLOCKS 8               // Wm pack blocks

// Scratch (static __device__ arrays — no allocation)
__device__ __half2 g_TIh[IMG_ELEMS/2];  // I transposed, fp16 (gather weights <= 0.25)
__device__ float g_TT[IMG_ELEMS];   // IT transposed
__device__ float g_A1[IMG_ELEMS];   // IX - 0.5*I transposed
__device__ float g_A2[IMG_ELEMS];   // IY - 0.5*I transposed
__device__ unsigned long long g_Wt8[64*512];   // (Ws[2kk][c], Ws[2kk+1][c])
__device__ unsigned long long g_Wm2[256*64];   // (Wm[2c2][j], Wm[2c2+1][j])

// ---------------------------------------------------------------------------
__device__ __forceinline__ float4 f4add(float4 a, float4 b) {
    return make_float4(a.x + b.x, a.y + b.y, a.z + b.z, a.w + b.w);
}
__device__ __forceinline__ float4 f4sub(float4 a, float4 b) {
    return make_float4(a.x - b.x, a.y - b.y, a.z - b.z, a.w - b.w);
}
__device__ __forceinline__ float4 f4scale(float s, float4 a) {
    return make_float4(s * a.x, s * a.y, s * a.z, s * a.w);
}
__device__ __forceinline__ float sigmoidf_(float v) { return 1.f / (1.f + expf(-v)); }

__device__ __forceinline__ void ffma2(unsigned long long& d, unsigned long long a,
                                      unsigned long long b) {
    asm("fma.rn.f32x2 %0, %1, %2, %0;" : "+l"(d) : "l"(a), "l"(b));
}
union F4U { float4 f; unsigned long long l[2]; };

__device__ __forceinline__ float4 ldh4(const __half2* __restrict__ T, int cell, int lane) {
    uint2 v = __ldg((const uint2*)(T + cell * 64 + lane * 2));
    __half2 h0 = *reinterpret_cast<__half2*>(&v.x);
    __half2 h1 = *reinterpret_cast<__half2*>(&v.y);
    float2 f0 = __half22float2(h0), f1 = __half22float2(h1);
    return make_float4(f0.x, f0.y, f1.x, f1.y);
}

// ---------------------------------------------------------------------------
// Kernel 1: transpose (9216 blocks) + Ws pack (16) + Wm pack (8).
// ---------------------------------------------------------------------------
__global__ void __launch_bounds__(256)
k_pre(const float* __restrict__ I, const float* __restrict__ IX,
      const float* __restrict__ IY, const float* __restrict__ IT,
      const float* __restrict__ Ws, const float* __restrict__ Wm)
{
    __shared__ __align__(16) float sm[4 * 1056];
    int tid = threadIdx.x;

    if (blockIdx.x >= NT_BLOCKS + WT_BLOCKS) {
        // ===== Wm pack: g_Wm2[c2*64+j] = (Wm[2c2][j], Wm[2c2+1][j]) =====
        int base = (blockIdx.x - NT_BLOCKS - WT_BLOCKS) * 2048 + tid;
        #pragma unroll
        for (int i = 0; i < 8; i++) {
            int idx = base + i * 256;
            int c2 = idx >> 6, j = idx & 63;
            unsigned int lo = __float_as_uint(Wm[(2 * c2) * 64 + j]);
            unsigned int hi = __float_as_uint(Wm[(2 * c2 + 1) * 64 + j]);
            g_Wm2[idx] = ((unsigned long long)hi << 32) | lo;
        }
        return;
    }
    if (blockIdx.x >= NT_BLOCKS) {
        int base = (blockIdx.x - NT_BLOCKS) * 2048 + tid;
        #pragma unroll
        for (int i = 0; i < 8; i++) {
            int idx = base + i * 256;
            int kk = idx >> 9, c = idx & 511;
            unsigned int lo = __float_as_uint(Ws[(2 * kk) * 512 + c]);
            unsigned int hi = __float_as_uint(Ws[(2 * kk + 1) * 512 + c]);
            g_Wt8[idx] = ((unsigned long long)hi << 32) | lo;
        }
        return;
    }

    float* tI = sm;
    float* tT = tI + 1056;
    float* t1 = tT + 1056;
    float* t2 = t1 + 1056;

    int t = blockIdx.x;
    int y0 = (t % 3) * 32;
    int c0 = ((t / 3) & 3) * 32;
    int xx = (t / 12) % HH;
    int b  = t / (12 * HH);

    int cl = tid >> 3;             // 0..31
    int y4 = (tid & 7) << 2;       // 0,4..28

    size_t idx = ((size_t)(b * CIN + c0 + cl) * (HH * WW) + (size_t)xx * WW + y0 + y4);
    float4 vi = *(const float4*)(I + idx);
    float4 vx = *(const float4*)(IX + idx);
    float4 vy = *(const float4*)(IY + idx);
    float4 vt = *(const float4*)(IT + idx);

    int sb = cl * 33 + y4;
    tI[sb + 0] = vi.x; tI[sb + 1] = vi.y; tI[sb + 2] = vi.z; tI[sb + 3] = vi.w;
    tT[sb + 0] = vt.x; tT[sb + 1] = vt.y; tT[sb + 2] = vt.z; tT[sb + 3] = vt.w;
    t1[sb + 0] = vx.x - 0.5f * vi.x; t1[sb + 1] = vx.y - 0.5f * vi.y;
    t1[sb + 2] = vx.z - 0.5f * vi.z; t1[sb + 3] = vx.w - 0.5f * vi.w;
    t2[sb + 0] = vy.x - 0.5f * vi.x; t2[sb + 1] = vy.y - 0.5f * vi.y;
    t2[sb + 2] = vy.z - 0.5f * vi.z; t2[sb + 3] = vy.w - 0.5f * vi.w;
    __syncthreads();

    int yl = tid >> 3;
    int c4 = (tid & 7) << 2;
    size_t o = (((size_t)b * HH + xx) * WW + y0 + yl) * CIN + c0 + c4;
    float4 oi, ot, o1, o2;
    oi.x = tI[(c4 + 0) * 33 + yl]; oi.y = tI[(c4 + 1) * 33 + yl];
    oi.z = tI[(c4 + 2) * 33 + yl]; oi.w = tI[(c4 + 3) * 33 + yl];
    ot.x = tT[(c4 + 0) * 33 + yl]; ot.y = tT[(c4 + 1) * 33 + yl];
    ot.z = tT[(c4 + 2) * 33 + yl]; ot.w = tT[(c4 + 3) * 33 + yl];
    o1.x = t1[(c4 + 0) * 33 + yl]; o1.y = t1[(c4 + 1) * 33 + yl];
    o1.z = t1[(c4 + 2) * 33 + yl]; o1.w = t1[(c4 + 3) * 33 + yl];
    o2.x = t2[(c4 + 0) * 33 + yl]; o2.y = t2[(c4 + 1) * 33 + yl];
    o2.z = t2[(c4 + 2) * 33 + yl]; o2.w = t2[(c4 + 3) * 33 + yl];
    {
        __half2 h01 = __floats2half2_rn(oi.x, oi.y);
        __half2 h23 = __floats2half2_rn(oi.z, oi.w);
        uint2 hp;
        hp.x = *reinterpret_cast<unsigned int*>(&h01);
        hp.y = *reinterpret_cast<unsigned int*>(&h23);
        *(uint2*)(g_TIh + o / 2) = hp;
    }
    *(float4*)(g_TT + o) = ot;
    *(float4*)(g_A1 + o) = o1;
    *(float4*)(g_A2 + o) = o2;
}

// ---------------------------------------------------------------------------
// Corner eval: TT/A1/A2 fp32 (5 loads), TI fp16 (4 x 8B loads).
// ---------------------------------------------------------------------------
__device__ __forceinline__ float4 corner_nb(const __half2* __restrict__ TIh,
                                            const float4* __restrict__ TT,
                                            const float4* __restrict__ A1,
                                            const float4* __restrict__ A2,
                                            int lane, float px, float py)
{
    float X = ceilf(px), Y = ceilf(py);
    int Xi = (int)X, Yi = (int)Y;
    int Xm = max(Xi - 1, 0), Ym = max(Yi - 1, 0);
    float dx = X - px, dy = Y - py;
    float wx1 = 0.5f * (dx * dx), wx2 = dx - wx1;
    float wy1 = 0.5f * (dy * dy), wy2 = dy - wy1;
#define AT4(T, xi, yi) __ldg(&T[(((xi) * WW + (yi)) << 5) + lane])
    float4 s = AT4(TT, Xi, Yi);
    s = f4sub(s, f4add(f4scale(wy1, AT4(A1, Xi, Ym)), f4scale(wy2, AT4(A1, Xi, Yi))));
    s = f4sub(s, f4add(f4scale(wx1, AT4(A2, Xm, Yi)), f4scale(wx2, AT4(A2, Xi, Yi))));
    s = f4add(s, f4add(f4add(f4scale(wx1 * wy1, ldh4(TIh, Xm * WW + Ym, lane)),
                             f4scale(wx2 * wy1, ldh4(TIh, Xi * WW + Ym, lane))),
                       f4add(f4scale(wx1 * wy2, ldh4(TIh, Xm * WW + Yi, lane)),
                             f4scale(wx2 * wy2, ldh4(TIh, Xi * WW + Yi, lane)))));
#undef AT4
    return s;
}

// ---------------------------------------------------------------------------
// Kernel 2 (mega-fused): logits (c-pair FFMA2 GEMV) -> cascade -> softmax ->
// sampling -> U -> packed-f32x2 GEMM -> LN + residual. 8 points, 256 threads.
// ---------------------------------------------------------------------------
__global__ void __launch_bounds__(256)
k_fused(const float* __restrict__ x, const float* __restrict__ r,
        const float* __restrict__ Wr, const float* __restrict__ br,
        const float* __restrict__ bm,
        const float* __restrict__ bs, const float* __restrict__ lg,
        const float* __restrict__ lb, float* __restrict__ out)
{
    // Aliased smem: [0,32768) = sxs(16K)+part(8K) during logits, sU after.
    __shared__ __align__(16) char sm[43296];
    float* sxs   = (float*)sm;                   // [0,16384)   (logit phase)
    float* part  = (float*)(sm + 16384);         // [16384,24576) (logit phase)
    float* sU    = (float*)sm;                   // [0,32768)   (sampling/GEMM)
    float* rpart = (float*)(sm + 32768);         // 896
    float* slog  = (float*)(sm + 33664);         // 2272
    float* srect = (float*)(sm + 35936);         // 1792
    float* smask = (float*)(sm + 37728);         // 2048
    float2* scoord = (float2*)(sm + 39776);      // 1152 (8x18 float2)
    float* scoefR = (float*)(sm + 40928);        // 2048
    float* sinv  = (float*)(sm + 42976);         // 256
    float* smu   = (float*)(sm + 43232);         // 32
    float* srs   = (float*)(sm + 43264);         // 32

    int tid = threadIdx.x;
    int wid = tid >> 5, lane = tid & 31;
    int pt0 = blockIdx.x * 8;
    int pt = pt0 + wid;
    int b = pt / NN;

    // ================= Stage A: logits =================
    {
        const float4* src = (const float4*)(x + (size_t)pt0 * CC);
        float4* dst = (float4*)sxs;
        for (int i = tid; i < 8 * CC / 4; i += 256) dst[i] = src[i];
    }
    __syncthreads();

    // mask logits: j = tid&63, c-chunk q = tid>>6 (128 c each), c-pair FFMA2
    {
        int j = tid & 63, q = tid >> 6;
        int cbase = q * 128;
        unsigned long long acc2[8];
        #pragma unroll
        for (int p = 0; p < 8; p++) acc2[p] = 0ull;
        #pragma unroll 4
        for (int c4i = 0; c4i < 32; c4i++) {
            int c = cbase + c4i * 4;
            int c2 = c >> 1;
            unsigned long long wA = __ldg(&g_Wm2[(c2 + 0) * 64 + j]);  // c, c+1
            unsigned long long wB = __ldg(&g_Wm2[(c2 + 1) * 64 + j]);  // c+2, c+3
            #pragma unroll
            for (int p = 0; p < 8; p++) {
                F4U u;
                u.f = *(const float4*)(sxs + p * CC + c);
                ffma2(acc2[p], u.l[0], wA);
                ffma2(acc2[p], u.l[1], wB);
            }
        }
        #pragma unroll
        for (int p = 0; p < 8; p++) {
            unsigned int e = (unsigned int)acc2[p], o = (unsigned int)(acc2[p] >> 32);
            part[tid * 8 + p] = __uint_as_float(e) + __uint_as_float(o);
        }
    }
    // ratio logits: Kahan, 8 pts x 7 logits x 4 chunks of 128 (2 ILP chains)
    if (tid < 224) {
        int p = tid / 28, rem = tid % 28;
        int j = rem % 7, h = rem / 7;
        int c0 = h * 128;
        const float* sx = sxs + p * CC;
        float s0 = 0.f, k0 = 0.f, s1 = 0.f, k1 = 0.f;
        #pragma unroll 4
        for (int c = 0; c < 64; c++) {
            float t = __fmul_rn(sx[c0 + c], Wr[(size_t)(c0 + c) * 7 + j]);
            float y = __fadd_rn(t, -k0);
            float u = __fadd_rn(s0, y);
            k0 = __fadd_rn(__fadd_rn(u, -s0), -y);
            s0 = u;
            float t2 = __fmul_rn(sx[c0 + 64 + c], Wr[(size_t)(c0 + 64 + c) * 7 + j]);
            float y2 = __fadd_rn(t2, -k1);
            float u2 = __fadd_rn(s1, y2);
            k1 = __fadd_rn(__fadd_rn(u2, -s1), -y2);
            s1 = u2;
        }
        rpart[(p * 7 + j) * 4 + h] = __fadd_rn(s0, s1);
    }
    __syncthreads();
    if (tid < 64) {
        int j = tid;
        float bmv = bm[j];
        #pragma unroll
        for (int p = 0; p < 8; p++) {
            float v = ((part[(0 * 64 + j) * 8 + p] + part[(1 * 64 + j) * 8 + p])
                     + (part[(2 * 64 + j) * 8 + p] + part[(3 * 64 + j) * 8 + p])) + bmv;
            slog[p * 71 + 7 + j] = v;
        }
    }
    if (tid < 56) {
        int p = tid / 7, j = tid % 7;
        const float* q = rpart + (p * 7 + j) * 4;
        slog[p * 71 + j] = __fadd_rn(__fadd_rn(__fadd_rn(q[0], q[1]),
                                               __fadd_rn(q[2], q[3])), br[j]);
    }
    __syncthreads();

    // rect cascade: thread p < 8 per point
    if (tid < 8) {
        int p = tid;
        const float* sl = slog + p * 71;
        float* sr = srect + p * 56;
        const float* rp = r + (size_t)(pt0 + p) * 4;
        float p0 = rp[0], p1 = rp[1], p2 = rp[2], p3 = rp[3];
        float rA[2][4], rBv[4][4], rCv[8][4];
        {
            float rat = sigmoidf_(sl[0]);
            float mid = p0 * (1.f - rat) + p2 * rat;
            rA[0][0] = p0;  rA[0][1] = p1; rA[0][2] = mid; rA[0][3] = p3;
            rA[1][0] = mid; rA[1][1] = p1; rA[1][2] = p2;  rA[1][3] = p3;
        }
        for (int j = 0; j < 2; j++) {
            float rat = sigmoidf_(sl[1 + j]);
            float mid = rA[j][1] * (1.f - rat) + rA[j][3] * rat;
            rBv[j][0] = rA[j][0]; rBv[j][1] = rA[j][1]; rBv[j][2] = rA[j][2]; rBv[j][3] = mid;
            rBv[2 + j][0] = rA[j][0]; rBv[2 + j][1] = mid; rBv[2 + j][2] = rA[j][2]; rBv[2 + j][3] = rA[j][3];
        }
        for (int j = 0; j < 4; j++) {
            float rat = sigmoidf_(sl[3 + j]);
            float mid = rBv[j][0] * (1.f - rat) + rBv[j][2] * rat;
            rCv[j][0] = rBv[j][0]; rCv[j][1] = rBv[j][1]; rCv[j][2] = mid; rCv[j][3] = rBv[j][3];
            rCv[4 + j][0] = mid; rCv[4 + j][1] = rBv[j][1]; rCv[4 + j][2] = rBv[j][2]; rCv[4 + j][3] = rBv[j][3];
        }
        for (int j = 0; j < 2; j++) for (int q = 0; q < 4; q++) sr[j * 4 + q] = rA[j][q];
        for (int j = 0; j < 4; j++) for (int q = 0; q < 4; q++) sr[8 + j * 4 + q] = rBv[j][q];
        for (int j = 0; j < 8; j++) for (int q = 0; q < 4; q++) sr[24 + j * 4 + q] = rCv[j][q];
    }
    // softmax: 64 threads, (p, g) -> smask
    if (tid < 64) {
        int p = tid >> 3, g = tid & 7;
        const float* sl = slog + p * 71;
        float mx = -1e30f;
        for (int s = 0; s < 8; s++) mx = fmaxf(mx, sl[7 + s * 8 + g]);
        float e[8], sum = 0.f;
        for (int s = 0; s < 8; s++) { e[s] = expf(sl[7 + s * 8 + g] - mx); sum += e[s]; }
        float inv = 1.f / sum;
        for (int s = 0; s < 8; s++) smask[p * 64 + s * 8 + g] = e[s] * inv;
    }
    __syncthreads();

    // rect outputs
    {
        const size_t O1 = (size_t)PTS * CC;
        const size_t O2 = O1 + (size_t)PTS * 8;
        const size_t O3 = O2 + (size_t)PTS * 16;
        if (tid < 64)  { int p = tid >> 3, i = tid & 7;  out[O1 + (size_t)(pt0 + p) * 8 + i]  = srect[p * 56 + i]; }
        if (tid < 128) { int p = tid >> 4, i = tid & 15; out[O2 + (size_t)(pt0 + p) * 16 + i] = srect[p * 56 + 8 + i]; }
        {              int p = tid >> 5, i = tid & 31; out[O3 + (size_t)(pt0 + p) * 32 + i] = srect[p * 56 + 24 + i]; }
    }

    // ================= Stage B: sampling =================
    const float F = (float)(HH - 1);
    const float* rp = srect + wid * 56 + 24;
    const float* mp = smask + wid * 64;

    const int T_CX[18] = {0,0,0, 4,4,4,4, 22,22,22, 2,2, 6,6, 10,10, 14,14};
    const int T_CY[18] = {1,3,11, 1,3,7,11, 1,7,11, 1,3, 1,7, 3,11, 7,11};
    const int T_R1[18] = {0,0,2, 4,4,1,6, 5,5,7, 0,0, 1,1, 2,2, 3,3};
    const int T_S1[18] = {1,-1,-1, -1,1,-1,1, -1,1,1, -1,1, -1,1, -1,1, -1,1};
    const int T_R2[18] = {0,2,0, 1,6,3,3, 0,7,0, 4,4, 5,5, 6,6, 7,7};
    const int T_S2[18] = {0,1,0, 1,-1,1,-1, 0,-1,0, 1,-1, 1,-1, 1,-1, 1,-1};

    if (lane < 18) {
        scoord[wid * 18 + lane] = make_float2(rp[T_CX[lane]] * F, rp[T_CY[lane]] * F);
    }
    if (lane < 8) {
        float x1 = rp[4 * lane] * F,     y1 = rp[4 * lane + 1] * F;
        float x2 = rp[4 * lane + 2] * F, y2 = rp[4 * lane + 3] * F;
        sinv[wid * 8 + lane] = 1.f / (fabsf((x1 - x2) * (y1 - y2)) + 1e-9f);
    }
    __syncwarp();
    #pragma unroll
    for (int t = lane; t < 64; t += 32)
        scoefR[wid * 64 + t] = mp[t] * sinv[wid * 8 + (t >> 3)];
    __syncthreads();   // sxs/part region about to be overwritten by sU

    {
        size_t ibase = (size_t)b * (HH * WW);
        const __half2* TIh = g_TIh + ibase * (CIN / 2);
        const float4* TT = (const float4*)g_TT + ibase * (CIN / 4);
        const float4* A1 = (const float4*)g_A1 + ibase * (CIN / 4);
        const float4* A2 = (const float4*)g_A2 + ibase * (CIN / 4);

        float4 S[8];
        #pragma unroll
        for (int rr = 0; rr < 8; rr++) S[rr] = make_float4(0.f, 0.f, 0.f, 0.f);

        #pragma unroll
        for (int e = 0; e < 18; e++) {
            float2 cc = scoord[wid * 18 + e];
            float4 v = corner_nb(TIh, TT, A1, A2, lane, cc.x, cc.y);
            if (T_S1[e] > 0) S[T_R1[e]] = f4add(S[T_R1[e]], v);
            else             S[T_R1[e]] = f4sub(S[T_R1[e]], v);
            if (T_S2[e] > 0)      S[T_R2[e]] = f4add(S[T_R2[e]], v);
            else if (T_S2[e] < 0) S[T_R2[e]] = f4sub(S[T_R2[e]], v);
        }

        const float* cr = scoefR + wid * 64;
        float4* up = (float4*)(sU + wid * 1024);
        #pragma unroll
        for (int g = 0; g < 8; g++) {
            float4 u = make_float4(0.f, 0.f, 0.f, 0.f);
            #pragma unroll
            for (int rr = 0; rr < 8; rr++) {
                float c = cr[rr * 8 + g];
                u.x += c * S[rr].x; u.y += c * S[rr].y;
                u.z += c * S[rr].z; u.w += c * S[rr].w;
            }
            up[g * 32 + lane] = u;
        }
    }
    __syncthreads();

    // ================= Stage C: packed-f32x2 group-GEMM =================
    int g = tid >> 5;
    unsigned long long acc0[8], acc1[8];
    #pragma unroll
    for (int p = 0; p < 8; p++) { acc0[p] = 0ull; acc1[p] = 0ull; }

    const ulonglong2* Wt16 = (const ulonglong2*)g_Wt8;
    const float4* sU4 = (const float4*)sU;
    for (int k4 = 0; k4 < 32; k4++) {
        ulonglong2 wA = __ldg(&Wt16[(2 * k4) * 256 + tid]);
        ulonglong2 wB = __ldg(&Wt16[(2 * k4 + 1) * 256 + tid]);
        #pragma unroll
        for (int p = 0; p < 8; p++) {
            F4U u;
            u.f = sU4[p * 256 + g * 32 + k4];
            ffma2(acc0[p], u.l[0], wA.x);
            ffma2(acc0[p], u.l[1], wB.x);
            ffma2(acc1[p], u.l[0], wA.y);
            ffma2(acc1[p], u.l[1], wB.y);
        }
    }
    float2 bsv = __ldg(&((const float2*)bs)[tid]);
    __syncthreads();
    #pragma unroll
    for (int p = 0; p < 8; p++) {
        unsigned int e0 = (unsigned int)acc0[p], o0 = (unsigned int)(acc0[p] >> 32);
        unsigned int e1 = (unsigned int)acc1[p], o1 = (unsigned int)(acc1[p] >> 32);
        sU[p * 512 + 2 * tid]     = (__uint_as_float(e0) + __uint_as_float(o0)) + bsv.x;
        sU[p * 512 + 2 * tid + 1] = (__uint_as_float(e1) + __uint_as_float(o1)) + bsv.y;
    }
    __syncthreads();

    // ================= Stage D: LayerNorm + residual =================
    {
        float sum = 0.f, sq = 0.f;
        for (int i = lane; i < 512; i += 32) {
            float v = sU[wid * 512 + i];
            sum += v; sq += v * v;
        }
        #pragma unroll
        for (int o = 16; o; o >>= 1) {
            sum += __shfl_xor_sync(0xffffffffu, sum, o);
            sq  += __shfl_xor_sync(0xffffffffu, sq, o);
        }
        if (lane == 0) {
            float mu = sum * (1.f / 512.f);
            float var = sq * (1.f / 512.f) - mu * mu;
            smu[wid] = mu;
            srs[wid] = rsqrtf(var + 1e-5f);
        }
    }
    __syncthreads();

    float2 gg = __ldg(&((const float2*)lg)[tid]);
    float2 bb = __ldg(&((const float2*)lb)[tid]);
    const float2* x2 = (const float2*)x;
    float2* o2 = (float2*)out;
    #pragma unroll
    for (int p = 0; p < 8; p++) {
        float mu = smu[p], rs = srs[p];
        float2 v = make_float2(sU[p * 512 + 2 * tid], sU[p * 512 + 2 * tid + 1]);
        float2 xr = __ldg(&x2[(size_t)(pt0 + p) * 256 + tid]);
        float2 o;
        o.x = (v.x - mu) * rs * gg.x + bb.x + xr.x;
        o.y = (v.y - mu) * rs * gg.y + bb.y + xr.y;
        o2[(size_t)(pt0 + p) * 256 + tid] = o;
    }
}

// ---------------------------------------------------------------------------
extern "C" void kernel_launch(void* const* d_in, const int* in_sizes, int n_in,
                              void* d_out, int out_size)
{
    const float* x  = (const float*)d_in[0];
    const float* r  = (const float*)d_in[1];
    const float* I  = (const float*)d_in[2];
    const float* IX = (const float*)d_in[3];
    const float* IY = (const float*)d_in[4];
    const float* IT = (const float*)d_in[5];
    const float* Wr = (const float*)d_in[6];
    const float* br = (const float*)d_in[7];
    const float* Wm = (const float*)d_in[8];
    const float* bm = (const float*)d_in[9];
    const float* Ws = (const float*)d_in[10];
    const float* bs = (const float*)d_in[11];
    const float* lg = (const float*)d_in[12];
    const float* lb = (const float*)d_in[13];
    float* out = (float*)d_out;
    (void)in_sizes; (void)n_in; (void)out_size;

    k_pre<<<NT_BLOCKS + WT_BLOCKS + WM_BLOCKS, 256>>>(I, IX, IY, IT, Ws, Wm);
    k_fused<<<PTS / 8, 256>>>(x, r, Wr, br, bm, bs, lg, lb, out);
}